// round 8
// baseline (speedup 1.0000x reference)
#include <cuda_runtime.h>
#include <math.h>

#define VOL (256*128*128)     /* 4194304 full padded volume */
#define NB  (128*64*64)       /* 524288  crop / attention block */
#define RBLK 64

// ---------------- scratch (static device allocations, no runtime alloc) ----------------
static __device__ float2 g_bufA[2*(size_t)VOL];   // Z spectra per bd
static __device__ float2 g_bufB[4*(size_t)VOL];   // G1,G2 per bd -> P,Q
static __device__ float2 g_zc[2*(size_t)NB];      // conv+mtx packed complex (cos + i sin)
static __device__ float  g_sq[2*(size_t)NB];      // sqrt(mag) crop
static __device__ float  g_Mc[128*128];
static __device__ float  g_Ms[128*128];
static __device__ float2 g_tw[128];               // W_256^k, k<128 (forward sign)

// attention reduction state
static __device__ double g_pD[2][RBLK];
static __device__ float  g_pMnL[2][RBLK], g_pMxL[2][RBLK], g_pMnH[2][RBLK], g_pMxH[2][RBLK];
static __device__ float  g_a1[2], g_c1[2], g_M1f[2], g_Z1i[2];
static __device__ float  g_a2[2], g_c2[2], g_M2f[2], g_Z2i[2];
static __device__ float  g_mnH[2], g_mxH[2];
static __device__ double g_Z1d[2];

__device__ __forceinline__ float2 cmul(float2 a, float2 b){
    return make_float2(a.x*b.x - a.y*b.y, a.x*b.y + a.y*b.x);
}
__device__ __forceinline__ int brev7(int i){ return (int)(__brev((unsigned)i) >> 25); }
__device__ __forceinline__ int brev8(int i){ return (int)(__brev((unsigned)i) >> 24); }

// ---------------- init ----------------
__global__ void k_init_tw(){
    int i = threadIdx.x;
    if (i < 128){
        double a = -2.0*3.14159265358979323846*(double)i/256.0;
        double s, c; sincos(a, &s, &c);
        g_tw[i] = make_float2((float)c, (float)s);
    }
}

// Mc[t][j] = sum_m mtx[t][m] * waveC[j-m+31], same for Ms with waveS (k=63 taps)
__global__ void k_build_M(const float* __restrict__ mtx, const float* __restrict__ wave){
    int idx = blockIdx.x*blockDim.x + threadIdx.x;
    if (idx >= 128*128) return;
    int t = idx >> 7, j = idx & 127;
    float ac = 0.f, as = 0.f;
    for (int m = 0; m < 128; m++){
        int tau = j - m + 31;
        if (tau >= 0 && tau < 63){
            float mv = mtx[t*128 + m];
            ac = fmaf(mv, wave[tau],      ac);
            as = fmaf(mv, wave[63 + tau], as);
        }
    }
    g_Mc[idx] = ac; g_Ms[idx] = as;
}

// ---------------- conv+mtx -> packed complex ----------------
__global__ __launch_bounds__(256) void k_conv_mtx(const float* __restrict__ feat){
    __shared__ float sx[128*64];
    int bd = blockIdx.x >> 6, h = blockIdx.x & 63;
    const float* src = feat + (size_t)bd*NB + h*64;
    for (int i = threadIdx.x; i < 128*64; i += 256){
        int t = i >> 6, w = i & 63;
        sx[i] = src[(size_t)t*4096 + w];
    }
    __syncthreads();
    float2* dst = g_zc + (size_t)bd*NB + h*64;
    for (int o = threadIdx.x; o < 128*64; o += 256){
        int t = o >> 6, w = o & 63;
        float ac = 0.f, as = 0.f;
        const float* mc = g_Mc + t*128;
        const float* ms = g_Ms + t*128;
        #pragma unroll 8
        for (int m = 0; m < 128; m++){
            float xv = sx[m*64 + w];
            ac = fmaf(mc[m], xv, ac);
            as = fmaf(ms[m], xv, as);
        }
        dst[(size_t)t*4096 + w] = make_float2(ac, as);
    }
}

// ---------------- forward W-pass: length-128 FFT of (64 data + 64 zeros) ----------------
__global__ __launch_bounds__(256) void k_fwdW(){
    __shared__ float2 s[4][128];
    int team = threadIdx.x >> 6, tl = threadIdx.x & 63;
    int L = blockIdx.x*4 + team;            // 0..8191
    int bd = blockIdx.y;
    int t = L >> 6, h = L & 63;
    const float2* src = g_zc + (size_t)bd*NB + (size_t)t*4096 + h*64;
    s[team][brev7(tl)]      = src[tl];
    s[team][brev7(tl + 64)] = make_float2(0.f, 0.f);
    __syncthreads();
    #pragma unroll
    for (int len = 2; len <= 128; len <<= 1){
        int half = len >> 1;
        int grp = tl / half, pos = tl - grp*half;
        float2 w = g_tw[pos * (256/len)];
        int i0 = grp*len + pos;
        float2 b = cmul(s[team][i0 + half], w);
        float2 a = s[team][i0];
        s[team][i0]        = make_float2(a.x + b.x, a.y + b.y);
        s[team][i0 + half] = make_float2(a.x - b.x, a.y - b.y);
        __syncthreads();
    }
    size_t dst = (size_t)bd*VOL + (size_t)t*16384 + h*128;
    g_bufA[dst + tl]      = s[team][tl];
    g_bufA[dst + tl + 64] = s[team][tl + 64];
}

// ---------------- H-pass (length-128, stride-128 lines), fwd & inv ----------------
__global__ __launch_bounds__(256) void k_fftH(int useB, int inv, int loadHalf, int storeHalf, float scale){
    __shared__ float2 s[128*33];
    float2* buf = useB ? g_bufB : g_bufA;
    int t = blockIdx.x, wb = blockIdx.y << 5;
    size_t base = (size_t)blockIdx.z*VOL + (size_t)t*16384 + wb;
    for (int i = threadIdx.x; i < 128*32; i += 256){
        int h = i >> 5, lane = i & 31;
        float2 v = make_float2(0.f, 0.f);
        if (!loadHalf || h < 64) v = buf[base + (size_t)h*128 + lane];
        s[brev7(h)*33 + lane] = v;
    }
    __syncthreads();
    #pragma unroll
    for (int len = 2; len <= 128; len <<= 1){
        int half = len >> 1;
        for (int j = threadIdx.x; j < 64*32; j += 256){
            int lane = j & 31, bf = j >> 5;
            int grp = bf / half, pos = bf - grp*half;
            float2 w = g_tw[pos * (256/len)];
            if (inv) w.y = -w.y;
            int i0 = (grp*len + pos)*33 + lane;
            int i1 = i0 + half*33;
            float2 b = cmul(s[i1], w);
            float2 a = s[i0];
            s[i0] = make_float2(a.x + b.x, a.y + b.y);
            s[i1] = make_float2(a.x - b.x, a.y - b.y);
        }
        __syncthreads();
    }
    int hmax = storeHalf ? 64 : 128;
    for (int i = threadIdx.x; i < hmax*32; i += 256){
        int h = i >> 5, lane = i & 31;
        float2 v = s[h*33 + lane];
        buf[base + (size_t)h*128 + lane] = make_float2(v.x*scale, v.y*scale);
    }
}

// ---------------- T-pass (length-256, stride-16384 lines), fwd & inv ----------------
__global__ __launch_bounds__(256) void k_fftT(int useB, int inv, int loadHalf, int storeHalf, float scale){
    __shared__ float2 s[256*17];
    float2* buf = useB ? g_bufB : g_bufA;
    int h = blockIdx.x, wb = blockIdx.y << 4;
    size_t base = (size_t)blockIdx.z*VOL + (size_t)h*128 + wb;
    for (int i = threadIdx.x; i < 256*16; i += 256){
        int t = i >> 4, lane = i & 15;
        float2 v = make_float2(0.f, 0.f);
        if (!loadHalf || t < 128) v = buf[base + (size_t)t*16384 + lane];
        s[brev8(t)*17 + lane] = v;
    }
    __syncthreads();
    #pragma unroll
    for (int len = 2; len <= 256; len <<= 1){
        int half = len >> 1;
        for (int j = threadIdx.x; j < 128*16; j += 256){
            int lane = j & 15, bf = j >> 4;
            int grp = bf / half, pos = bf - grp*half;
            float2 w = g_tw[pos * (256/len)];
            if (inv) w.y = -w.y;
            int i0 = (grp*len + pos)*17 + lane;
            int i1 = i0 + half*17;
            float2 b = cmul(s[i1], w);
            float2 a = s[i0];
            s[i0] = make_float2(a.x + b.x, a.y + b.y);
            s[i1] = make_float2(a.x - b.x, a.y - b.y);
        }
        __syncthreads();
    }
    int tmax = storeHalf ? 128 : 256;
    for (int i = threadIdx.x; i < tmax*16; i += 256){
        int t = i >> 4, lane = i & 15;
        float2 v = s[t*17 + lane];
        buf[base + (size_t)t*16384 + lane] = make_float2(v.x*scale, v.y*scale);
    }
}

// ---------------- attention scalar reductions ----------------
__device__ double blockReduceD(double v){
    __shared__ double sh[256];
    sh[threadIdx.x] = v; __syncthreads();
    for (int s = 128; s; s >>= 1){ if (threadIdx.x < s) sh[threadIdx.x] += sh[threadIdx.x + s]; __syncthreads(); }
    double r = sh[0]; __syncthreads(); return r;
}
__device__ float blockReduceMin(float v){
    __shared__ float sh[256];
    sh[threadIdx.x] = v; __syncthreads();
    for (int s = 128; s; s >>= 1){ if (threadIdx.x < s) sh[threadIdx.x] = fminf(sh[threadIdx.x], sh[threadIdx.x + s]); __syncthreads(); }
    float r = sh[0]; __syncthreads(); return r;
}
__device__ float blockReduceMax(float v){
    __shared__ float sh[256];
    sh[threadIdx.x] = v; __syncthreads();
    for (int s = 128; s; s >>= 1){ if (threadIdx.x < s) sh[threadIdx.x] = fmaxf(sh[threadIdx.x], sh[threadIdx.x + s]); __syncthreads(); }
    float r = sh[0]; __syncthreads(); return r;
}

__device__ __forceinline__ void block_elems(const float* K, int j, float& kL, float& kH, float& vL){
    int tl = j >> 12, hl = (j >> 6) & 63, wl = j & 63;
    float pe = sinf((float)tl);
    vL = K[((192 + tl) & 255)*16384 + ((96 + hl) & 127)*128 + ((96 + wl) & 127)];
    float vH = K[(64 + tl)*16384 + (32 + hl)*128 + (32 + wl)];
    kL = vL + pe; kH = vH + pe;
}

__global__ __launch_bounds__(256) void k_redA(const float* __restrict__ invr, const float* __restrict__ invi){
    int f = blockIdx.y;
    const float* K = f ? invi : invr;
    double sum = 0.0;
    float mnL = 3.4e38f, mxL = -3.4e38f, mnH = 3.4e38f, mxH = -3.4e38f;
    for (int j = blockIdx.x*256 + threadIdx.x; j < NB; j += RBLK*256){
        float kL, kH, vL; block_elems(K, j, kL, kH, vL);
        sum += (double)vL;
        mnL = fminf(mnL, kL); mxL = fmaxf(mxL, kL);
        mnH = fminf(mnH, kH); mxH = fmaxf(mxH, kH);
    }
    sum = blockReduceD(sum);
    mnL = blockReduceMin(mnL); mxL = blockReduceMax(mxL);
    mnH = blockReduceMin(mnH); mxH = blockReduceMax(mxH);
    if (threadIdx.x == 0){
        g_pD[f][blockIdx.x] = sum;
        g_pMnL[f][blockIdx.x] = mnL; g_pMxL[f][blockIdx.x] = mxL;
        g_pMnH[f][blockIdx.x] = mnH; g_pMxH[f][blockIdx.x] = mxH;
    }
}

__global__ void k_combA(const float* __restrict__ wp, const float* __restrict__ bp){
    int f = blockIdx.x, i = threadIdx.x;
    __shared__ double sd[64]; __shared__ float s1[64], s2[64], s3[64], s4[64];
    sd[i] = g_pD[f][i]; s1[i] = g_pMnL[f][i]; s2[i] = g_pMxL[f][i]; s3[i] = g_pMnH[f][i]; s4[i] = g_pMxH[f][i];
    __syncthreads();
    for (int s = 32; s; s >>= 1){
        if (i < s){
            sd[i] += sd[i+s];
            s1[i] = fminf(s1[i], s1[i+s]); s2[i] = fmaxf(s2[i], s2[i+s]);
            s3[i] = fminf(s3[i], s3[i+s]); s4[i] = fmaxf(s4[i], s4[i+s]);
        }
        __syncthreads();
    }
    if (i == 0){
        float W = *wp, B = *bp;
        float scal1 = W*(float)(sd[0]/(double)NB) + B;
        float a1 = scal1*W, c1 = scal1*B;
        g_a1[f] = a1; g_c1[f] = c1;
        g_M1f[f] = (a1 >= 0.f ? a1*s2[0] : a1*s1[0]) + c1;
        g_mnH[f] = s3[0]; g_mxH[f] = s4[0];
    }
}

__global__ __launch_bounds__(256) void k_redB(const float* __restrict__ invr, const float* __restrict__ invi){
    int f = blockIdx.y; const float* K = f ? invi : invr;
    float a1 = g_a1[f], c1 = g_c1[f], M1 = g_M1f[f];
    double acc = 0.0;
    for (int j = blockIdx.x*256 + threadIdx.x; j < NB; j += RBLK*256){
        float kL, kH, vL; block_elems(K, j, kL, kH, vL);
        acc += (double)expf(fmaf(a1, kL, c1) - M1);
    }
    acc = blockReduceD(acc);
    if (threadIdx.x == 0) g_pD[f][blockIdx.x] = acc;
}
__global__ void k_combB(){
    int f = blockIdx.x, i = threadIdx.x;
    __shared__ double sd[64];
    sd[i] = g_pD[f][i]; __syncthreads();
    for (int s = 32; s; s >>= 1){ if (i < s) sd[i] += sd[i+s]; __syncthreads(); }
    if (i == 0){ g_Z1d[f] = sd[0]; g_Z1i[f] = (float)(1.0/sd[0]); }
}

__global__ __launch_bounds__(256) void k_redC(const float* __restrict__ invr, const float* __restrict__ invi){
    int f = blockIdx.y; const float* K = f ? invi : invr;
    float a1 = g_a1[f], c1 = g_c1[f], M1 = g_M1f[f], Z1i = g_Z1i[f];
    double acc = 0.0;
    for (int j = blockIdx.x*256 + threadIdx.x; j < NB; j += RBLK*256){
        float kL, kH, vL; block_elems(K, j, kL, kH, vL);
        float sm = expf(fmaf(a1, kL, c1) - M1) * Z1i;
        acc += (double)(kL / (1.f + expf(-sm)));
    }
    acc = blockReduceD(acc);
    if (threadIdx.x == 0) g_pD[f][blockIdx.x] = acc;
}
__global__ void k_combC(const float* __restrict__ wp, const float* __restrict__ bp){
    int f = blockIdx.x, i = threadIdx.x;
    __shared__ double sd[64];
    sd[i] = g_pD[f][i]; __syncthreads();
    for (int s = 32; s; s >>= 1){ if (i < s) sd[i] += sd[i+s]; __syncthreads(); }
    if (i == 0){
        float W = *wp, B = *bp;
        float scal2 = W*(float)(sd[0]/(double)NB) + B;
        float a2 = scal2*W, c2 = scal2*B;
        g_a2[f] = a2; g_c2[f] = c2;
        g_M2f[f] = (a2 >= 0.f ? a2*g_mxH[f] : a2*g_mnH[f]) + c2;
    }
}

__global__ __launch_bounds__(256) void k_redD(const float* __restrict__ invr, const float* __restrict__ invi){
    int f = blockIdx.y; const float* K = f ? invi : invr;
    float a2 = g_a2[f], c2 = g_c2[f], M2 = g_M2f[f];
    double acc = 0.0;
    for (int j = blockIdx.x*256 + threadIdx.x; j < NB; j += RBLK*256){
        float kL, kH, vL; block_elems(K, j, kL, kH, vL);
        acc += (double)expf(fmaf(a2, kH, c2) - M2);
    }
    acc = blockReduceD(acc);
    if (threadIdx.x == 0) g_pD[f][blockIdx.x] = acc;
}
__global__ void k_combD(){
    int f = blockIdx.x, i = threadIdx.x;
    __shared__ double sd[64];
    sd[i] = g_pD[f][i]; __syncthreads();
    for (int s = 32; s; s >>= 1){ if (i < s) sd[i] += sd[i+s]; __syncthreads(); }
    if (i == 0) g_Z2i[f] = (float)(1.0/sd[0]);
}

// ---------------- spectral multiply with inline attention filter ----------------
__device__ __forceinline__ float atten_filter(float v, int t, int h, int w, int f){
    int tl = t - 64, hl = h - 32, wl = w - 32;
    if ((unsigned)tl < 128u && (unsigned)hl < 64u && (unsigned)wl < 64u){
        float k2p = v + sinf((float)tl);
        float sm = expf(fmaf(g_a2[f], k2p, g_c2[f]) - g_M2f[f]) * g_Z2i[f];
        return k2p / (1.f + expf(-sm));
    }
    int tl2 = (t + 64) & 255, hl2 = (h + 32) & 127, wl2 = (w + 32) & 127;
    if (tl2 < 128 && hl2 < 64 && wl2 < 64){
        float k2p = v + sinf((float)tl2);
        float sm = expf(fmaf(g_a1[f], k2p, g_c1[f]) - g_M1f[f]) * g_Z1i[f];
        return k2p / (1.f + expf(-sm));
    }
    return v;
}

__global__ __launch_bounds__(256) void k_spectral(const float* __restrict__ invr, const float* __restrict__ invi){
    int idx = blockIdx.x*256 + threadIdx.x;
    int bd = blockIdx.y;
    int t = idx >> 14, h = (idx >> 7) & 127, w = idx & 127;
    float w1 = atten_filter(invr[idx], t, h, w, 0);
    float w2 = atten_filter(invi[idx], t, h, w, 1);
    const float2* Z = g_bufA + (size_t)bd*VOL;
    float2 Zk = Z[idx];
    int tn = (-t) & 255, hn = (-h) & 127, wn = (-w) & 127;
    float2 Zn = Z[(size_t)tn*16384 + hn*128 + wn];
    float2 W = make_float2(w1, w2);
    float2 G1 = cmul(W, Zk);
    float2 G2 = cmul(W, make_float2(Zn.x, -Zn.y));
    g_bufB[(size_t)(2*bd    )*VOL + idx] = G1;
    g_bufB[(size_t)(2*bd + 1)*VOL + idx] = G2;
}

// ---------------- inverse W-pass fused with P*Q, mag, sqrt ----------------
__global__ __launch_bounds__(256) void k_invWfinal(){
    __shared__ float2 sP[2][128], sQ[2][128];
    int team = threadIdx.x >> 7, tl = threadIdx.x & 127;
    int Lg = blockIdx.x*2 + team;           // 0..16383
    int bd = Lg >> 13, r = Lg & 8191;
    int t = r >> 6, h = r & 63;
    size_t baseP = (size_t)(2*bd)*VOL + (size_t)t*16384 + h*128;
    int rb = brev7(tl);
    sP[team][rb] = g_bufB[baseP + tl];
    sQ[team][rb] = g_bufB[baseP + VOL + tl];
    __syncthreads();
    float2* arr = (tl < 64) ? sP[team] : sQ[team];
    int bf = tl & 63;
    #pragma unroll
    for (int len = 2; len <= 128; len <<= 1){
        int half = len >> 1;
        int grp = bf / half, pos = bf - grp*half;
        float2 w = g_tw[pos * (256/len)];
        w.y = -w.y;                          // inverse
        int i0 = grp*len + pos;
        float2 b = cmul(arr[i0 + half], w);
        float2 a = arr[i0];
        arr[i0]        = make_float2(a.x + b.x, a.y + b.y);
        arr[i0 + half] = make_float2(a.x - b.x, a.y - b.y);
        __syncthreads();
    }
    if (tl < 64){
        const float s2 = 1.f/(128.f*128.f);  // remaining 1/128 per inverse W FFT, twice
        float2 P = sP[team][tl], Q = sQ[team][tl];
        float Sr = (P.x*Q.x - P.y*Q.y)*s2;
        float Si = (P.x*Q.y + P.y*Q.x)*s2;
        float mag = 0.5f*(sqrtf(Sr*Sr + Si*Si) + Sr);
        mag = fmaxf(mag, 0.f);
        g_sq[(size_t)bd*NB + (size_t)t*4096 + h*64 + tl] = sqrtf(mag);
    }
}

// ---------------- final mtxi matmul along T ----------------
__global__ __launch_bounds__(256) void k_final(const float* __restrict__ mtxi, float* __restrict__ out){
    __shared__ float sx[128*64];
    int bd = blockIdx.x >> 6, h = blockIdx.x & 63;
    const float* src = g_sq + (size_t)bd*NB + h*64;
    for (int i = threadIdx.x; i < 128*64; i += 256){
        int t = i >> 6, w = i & 63;
        sx[i] = src[(size_t)t*4096 + w];
    }
    __syncthreads();
    float* dst = out + (size_t)bd*NB + h*64;
    for (int o = threadIdx.x; o < 128*64; o += 256){
        int t = o >> 6, w = o & 63;
        float acc = 0.f;
        const float* mi = mtxi + t*128;
        #pragma unroll 8
        for (int m = 0; m < 128; m++) acc = fmaf(mi[m], sx[m*64 + w], acc);
        dst[(size_t)t*4096 + w] = acc;
    }
}

// ---------------- launch ----------------
extern "C" void kernel_launch(void* const* d_in, const int* in_sizes, int n_in,
                              void* d_out, int out_size){
    const float *feature = 0, *conv_w = 0, *conv_b = 0, *wave = 0;
    const float *invr = 0, *invi = 0, *mtx = 0, *mtxi = 0;
    int scal_seen = 0, mat_seen = 0, psf_seen = 0;
    for (int i = 0; i < n_in; i++){
        const float* p = (const float*)d_in[i];
        int s = in_sizes[i];
        if      (s == 1)       { if (scal_seen++ == 0) conv_w = p; else conv_b = p; }
        else if (s == 126)     wave = p;
        else if (s == 16384)   { if (mat_seen++ == 0) mtx = p; else mtxi = p; }
        else if (s == 4194304) { if (psf_seen++ == 0) invr = p; else invi = p; }
        else if (s == 1048576) feature = p;
    }
    float* out = (float*)d_out;

    k_init_tw<<<1,128>>>();
    k_build_M<<<64,256>>>(mtx, wave);
    k_conv_mtx<<<128,256>>>(feature);

    // forward 3D FFT (exploit zero padding)
    k_fwdW<<<dim3(2048,2),256>>>();
    k_fftH<<<dim3(128,4,2),256>>>(0, 0, 1, 0, 1.f);
    k_fftT<<<dim3(128,8,2),256>>>(0, 0, 1, 0, 1.f);

    // attention scalars (4 reduce + 4 combine)
    k_redA<<<dim3(RBLK,2),256>>>(invr, invi);
    k_combA<<<2,64>>>(conv_w, conv_b);
    k_redB<<<dim3(RBLK,2),256>>>(invr, invi);
    k_combB<<<2,64>>>();
    k_redC<<<dim3(RBLK,2),256>>>(invr, invi);
    k_combC<<<2,64>>>(conv_w, conv_b);
    k_redD<<<dim3(RBLK,2),256>>>(invr, invi);
    k_combD<<<2,64>>>();

    // G1 = W*Z, G2 = W*conj(Z(-k)) with inline attention-filtered W
    k_spectral<<<dim3(VOL/256,2),256>>>(invr, invi);

    // inverse 3D FFT (crop-aware) + fused P*Q/mag/sqrt
    k_fftT<<<dim3(128,8,4),256>>>(1, 1, 0, 1, 1.f/256.f);
    k_fftH<<<dim3(128,4,4),256>>>(1, 1, 0, 1, 1.f/128.f);
    k_invWfinal<<<8192,256>>>();

    k_final<<<128,256>>>(mtxi, out);
}

// round 9
// speedup vs baseline: 1.2100x; 1.2100x over previous
#include <cuda_runtime.h>
#include <math.h>

#define VOL (256*128*128)     /* 4194304 full padded volume */
#define NB  (128*64*64)       /* 524288  crop / attention block */
#define RBLK 512

// ---------------- scratch (static device allocations, no runtime alloc) ----------------
static __device__ float2 g_bufA[2*(size_t)VOL];   // Z spectra per bd
static __device__ float2 g_bufB[4*(size_t)VOL];   // P,Q per bd
static __device__ float  g_sq[2*(size_t)NB];      // sqrt(mag) crop
static __device__ float  g_Mc[128*128];
static __device__ float  g_Ms[128*128];
static __device__ float2 g_tw[128];               // W_256^k, k<128 (forward sign)

// attention reduction state
static __device__ double g_pD[2][RBLK];
static __device__ float  g_pMnL[2][RBLK], g_pMxL[2][RBLK], g_pMnH[2][RBLK], g_pMxH[2][RBLK];
static __device__ float  g_a1[2], g_c1[2], g_M1f[2], g_Z1i[2];
static __device__ float  g_a2[2], g_c2[2], g_M2f[2], g_Z2i[2];
static __device__ float  g_mnH[2], g_mxH[2];

__device__ __forceinline__ float2 cmul(float2 a, float2 b){
    return make_float2(a.x*b.x - a.y*b.y, a.x*b.y + a.y*b.x);
}
__device__ __forceinline__ float2 cadd(float2 a, float2 b){ return make_float2(a.x+b.x, a.y+b.y); }
__device__ __forceinline__ float2 csub(float2 a, float2 b){ return make_float2(a.x-b.x, a.y-b.y); }
__device__ __forceinline__ int brev7(int i){ return (int)(__brev((unsigned)i) >> 25); }
__device__ __forceinline__ int dr4(int x){   // base-4 digit reversal of 8-bit value
    return ((x&3)<<6) | ((x&12)<<2) | ((x&48)>>2) | ((x&192)>>6);
}

// ---------------- init ----------------
__global__ void k_init_tw(){
    int i = threadIdx.x;
    if (i < 128){
        double a = -2.0*3.14159265358979323846*(double)i/256.0;
        double s, c; sincos(a, &s, &c);
        g_tw[i] = make_float2((float)c, (float)s);
    }
}

// Mc[t][j] = sum_m mtx[t][m] * waveC[j-m+31] (k=63 taps), same for Ms
__global__ void k_build_M(const float* __restrict__ mtx, const float* __restrict__ wave){
    int idx = blockIdx.x*blockDim.x + threadIdx.x;
    if (idx >= 128*128) return;
    int t = idx >> 7, j = idx & 127;
    float ac = 0.f, as = 0.f;
    for (int m = 0; m < 128; m++){
        int tau = j - m + 31;
        if (tau >= 0 && tau < 63){
            float mv = mtx[t*128 + m];
            ac = fmaf(mv, wave[tau],      ac);
            as = fmaf(mv, wave[63 + tau], as);
        }
    }
    g_Mc[idx] = ac; g_Ms[idx] = as;
}

// ---------------- fused conv+mtx + forward W-FFT (64 data + 64 zeros -> 128) ----------------
// per block: (bd,h). dyn smem: sx 32768 + sz 128*129*8 + stw 1024
__global__ __launch_bounds__(512) void k_conv_fwdW(const float* __restrict__ feat){
    extern __shared__ unsigned char smraw[];
    float*  sx  = (float*)smraw;                          // 128t x 64w input
    float2* sz  = (float2*)(smraw + 32768);               // [wpos*129 + t]
    float2* stw = (float2*)(smraw + 32768 + 132096);
    int tid = threadIdx.x;
    int bd = blockIdx.x >> 6, h = blockIdx.x & 63;
    if (tid < 128) stw[tid] = g_tw[tid];
    const float* src = feat + (size_t)bd*NB + h*64;
    for (int i = tid; i < 128*64; i += 512){
        int t = i >> 6, w = i & 63;
        sx[i] = src[(size_t)t*4096 + w];
    }
    __syncthreads();
    // conv+mtx -> scatter bit-reversed along w (zeros at odd bitrev slots)
    for (int o = tid; o < 128*64; o += 512){
        int t = o >> 6, w = o & 63;
        float ac = 0.f, as = 0.f;
        const float* mc = g_Mc + t*128;
        const float* ms = g_Ms + t*128;
        #pragma unroll 8
        for (int m = 0; m < 128; m++){
            float xv = sx[m*64 + w];
            ac = fmaf(mc[m], xv, ac);
            as = fmaf(ms[m], xv, as);
        }
        int p = brev7(w);                 // even for w<64
        sz[p*129 + t]     = make_float2(ac, as);
        sz[(p|1)*129 + t] = make_float2(0.f, 0.f);
    }
    __syncthreads();
    // radix-2 stage (L=1)
    for (int j = tid; j < 64*128; j += 512){
        int t = j & 127, g = j >> 7;
        float2 a = sz[(2*g)*129 + t], b = sz[(2*g+1)*129 + t];
        sz[(2*g)*129 + t]   = cadd(a, b);
        sz[(2*g+1)*129 + t] = csub(a, b);
    }
    __syncthreads();
    // fused radix-4 stages (two radix-2 DIT stages), forward
    for (int L = 2; L <= 32; L <<= 2){
        for (int j = tid; j < 32*128; j += 512){
            int t = j & 127, o = j >> 7;
            int grp = o / L, k = o - grp*L;
            int i0 = grp*4*L + k;
            float2 A = sz[i0*129+t], B = sz[(i0+L)*129+t];
            float2 C = sz[(i0+2*L)*129+t], D = sz[(i0+3*L)*129+t];
            float2 w1 = stw[k*(256/(2*L))];
            float2 w2 = stw[k*(256/(4*L))];
            float2 Bt = cmul(w1,B), Dt = cmul(w1,D);
            float2 A1 = cadd(A,Bt), B1 = csub(A,Bt);
            float2 C1 = cadd(C,Dt), D1 = csub(C,Dt);
            float2 C2 = cmul(w2,C1), D2 = cmul(w2,D1);
            float2 D2m = make_float2(D2.y, -D2.x);       // -i * D2 (forward)
            sz[i0*129+t]       = cadd(A1,C2);
            sz[(i0+2*L)*129+t] = csub(A1,C2);
            sz[(i0+L)*129+t]   = cadd(B1,D2m);
            sz[(i0+3*L)*129+t] = csub(B1,D2m);
        }
        __syncthreads();
    }
    float2* dst = g_bufA + (size_t)bd*VOL + h*128;
    for (int i = tid; i < 128*128; i += 512){
        int t = i >> 7, w = i & 127;
        dst[(size_t)t*16384 + w] = sz[w*129 + t];
    }
}

// ---------------- forward H-pass (radix-4), t<128 lines, loads h<64, stores full h ------
__global__ __launch_bounds__(256) void k_fwdH(){
    __shared__ float2 s[128*33];
    __shared__ float2 stw[128];
    int tid = threadIdx.x;
    if (tid < 128) stw[tid] = g_tw[tid];
    int t = blockIdx.x, wb = blockIdx.y << 5, bd = blockIdx.z;
    size_t base = (size_t)bd*VOL + (size_t)t*16384 + wb;
    for (int i = tid; i < 128*32; i += 256){
        int hh = i >> 5, lane = i & 31;
        float2 v = make_float2(0.f, 0.f);
        if (hh < 64) v = g_bufA[base + (size_t)hh*128 + lane];
        s[brev7(hh)*33 + lane] = v;
    }
    __syncthreads();
    for (int j = tid; j < 64*32; j += 256){
        int lane = j & 31, g = j >> 5;
        float2 a = s[(2*g)*33+lane], b = s[(2*g+1)*33+lane];
        s[(2*g)*33+lane]   = cadd(a, b);
        s[(2*g+1)*33+lane] = csub(a, b);
    }
    __syncthreads();
    for (int L = 2; L <= 32; L <<= 2){
        for (int j = tid; j < 32*32; j += 256){
            int lane = j & 31, o = j >> 5;
            int grp = o / L, k = o - grp*L;
            int i0 = grp*4*L + k;
            float2 A = s[i0*33+lane], B = s[(i0+L)*33+lane];
            float2 C = s[(i0+2*L)*33+lane], D = s[(i0+3*L)*33+lane];
            float2 w1 = stw[k*(256/(2*L))];
            float2 w2 = stw[k*(256/(4*L))];
            float2 Bt = cmul(w1,B), Dt = cmul(w1,D);
            float2 A1 = cadd(A,Bt), B1 = csub(A,Bt);
            float2 C1 = cadd(C,Dt), D1 = csub(C,Dt);
            float2 C2 = cmul(w2,C1), D2 = cmul(w2,D1);
            float2 D2m = make_float2(D2.y, -D2.x);
            s[i0*33+lane]       = cadd(A1,C2);
            s[(i0+2*L)*33+lane] = csub(A1,C2);
            s[(i0+L)*33+lane]   = cadd(B1,D2m);
            s[(i0+3*L)*33+lane] = csub(B1,D2m);
        }
        __syncthreads();
    }
    for (int i = tid; i < 128*32; i += 256){
        int hh = i >> 5, lane = i & 31;
        g_bufA[base + (size_t)hh*128 + lane] = s[hh*33 + lane];
    }
}

// ---------------- inverse H-pass (radix-4), loads full h, stores h<64, scale 1/128 ------
__global__ __launch_bounds__(256) void k_invH(){
    __shared__ float2 s[128*33];
    __shared__ float2 stw[128];
    int tid = threadIdx.x;
    if (tid < 128){ float2 w = g_tw[tid]; stw[tid] = make_float2(w.x, -w.y); } // conj
    int t = blockIdx.x, wb = blockIdx.y << 5, vol = blockIdx.z;
    size_t base = (size_t)vol*VOL + (size_t)t*16384 + wb;
    for (int i = tid; i < 128*32; i += 256){
        int hh = i >> 5, lane = i & 31;
        s[brev7(hh)*33 + lane] = g_bufB[base + (size_t)hh*128 + lane];
    }
    __syncthreads();
    for (int j = tid; j < 64*32; j += 256){
        int lane = j & 31, g = j >> 5;
        float2 a = s[(2*g)*33+lane], b = s[(2*g+1)*33+lane];
        s[(2*g)*33+lane]   = cadd(a, b);
        s[(2*g+1)*33+lane] = csub(a, b);
    }
    __syncthreads();
    for (int L = 2; L <= 32; L <<= 2){
        for (int j = tid; j < 32*32; j += 256){
            int lane = j & 31, o = j >> 5;
            int grp = o / L, k = o - grp*L;
            int i0 = grp*4*L + k;
            float2 A = s[i0*33+lane], B = s[(i0+L)*33+lane];
            float2 C = s[(i0+2*L)*33+lane], D = s[(i0+3*L)*33+lane];
            float2 w1 = stw[k*(256/(2*L))];
            float2 w2 = stw[k*(256/(4*L))];
            float2 Bt = cmul(w1,B), Dt = cmul(w1,D);
            float2 A1 = cadd(A,Bt), B1 = csub(A,Bt);
            float2 C1 = cadd(C,Dt), D1 = csub(C,Dt);
            float2 C2 = cmul(w2,C1), D2 = cmul(w2,D1);
            float2 D2m = make_float2(-D2.y, D2.x);       // +i * D2 (inverse)
            s[i0*33+lane]       = cadd(A1,C2);
            s[(i0+2*L)*33+lane] = csub(A1,C2);
            s[(i0+L)*33+lane]   = cadd(B1,D2m);
            s[(i0+3*L)*33+lane] = csub(B1,D2m);
        }
        __syncthreads();
    }
    const float sc = 1.f/128.f;
    for (int i = tid; i < 64*32; i += 256){
        int hh = i >> 5, lane = i & 31;
        float2 v = s[hh*33 + lane];
        g_bufB[base + (size_t)hh*128 + lane] = make_float2(v.x*sc, v.y*sc);
    }
}

// ---------------- attention scalar reductions ----------------
__device__ double blockReduceD(double v){
    __shared__ double sh[256];
    sh[threadIdx.x] = v; __syncthreads();
    for (int s = 128; s; s >>= 1){ if (threadIdx.x < s) sh[threadIdx.x] += sh[threadIdx.x + s]; __syncthreads(); }
    double r = sh[0]; __syncthreads(); return r;
}
__device__ float blockReduceMin(float v){
    __shared__ float sh[256];
    sh[threadIdx.x] = v; __syncthreads();
    for (int s = 128; s; s >>= 1){ if (threadIdx.x < s) sh[threadIdx.x] = fminf(sh[threadIdx.x], sh[threadIdx.x + s]); __syncthreads(); }
    float r = sh[0]; __syncthreads(); return r;
}
__device__ float blockReduceMax(float v){
    __shared__ float sh[256];
    sh[threadIdx.x] = v; __syncthreads();
    for (int s = 128; s; s >>= 1){ if (threadIdx.x < s) sh[threadIdx.x] = fmaxf(sh[threadIdx.x], sh[threadIdx.x + s]); __syncthreads(); }
    float r = sh[0]; __syncthreads(); return r;
}

__device__ __forceinline__ void block_elems(const float* K, int j, float& kL, float& kH, float& vL){
    int tl = j >> 12, hl = (j >> 6) & 63, wl = j & 63;
    float pe = sinf((float)tl);
    vL = K[((192 + tl) & 255)*16384 + ((96 + hl) & 127)*128 + ((96 + wl) & 127)];
    float vH = K[(64 + tl)*16384 + (32 + hl)*128 + (32 + wl)];
    kL = vL + pe; kH = vH + pe;
}

__global__ __launch_bounds__(256) void k_redA(const float* __restrict__ invr, const float* __restrict__ invi){
    int f = blockIdx.y;
    const float* K = f ? invi : invr;
    double sum = 0.0;
    float mnL = 3.4e38f, mxL = -3.4e38f, mnH = 3.4e38f, mxH = -3.4e38f;
    for (int j = blockIdx.x*256 + threadIdx.x; j < NB; j += RBLK*256){
        float kL, kH, vL; block_elems(K, j, kL, kH, vL);
        sum += (double)vL;
        mnL = fminf(mnL, kL); mxL = fmaxf(mxL, kL);
        mnH = fminf(mnH, kH); mxH = fmaxf(mxH, kH);
    }
    sum = blockReduceD(sum);
    mnL = blockReduceMin(mnL); mxL = blockReduceMax(mxL);
    mnH = blockReduceMin(mnH); mxH = blockReduceMax(mxH);
    if (threadIdx.x == 0){
        g_pD[f][blockIdx.x] = sum;
        g_pMnL[f][blockIdx.x] = mnL; g_pMxL[f][blockIdx.x] = mxL;
        g_pMnH[f][blockIdx.x] = mnH; g_pMxH[f][blockIdx.x] = mxH;
    }
}

__global__ void k_combA(const float* __restrict__ wp, const float* __restrict__ bp){
    int f = blockIdx.x, i = threadIdx.x;   // 256 threads over 512 partials
    __shared__ double sd[256]; __shared__ float s1[256], s2[256], s3[256], s4[256];
    sd[i] = g_pD[f][i] + g_pD[f][i+256];
    s1[i] = fminf(g_pMnL[f][i], g_pMnL[f][i+256]);
    s2[i] = fmaxf(g_pMxL[f][i], g_pMxL[f][i+256]);
    s3[i] = fminf(g_pMnH[f][i], g_pMnH[f][i+256]);
    s4[i] = fmaxf(g_pMxH[f][i], g_pMxH[f][i+256]);
    __syncthreads();
    for (int s = 128; s; s >>= 1){
        if (i < s){
            sd[i] += sd[i+s];
            s1[i] = fminf(s1[i], s1[i+s]); s2[i] = fmaxf(s2[i], s2[i+s]);
            s3[i] = fminf(s3[i], s3[i+s]); s4[i] = fmaxf(s4[i], s4[i+s]);
        }
        __syncthreads();
    }
    if (i == 0){
        float W = *wp, B = *bp;
        float scal1 = W*(float)(sd[0]/(double)NB) + B;
        float a1 = scal1*W, c1 = scal1*B;
        g_a1[f] = a1; g_c1[f] = c1;
        g_M1f[f] = (a1 >= 0.f ? a1*s2[0] : a1*s1[0]) + c1;
        g_mnH[f] = s3[0]; g_mxH[f] = s4[0];
    }
}

__global__ __launch_bounds__(256) void k_redB(const float* __restrict__ invr, const float* __restrict__ invi){
    int f = blockIdx.y; const float* K = f ? invi : invr;
    float a1 = g_a1[f], c1 = g_c1[f], M1 = g_M1f[f];
    double acc = 0.0;
    for (int j = blockIdx.x*256 + threadIdx.x; j < NB; j += RBLK*256){
        float kL, kH, vL; block_elems(K, j, kL, kH, vL);
        acc += (double)expf(fmaf(a1, kL, c1) - M1);
    }
    acc = blockReduceD(acc);
    if (threadIdx.x == 0) g_pD[f][blockIdx.x] = acc;
}
__global__ void k_combB(){
    int f = blockIdx.x, i = threadIdx.x;
    __shared__ double sd[256];
    sd[i] = g_pD[f][i] + g_pD[f][i+256]; __syncthreads();
    for (int s = 128; s; s >>= 1){ if (i < s) sd[i] += sd[i+s]; __syncthreads(); }
    if (i == 0) g_Z1i[f] = (float)(1.0/sd[0]);
}

__global__ __launch_bounds__(256) void k_redC(const float* __restrict__ invr, const float* __restrict__ invi){
    int f = blockIdx.y; const float* K = f ? invi : invr;
    float a1 = g_a1[f], c1 = g_c1[f], M1 = g_M1f[f], Z1i = g_Z1i[f];
    double acc = 0.0;
    for (int j = blockIdx.x*256 + threadIdx.x; j < NB; j += RBLK*256){
        float kL, kH, vL; block_elems(K, j, kL, kH, vL);
        float sm = expf(fmaf(a1, kL, c1) - M1) * Z1i;
        acc += (double)(kL / (1.f + expf(-sm)));
    }
    acc = blockReduceD(acc);
    if (threadIdx.x == 0) g_pD[f][blockIdx.x] = acc;
}
__global__ void k_combC(const float* __restrict__ wp, const float* __restrict__ bp){
    int f = blockIdx.x, i = threadIdx.x;
    __shared__ double sd[256];
    sd[i] = g_pD[f][i] + g_pD[f][i+256]; __syncthreads();
    for (int s = 128; s; s >>= 1){ if (i < s) sd[i] += sd[i+s]; __syncthreads(); }
    if (i == 0){
        float W = *wp, B = *bp;
        float scal2 = W*(float)(sd[0]/(double)NB) + B;
        float a2 = scal2*W, c2 = scal2*B;
        g_a2[f] = a2; g_c2[f] = c2;
        g_M2f[f] = (a2 >= 0.f ? a2*g_mxH[f] : a2*g_mnH[f]) + c2;
    }
}

__global__ __launch_bounds__(256) void k_redD(const float* __restrict__ invr, const float* __restrict__ invi){
    int f = blockIdx.y; const float* K = f ? invi : invr;
    float a2 = g_a2[f], c2 = g_c2[f], M2 = g_M2f[f];
    double acc = 0.0;
    for (int j = blockIdx.x*256 + threadIdx.x; j < NB; j += RBLK*256){
        float kL, kH, vL; block_elems(K, j, kL, kH, vL);
        acc += (double)expf(fmaf(a2, kH, c2) - M2);
    }
    acc = blockReduceD(acc);
    if (threadIdx.x == 0) g_pD[f][blockIdx.x] = acc;
}
__global__ void k_combD(){
    int f = blockIdx.x, i = threadIdx.x;
    __shared__ double sd[256];
    sd[i] = g_pD[f][i] + g_pD[f][i+256]; __syncthreads();
    for (int s = 128; s; s >>= 1){ if (i < s) sd[i] += sd[i+s]; __syncthreads(); }
    if (i == 0) g_Z2i[f] = (float)(1.0/sd[0]);
}

// ---------------- attention filter (pointwise) ----------------
__device__ __forceinline__ float atten_filter(float v, int t, int h, int w, int f){
    int tl = t - 64, hl = h - 32, wl = w - 32;
    if ((unsigned)tl < 128u && (unsigned)hl < 64u && (unsigned)wl < 64u){
        float k2p = v + sinf((float)tl);
        float sm = expf(fmaf(g_a2[f], k2p, g_c2[f]) - g_M2f[f]) * g_Z2i[f];
        return k2p / (1.f + expf(-sm));
    }
    int tl2 = (t + 64) & 255, hl2 = (h + 32) & 127, wl2 = (w + 32) & 127;
    if (tl2 < 128 && hl2 < 64 && wl2 < 64){
        float k2p = v + sinf((float)tl2);
        float sm = expf(fmaf(g_a1[f], k2p, g_c1[f]) - g_M1f[f]) * g_Z1i[f];
        return k2p / (1.f + expf(-sm));
    }
    return v;
}

// ---------------- fused T: fwd DIF-FFT + spectral multiply + inv DIT-FFT ----------------
// block: (w-tile 16, h, bd). dyn smem: ZA,ZB,Wc (256*17 f2 each) + stw
__global__ __launch_bounds__(256) void k_fusedT(const float* __restrict__ invr, const float* __restrict__ invi){
    extern __shared__ unsigned char smraw[];
    float2* ZA  = (float2*)smraw;
    float2* ZB  = ZA + 256*17;
    float2* Wc  = ZB + 256*17;
    float2* stw = Wc + 256*17;
    int tid = threadIdx.x;
    int wb = blockIdx.x << 4, h = blockIdx.y, bd = blockIdx.z;
    if (tid < 128) stw[tid] = g_tw[tid];
    int hn = (128 - h) & 127;
    const float2* ZS = g_bufA + (size_t)bd*VOL;
    // natural-order load (DIF wants natural input); t>=128 is zero padding
    for (int i = tid; i < 128*16; i += 256){
        int t = i >> 4, lane = i & 15;
        int w = wb + lane, wn = (128 - w) & 127;
        ZA[t*17+lane] = ZS[(size_t)t*16384 + h*128 + w];
        ZB[t*17+lane] = ZS[(size_t)t*16384 + hn*128 + wn];
        ZA[(t+128)*17+lane] = make_float2(0.f, 0.f);
        ZB[(t+128)*17+lane] = make_float2(0.f, 0.f);
    }
    // attention-filtered W, stored digit-reversed, pre-scaled by 1/256 (T inverse scale)
    const float sc = 1.f/256.f;
    for (int i = tid; i < 256*16; i += 256){
        int t = i >> 4, lane = i & 15, w = wb + lane;
        size_t gi = (size_t)t*16384 + (size_t)h*128 + w;
        float w1 = atten_filter(invr[gi], t, h, w, 0);
        float w2 = atten_filter(invi[gi], t, h, w, 1);
        Wc[dr4(t)*17+lane] = make_float2(w1*sc, w2*sc);
    }
    __syncthreads();
    // forward radix-4 DIF (natural -> dr4), both tiles
    for (int M = 256; M >= 4; M >>= 2){
        int q = M >> 2;
        for (int j = tid; j < 2048; j += 256){
            float2* S = (j < 1024) ? ZA : ZB;
            int jj = j & 1023;
            int lane = jj & 15, o = jj >> 4;
            int blk = o / q, k = o - blk*q;
            int b0 = blk*M + k;
            float2 A = S[b0*17+lane],       B = S[(b0+q)*17+lane];
            float2 C = S[(b0+2*q)*17+lane], D = S[(b0+3*q)*17+lane];
            float2 t0 = cadd(A,C), t1 = csub(A,C), t2 = cadd(B,D), t3 = csub(B,D);
            float2 w1 = stw[k*(256/M)];
            float2 w2 = cmul(w1,w1);
            float2 w3 = cmul(w1,w2);
            S[b0*17+lane] = cadd(t0,t2);
            float2 u1 = make_float2(t1.x + t3.y, t1.y - t3.x);   // t1 - i*t3
            S[(b0+q)*17+lane]   = cmul(u1, w1);
            S[(b0+2*q)*17+lane] = cmul(csub(t0,t2), w2);
            float2 u3 = make_float2(t1.x - t3.y, t1.y + t3.x);   // t1 + i*t3
            S[(b0+3*q)*17+lane] = cmul(u3, w3);
        }
        __syncthreads();
    }
    // G1 = W*Z in ZA (in place); G2 = W*conj(Z_refl(-f)) in ZB via pairwise reflection
    for (int i = tid; i < 256*16; i += 256){
        int p = i >> 4, lane = i & 15;
        ZA[p*17+lane] = cmul(Wc[p*17+lane], ZA[p*17+lane]);
    }
    for (int i = tid; i < 129*16; i += 256){
        int f = i >> 4, lane = i & 15;
        int p = dr4(f);
        if (f == 0 || f == 128){
            float2 z = ZB[p*17+lane];
            ZB[p*17+lane] = cmul(Wc[p*17+lane], make_float2(z.x, -z.y));
        } else {
            int p2 = dr4(256 - f);
            float2 z1 = ZB[p*17+lane], z2 = ZB[p2*17+lane];
            ZB[p*17+lane]  = cmul(Wc[p*17+lane],  make_float2(z2.x, -z2.y));
            ZB[p2*17+lane] = cmul(Wc[p2*17+lane], make_float2(z1.x, -z1.y));
        }
    }
    __syncthreads();
    // inverse radix-4 DIT (dr4 -> natural), both tiles
    for (int L = 1; L <= 64; L <<= 2){
        for (int j = tid; j < 2048; j += 256){
            float2* S = (j < 1024) ? ZA : ZB;
            int jj = j & 1023;
            int lane = jj & 15, o = jj >> 4;
            int grp = o / L, k = o - grp*L;
            int b0 = grp*4*L + k;
            float2 E0 = S[b0*17+lane],       E1 = S[(b0+L)*17+lane];
            float2 E2 = S[(b0+2*L)*17+lane], E3 = S[(b0+3*L)*17+lane];
            float2 w1 = stw[k*(256/(4*L))]; w1.y = -w1.y;        // conj (inverse)
            float2 w2 = cmul(w1,w1), w3 = cmul(w1,w2);
            float2 b1 = cmul(w1,E1), b2 = cmul(w2,E2), b3 = cmul(w3,E3);
            float2 s0 = cadd(E0,b2), s1 = csub(E0,b2);
            float2 s2 = cadd(b1,b3), s3 = csub(b1,b3);
            S[b0*17+lane]       = cadd(s0,s2);
            S[(b0+2*L)*17+lane] = csub(s0,s2);
            S[(b0+L)*17+lane]   = make_float2(s1.x - s3.y, s1.y + s3.x);  // s1 + i*s3
            S[(b0+3*L)*17+lane] = make_float2(s1.x + s3.y, s1.y - s3.x);  // s1 - i*s3
        }
        __syncthreads();
    }
    // store cropped t<128: P, Q
    float2* dP = g_bufB + (size_t)(2*bd)*VOL + (size_t)h*128 + wb;
    for (int i = tid; i < 128*16; i += 256){
        int t = i >> 4, lane = i & 15;
        dP[(size_t)t*16384 + lane]                 = ZA[t*17+lane];
        dP[(size_t)VOL + (size_t)t*16384 + lane]   = ZB[t*17+lane];
    }
}

// ---------------- inverse W-pass fused with P*Q, mag, sqrt ----------------
__global__ __launch_bounds__(256) void k_invWfinal(){
    __shared__ float2 sP[2][128], sQ[2][128];
    int team = threadIdx.x >> 7, tl = threadIdx.x & 127;
    int Lg = blockIdx.x*2 + team;
    int bd = Lg >> 13, r = Lg & 8191;
    int t = r >> 6, h = r & 63;
    size_t baseP = (size_t)(2*bd)*VOL + (size_t)t*16384 + h*128;
    int rb = brev7(tl);
    sP[team][rb] = g_bufB[baseP + tl];
    sQ[team][rb] = g_bufB[baseP + VOL + tl];
    __syncthreads();
    float2* arr = (tl < 64) ? sP[team] : sQ[team];
    int bf = tl & 63;
    #pragma unroll
    for (int len = 2; len <= 128; len <<= 1){
        int half = len >> 1;
        int grp = bf / half, pos = bf - grp*half;
        float2 w = g_tw[pos * (256/len)];
        w.y = -w.y;
        int i0 = grp*len + pos;
        float2 b = cmul(arr[i0 + half], w);
        float2 a = arr[i0];
        arr[i0]        = cadd(a, b);
        arr[i0 + half] = csub(a, b);
        __syncthreads();
    }
    if (tl < 64){
        const float s2 = 1.f/(128.f*128.f);
        float2 P = sP[team][tl], Q = sQ[team][tl];
        float Sr = (P.x*Q.x - P.y*Q.y)*s2;
        float Si = (P.x*Q.y + P.y*Q.x)*s2;
        float mag = 0.5f*(sqrtf(Sr*Sr + Si*Si) + Sr);
        mag = fmaxf(mag, 0.f);
        g_sq[(size_t)bd*NB + (size_t)t*4096 + h*64 + tl] = sqrtf(mag);
    }
}

// ---------------- final mtxi matmul along T ----------------
__global__ __launch_bounds__(256) void k_final(const float* __restrict__ mtxi, float* __restrict__ out){
    __shared__ float sx[128*64];
    int bd = blockIdx.x >> 6, h = blockIdx.x & 63;
    const float* src = g_sq + (size_t)bd*NB + h*64;
    for (int i = threadIdx.x; i < 128*64; i += 256){
        int t = i >> 6, w = i & 63;
        sx[i] = src[(size_t)t*4096 + w];
    }
    __syncthreads();
    float* dst = out + (size_t)bd*NB + h*64;
    for (int o = threadIdx.x; o < 128*64; o += 256){
        int t = o >> 6, w = o & 63;
        float acc = 0.f;
        const float* mi = mtxi + t*128;
        #pragma unroll 8
        for (int m = 0; m < 128; m++) acc = fmaf(mi[m], sx[m*64 + w], acc);
        dst[(size_t)t*4096 + w] = acc;
    }
}

// ---------------- launch ----------------
#define CONV_SMEM (32768 + 128*129*8 + 1024)
#define FT_SMEM   (3*256*17*8 + 1024)

extern "C" void kernel_launch(void* const* d_in, const int* in_sizes, int n_in,
                              void* d_out, int out_size){
    const float *feature = 0, *conv_w = 0, *conv_b = 0, *wave = 0;
    const float *invr = 0, *invi = 0, *mtx = 0, *mtxi = 0;
    int scal_seen = 0, mat_seen = 0, psf_seen = 0;
    for (int i = 0; i < n_in; i++){
        const float* p = (const float*)d_in[i];
        int s = in_sizes[i];
        if      (s == 1)       { if (scal_seen++ == 0) conv_w = p; else conv_b = p; }
        else if (s == 126)     wave = p;
        else if (s == 16384)   { if (mat_seen++ == 0) mtx = p; else mtxi = p; }
        else if (s == 4194304) { if (psf_seen++ == 0) invr = p; else invi = p; }
        else if (s == 1048576) feature = p;
    }
    float* out = (float*)d_out;

    cudaFuncSetAttribute(k_conv_fwdW, cudaFuncAttributeMaxDynamicSharedMemorySize, CONV_SMEM);
    cudaFuncSetAttribute(k_fusedT,    cudaFuncAttributeMaxDynamicSharedMemorySize, FT_SMEM);

    k_init_tw<<<1,128>>>();
    k_build_M<<<64,256>>>(mtx, wave);

    // forward: conv+mtx+W-FFT fused, then H-FFT
    k_conv_fwdW<<<128,512,CONV_SMEM>>>(feature);
    k_fwdH<<<dim3(128,4,2),256>>>();

    // attention scalars (4 reduce + 4 combine)
    k_redA<<<dim3(RBLK,2),256>>>(invr, invi);
    k_combA<<<2,256>>>(conv_w, conv_b);
    k_redB<<<dim3(RBLK,2),256>>>(invr, invi);
    k_combB<<<2,256>>>();
    k_redC<<<dim3(RBLK,2),256>>>(invr, invi);
    k_combC<<<2,256>>>(conv_w, conv_b);
    k_redD<<<dim3(RBLK,2),256>>>(invr, invi);
    k_combD<<<2,256>>>();

    // fused: fwd T-FFT + spectral multiply (G1, G2) + inverse T-FFT (crop t<128)
    k_fusedT<<<dim3(8,128,2),256,FT_SMEM>>>(invr, invi);

    // inverse H (crop h<64), then inverse W fused with P*Q/mag/sqrt
    k_invH<<<dim3(128,4,4),256>>>();
    k_invWfinal<<<8192,256>>>();

    k_final<<<128,256>>>(mtxi, out);
}

// round 10
// speedup vs baseline: 1.2998x; 1.0742x over previous
#include <cuda_runtime.h>
#include <math.h>

#define VOL (256*128*128)     /* 4194304 full padded volume */
#define NB  (128*64*64)       /* 524288  crop / attention block */
#define RBLK 512

// ---------------- scratch (static device allocations, no runtime alloc) ----------------
static __device__ float2 g_bufA[2*(size_t)VOL];   // Z spectra per bd (t<128 used)
static __device__ float2 g_bufB[4*(size_t)VOL];   // P,R per bd (t<128 used)
static __device__ float2 g_zc[2*(size_t)NB];      // conv+mtx packed complex (cos + i sin)
static __device__ float  g_sq[2*(size_t)NB];      // sqrt(mag) crop
static __device__ float  g_Mc[128*128];
static __device__ float  g_Ms[128*128];
static __device__ float2 g_tw[128];               // W_256^k, k<128 (forward sign)

// attention reduction state
static __device__ double g_pD[2][RBLK];
static __device__ float  g_pMnL[2][RBLK], g_pMxL[2][RBLK], g_pMnH[2][RBLK], g_pMxH[2][RBLK];
static __device__ float  g_a1[2], g_c1[2], g_M1f[2], g_Z1i[2];
static __device__ float  g_a2[2], g_c2[2], g_M2f[2], g_Z2i[2];
static __device__ float  g_mnH[2], g_mxH[2];

__device__ __forceinline__ float2 cmul(float2 a, float2 b){
    return make_float2(a.x*b.x - a.y*b.y, a.x*b.y + a.y*b.x);
}
__device__ __forceinline__ float2 cadd(float2 a, float2 b){ return make_float2(a.x+b.x, a.y+b.y); }
__device__ __forceinline__ float2 csub(float2 a, float2 b){ return make_float2(a.x-b.x, a.y-b.y); }
__device__ __forceinline__ int brev7(int i){ return (int)(__brev((unsigned)i) >> 25); }
__device__ __forceinline__ int dr4(int x){   // base-4 digit reversal of 8-bit value
    return ((x&3)<<6) | ((x&12)<<2) | ((x&48)>>2) | ((x&192)>>6);
}

// ---------------- init ----------------
__global__ void k_init_tw(){
    int i = threadIdx.x;
    if (i < 128){
        double a = -2.0*3.14159265358979323846*(double)i/256.0;
        double s, c; sincos(a, &s, &c);
        g_tw[i] = make_float2((float)c, (float)s);
    }
}

// Mc[t][j] = sum_m mtx[t][m] * waveC[j-m+31] (k=63 taps), same for Ms
__global__ void k_build_M(const float* __restrict__ mtx, const float* __restrict__ wave){
    int idx = blockIdx.x*blockDim.x + threadIdx.x;
    if (idx >= 128*128) return;
    int t = idx >> 7, j = idx & 127;
    float ac = 0.f, as = 0.f;
    for (int m = 0; m < 128; m++){
        int tau = j - m + 31;
        if (tau >= 0 && tau < 63){
            float mv = mtx[t*128 + m];
            ac = fmaf(mv, wave[tau],      ac);
            as = fmaf(mv, wave[63 + tau], as);
        }
    }
    g_Mc[idx] = ac; g_Ms[idx] = as;
}

// ---------------- conv+mtx -> packed complex ----------------
__global__ __launch_bounds__(512) void k_conv(const float* __restrict__ feat){
    __shared__ float sx[128*64];
    int bd = blockIdx.x >> 6, h = blockIdx.x & 63;
    const float* src = feat + (size_t)bd*NB + h*64;
    for (int i = threadIdx.x; i < 128*64; i += 512){
        int t = i >> 6, w = i & 63;
        sx[i] = src[(size_t)t*4096 + w];
    }
    __syncthreads();
    float2* dst = g_zc + (size_t)bd*NB + h*64;
    for (int o = threadIdx.x; o < 128*64; o += 512){
        int t = o >> 6, w = o & 63;
        float ac = 0.f, as = 0.f;
        const float* mc = g_Mc + t*128;
        const float* ms = g_Ms + t*128;
        #pragma unroll 8
        for (int m = 0; m < 128; m++){
            float xv = sx[m*64 + w];
            ac = fmaf(mc[m], xv, ac);
            as = fmaf(ms[m], xv, as);
        }
        dst[(size_t)t*4096 + w] = make_float2(ac, as);
    }
}

// ---------------- forward 2D (H,W) FFT per t-slice, zero-padded 64x64 -> 128x128 --------
__global__ __launch_bounds__(512) void k_fwd2D(){
    extern __shared__ unsigned char smraw[];
    float2* s   = (float2*)smraw;              // [h*129 + w]
    float2* stw = s + 128*129;
    int tid = threadIdx.x;
    int t = blockIdx.x, bd = blockIdx.y;
    if (tid < 128) stw[tid] = g_tw[tid];
    for (int i = tid; i < 128*129; i += 512) s[i] = make_float2(0.f, 0.f);
    __syncthreads();
    const float2* src = g_zc + (size_t)bd*NB + (size_t)t*4096;
    for (int i = tid; i < 64*64; i += 512){
        int h = i >> 6, w = i & 63;
        s[brev7(h)*129 + brev7(w)] = src[i];    // even rows / even cols
    }
    __syncthreads();
    // W-axis DIT on the 64 even rows. radix-2 stage: odd w slots are zero -> copy
    for (int j = tid; j < 64*64; j += 512){
        int row = (j >> 6) << 1, g = j & 63;
        int i0 = row*129 + 2*g;
        s[i0 + 1] = s[i0];
    }
    __syncthreads();
    for (int L = 2; L <= 32; L <<= 2){
        for (int j = tid; j < 64*32; j += 512){
            int row = (j >> 5) << 1, o = j & 31;
            int grp = o / L, k = o - grp*L;
            int b0 = row*129 + grp*4*L + k;
            float2 A = s[b0], B = s[b0+L], C = s[b0+2*L], D = s[b0+3*L];
            float2 w1 = stw[k*(256/(2*L))];
            float2 w2 = stw[k*(256/(4*L))];
            float2 Bt = cmul(w1,B), Dt = cmul(w1,D);
            float2 A1 = cadd(A,Bt), B1 = csub(A,Bt);
            float2 C1 = cadd(C,Dt), D1 = csub(C,Dt);
            float2 C2 = cmul(w2,C1), D2 = cmul(w2,D1);
            float2 D2m = make_float2(D2.y, -D2.x);
            s[b0]     = cadd(A1,C2);
            s[b0+2*L] = csub(A1,C2);
            s[b0+L]   = cadd(B1,D2m);
            s[b0+3*L] = csub(B1,D2m);
        }
        __syncthreads();
    }
    // H-axis DIT on all 128 columns. radix-2 stage: odd rows are zero -> copy
    for (int j = tid; j < 64*128; j += 512){
        int w = j & 127, g = j >> 7;
        int i0 = (2*g)*129 + w;
        s[i0 + 129] = s[i0];
    }
    __syncthreads();
    for (int L = 2; L <= 32; L <<= 2){
        for (int j = tid; j < 32*128; j += 512){
            int w = j & 127, o = j >> 7;
            int grp = o / L, k = o - grp*L;
            int r0 = grp*4*L + k;
            float2 A = s[r0*129+w],       B = s[(r0+L)*129+w];
            float2 C = s[(r0+2*L)*129+w], D = s[(r0+3*L)*129+w];
            float2 w1 = stw[k*(256/(2*L))];
            float2 w2 = stw[k*(256/(4*L))];
            float2 Bt = cmul(w1,B), Dt = cmul(w1,D);
            float2 A1 = cadd(A,Bt), B1 = csub(A,Bt);
            float2 C1 = cadd(C,Dt), D1 = csub(C,Dt);
            float2 C2 = cmul(w2,C1), D2 = cmul(w2,D1);
            float2 D2m = make_float2(D2.y, -D2.x);
            s[r0*129+w]       = cadd(A1,C2);
            s[(r0+2*L)*129+w] = csub(A1,C2);
            s[(r0+L)*129+w]   = cadd(B1,D2m);
            s[(r0+3*L)*129+w] = csub(B1,D2m);
        }
        __syncthreads();
    }
    float2* dst = g_bufA + (size_t)bd*VOL + (size_t)t*16384;
    for (int i = tid; i < 128*128; i += 512)
        dst[i] = s[(i >> 7)*129 + (i & 127)];
}

// ---------------- attention scalar reductions ----------------
__device__ double blockReduceD(double v){
    __shared__ double sh[256];
    sh[threadIdx.x] = v; __syncthreads();
    for (int s = 128; s; s >>= 1){ if (threadIdx.x < s) sh[threadIdx.x] += sh[threadIdx.x + s]; __syncthreads(); }
    double r = sh[0]; __syncthreads(); return r;
}
__device__ float blockReduceMin(float v){
    __shared__ float sh[256];
    sh[threadIdx.x] = v; __syncthreads();
    for (int s = 128; s; s >>= 1){ if (threadIdx.x < s) sh[threadIdx.x] = fminf(sh[threadIdx.x], sh[threadIdx.x + s]); __syncthreads(); }
    float r = sh[0]; __syncthreads(); return r;
}
__device__ float blockReduceMax(float v){
    __shared__ float sh[256];
    sh[threadIdx.x] = v; __syncthreads();
    for (int s = 128; s; s >>= 1){ if (threadIdx.x < s) sh[threadIdx.x] = fmaxf(sh[threadIdx.x], sh[threadIdx.x + s]); __syncthreads(); }
    float r = sh[0]; __syncthreads(); return r;
}

__device__ __forceinline__ void block_elems(const float* K, int j, float& kL, float& kH, float& vL){
    int tl = j >> 12, hl = (j >> 6) & 63, wl = j & 63;
    float pe = sinf((float)tl);
    vL = K[((192 + tl) & 255)*16384 + ((96 + hl) & 127)*128 + ((96 + wl) & 127)];
    float vH = K[(64 + tl)*16384 + (32 + hl)*128 + (32 + wl)];
    kL = vL + pe; kH = vH + pe;
}

__global__ __launch_bounds__(256) void k_redA(const float* __restrict__ invr, const float* __restrict__ invi){
    int f = blockIdx.y;
    const float* K = f ? invi : invr;
    double sum = 0.0;
    float mnL = 3.4e38f, mxL = -3.4e38f, mnH = 3.4e38f, mxH = -3.4e38f;
    for (int j = blockIdx.x*256 + threadIdx.x; j < NB; j += RBLK*256){
        float kL, kH, vL; block_elems(K, j, kL, kH, vL);
        sum += (double)vL;
        mnL = fminf(mnL, kL); mxL = fmaxf(mxL, kL);
        mnH = fminf(mnH, kH); mxH = fmaxf(mxH, kH);
    }
    sum = blockReduceD(sum);
    mnL = blockReduceMin(mnL); mxL = blockReduceMax(mxL);
    mnH = blockReduceMin(mnH); mxH = blockReduceMax(mxH);
    if (threadIdx.x == 0){
        g_pD[f][blockIdx.x] = sum;
        g_pMnL[f][blockIdx.x] = mnL; g_pMxL[f][blockIdx.x] = mxL;
        g_pMnH[f][blockIdx.x] = mnH; g_pMxH[f][blockIdx.x] = mxH;
    }
}

__global__ void k_combA(const float* __restrict__ wp, const float* __restrict__ bp){
    int f = blockIdx.x, i = threadIdx.x;
    __shared__ double sd[256]; __shared__ float s1[256], s2[256], s3[256], s4[256];
    sd[i] = g_pD[f][i] + g_pD[f][i+256];
    s1[i] = fminf(g_pMnL[f][i], g_pMnL[f][i+256]);
    s2[i] = fmaxf(g_pMxL[f][i], g_pMxL[f][i+256]);
    s3[i] = fminf(g_pMnH[f][i], g_pMnH[f][i+256]);
    s4[i] = fmaxf(g_pMxH[f][i], g_pMxH[f][i+256]);
    __syncthreads();
    for (int s = 128; s; s >>= 1){
        if (i < s){
            sd[i] += sd[i+s];
            s1[i] = fminf(s1[i], s1[i+s]); s2[i] = fmaxf(s2[i], s2[i+s]);
            s3[i] = fminf(s3[i], s3[i+s]); s4[i] = fmaxf(s4[i], s4[i+s]);
        }
        __syncthreads();
    }
    if (i == 0){
        float W = *wp, B = *bp;
        float scal1 = W*(float)(sd[0]/(double)NB) + B;
        float a1 = scal1*W, c1 = scal1*B;
        g_a1[f] = a1; g_c1[f] = c1;
        g_M1f[f] = (a1 >= 0.f ? a1*s2[0] : a1*s1[0]) + c1;
        g_mnH[f] = s3[0]; g_mxH[f] = s4[0];
    }
}

__global__ __launch_bounds__(256) void k_redB(const float* __restrict__ invr, const float* __restrict__ invi){
    int f = blockIdx.y; const float* K = f ? invi : invr;
    float a1 = g_a1[f], c1 = g_c1[f], M1 = g_M1f[f];
    double acc = 0.0;
    for (int j = blockIdx.x*256 + threadIdx.x; j < NB; j += RBLK*256){
        float kL, kH, vL; block_elems(K, j, kL, kH, vL);
        acc += (double)expf(fmaf(a1, kL, c1) - M1);
    }
    acc = blockReduceD(acc);
    if (threadIdx.x == 0) g_pD[f][blockIdx.x] = acc;
}
__global__ void k_combB(){
    int f = blockIdx.x, i = threadIdx.x;
    __shared__ double sd[256];
    sd[i] = g_pD[f][i] + g_pD[f][i+256]; __syncthreads();
    for (int s = 128; s; s >>= 1){ if (i < s) sd[i] += sd[i+s]; __syncthreads(); }
    if (i == 0) g_Z1i[f] = (float)(1.0/sd[0]);
}

__global__ __launch_bounds__(256) void k_redC(const float* __restrict__ invr, const float* __restrict__ invi){
    int f = blockIdx.y; const float* K = f ? invi : invr;
    float a1 = g_a1[f], c1 = g_c1[f], M1 = g_M1f[f], Z1i = g_Z1i[f];
    double acc = 0.0;
    for (int j = blockIdx.x*256 + threadIdx.x; j < NB; j += RBLK*256){
        float kL, kH, vL; block_elems(K, j, kL, kH, vL);
        float sm = expf(fmaf(a1, kL, c1) - M1) * Z1i;
        acc += (double)(kL / (1.f + expf(-sm)));
    }
    acc = blockReduceD(acc);
    if (threadIdx.x == 0) g_pD[f][blockIdx.x] = acc;
}
__global__ void k_combC(const float* __restrict__ wp, const float* __restrict__ bp){
    int f = blockIdx.x, i = threadIdx.x;
    __shared__ double sd[256];
    sd[i] = g_pD[f][i] + g_pD[f][i+256]; __syncthreads();
    for (int s = 128; s; s >>= 1){ if (i < s) sd[i] += sd[i+s]; __syncthreads(); }
    if (i == 0){
        float W = *wp, B = *bp;
        float scal2 = W*(float)(sd[0]/(double)NB) + B;
        float a2 = scal2*W, c2 = scal2*B;
        g_a2[f] = a2; g_c2[f] = c2;
        g_M2f[f] = (a2 >= 0.f ? a2*g_mxH[f] : a2*g_mnH[f]) + c2;
    }
}

__global__ __launch_bounds__(256) void k_redD(const float* __restrict__ invr, const float* __restrict__ invi){
    int f = blockIdx.y; const float* K = f ? invi : invr;
    float a2 = g_a2[f], c2 = g_c2[f], M2 = g_M2f[f];
    double acc = 0.0;
    for (int j = blockIdx.x*256 + threadIdx.x; j < NB; j += RBLK*256){
        float kL, kH, vL; block_elems(K, j, kL, kH, vL);
        acc += (double)expf(fmaf(a2, kH, c2) - M2);
    }
    acc = blockReduceD(acc);
    if (threadIdx.x == 0) g_pD[f][blockIdx.x] = acc;
}
__global__ void k_combD(){
    int f = blockIdx.x, i = threadIdx.x;
    __shared__ double sd[256];
    sd[i] = g_pD[f][i] + g_pD[f][i+256]; __syncthreads();
    for (int s = 128; s; s >>= 1){ if (i < s) sd[i] += sd[i+s]; __syncthreads(); }
    if (i == 0) g_Z2i[f] = (float)(1.0/sd[0]);
}

// ---------------- attention filter (pointwise) ----------------
__device__ __forceinline__ float atten_filter(float v, int t, int h, int w, int f){
    int tl = t - 64, hl = h - 32, wl = w - 32;
    if ((unsigned)tl < 128u && (unsigned)hl < 64u && (unsigned)wl < 64u){
        float k2p = v + sinf((float)tl);
        float sm = expf(fmaf(g_a2[f], k2p, g_c2[f]) - g_M2f[f]) * g_Z2i[f];
        return k2p / (1.f + expf(-sm));
    }
    int tl2 = (t + 64) & 255, hl2 = (h + 32) & 127, wl2 = (w + 32) & 127;
    if (tl2 < 128 && hl2 < 64 && wl2 < 64){
        float k2p = v + sinf((float)tl2);
        float sm = expf(fmaf(g_a1[f], k2p, g_c1[f]) - g_M1f[f]) * g_Z1i[f];
        return k2p / (1.f + expf(-sm));
    }
    return v;
}

// ---------------- fused T: 1 fwd DIF-FFT + pointwise G1/G2' + 2 inv DIT-FFT ----------------
// G1 = W(k)Z(k) -> P ; G2' = conj(W(-k))Z(k) -> R, with Q = conj(R) applied at combine.
__global__ __launch_bounds__(256) void k_fusedT(const float* __restrict__ invr, const float* __restrict__ invi){
    extern __shared__ unsigned char smraw[];
    float2* ZA  = (float2*)smraw;
    float2* ZB  = ZA + 256*17;
    float2* stw = ZB + 256*17;
    int tid = threadIdx.x;
    int wb = blockIdx.x << 4, h = blockIdx.y, bd = blockIdx.z;
    if (tid < 128) stw[tid] = g_tw[tid];
    const float2* ZS = g_bufA + (size_t)bd*VOL + (size_t)h*128 + wb;
    for (int i = tid; i < 128*16; i += 256){
        int t = i >> 4, lane = i & 15;
        ZA[t*17+lane]       = ZS[(size_t)t*16384 + lane];
        ZA[(t+128)*17+lane] = make_float2(0.f, 0.f);
    }
    __syncthreads();
    // forward radix-4 DIF (natural -> dr4), single tile
    for (int M = 256; M >= 4; M >>= 2){
        int q = M >> 2;
        for (int j = tid; j < 1024; j += 256){
            int lane = j & 15, o = j >> 4;
            int blk = o / q, k = o - blk*q;
            int b0 = blk*M + k;
            float2 A = ZA[b0*17+lane],       B = ZA[(b0+q)*17+lane];
            float2 C = ZA[(b0+2*q)*17+lane], D = ZA[(b0+3*q)*17+lane];
            float2 t0 = cadd(A,C), t1 = csub(A,C), t2 = cadd(B,D), t3 = csub(B,D);
            float2 w1 = stw[k*(256/M)];
            float2 w2 = cmul(w1,w1);
            float2 w3 = cmul(w1,w2);
            ZA[b0*17+lane] = cadd(t0,t2);
            float2 u1 = make_float2(t1.x + t3.y, t1.y - t3.x);   // t1 - i*t3
            ZA[(b0+q)*17+lane]   = cmul(u1, w1);
            ZA[(b0+2*q)*17+lane] = cmul(csub(t0,t2), w2);
            float2 u3 = make_float2(t1.x - t3.y, t1.y + t3.x);   // t1 + i*t3
            ZA[(b0+3*q)*17+lane] = cmul(u3, w3);
        }
        __syncthreads();
    }
    // pointwise: ZB = conj(W(-k)) * Z, ZA = W(k) * Z    (W read + filtered on the fly)
    const float sc = 1.f/256.f;
    int hn = (128 - h) & 127;
    for (int i = tid; i < 256*16; i += 256){
        int t = i >> 4, lane = i & 15, w = wb + lane;
        int p = dr4(t);
        size_t gi  = (size_t)t*16384 + (size_t)h*128 + w;
        int tn = (256 - t) & 255, wn = (128 - w) & 127;
        size_t gir = (size_t)tn*16384 + (size_t)hn*128 + wn;
        float w1 = atten_filter(invr[gi],  t,  h,  w,  0)*sc;
        float w2 = atten_filter(invi[gi],  t,  h,  w,  1)*sc;
        float v1 = atten_filter(invr[gir], tn, hn, wn, 0)*sc;
        float v2 = atten_filter(invi[gir], tn, hn, wn, 1)*sc;
        float2 z = ZA[p*17+lane];
        ZB[p*17+lane] = cmul(make_float2(v1, -v2), z);
        ZA[p*17+lane] = cmul(make_float2(w1,  w2), z);
    }
    __syncthreads();
    // inverse radix-4 DIT (dr4 -> natural), both tiles
    for (int L = 1; L <= 64; L <<= 2){
        for (int j = tid; j < 2048; j += 256){
            float2* S = (j < 1024) ? ZA : ZB;
            int jj = j & 1023;
            int lane = jj & 15, o = jj >> 4;
            int grp = o / L, k = o - grp*L;
            int b0 = grp*4*L + k;
            float2 E0 = S[b0*17+lane],       E1 = S[(b0+L)*17+lane];
            float2 E2 = S[(b0+2*L)*17+lane], E3 = S[(b0+3*L)*17+lane];
            float2 w1 = stw[k*(256/(4*L))]; w1.y = -w1.y;
            float2 w2 = cmul(w1,w1), w3 = cmul(w1,w2);
            float2 b1 = cmul(w1,E1), b2 = cmul(w2,E2), b3 = cmul(w3,E3);
            float2 s0 = cadd(E0,b2), s1 = csub(E0,b2);
            float2 s2 = cadd(b1,b3), s3 = csub(b1,b3);
            S[b0*17+lane]       = cadd(s0,s2);
            S[(b0+2*L)*17+lane] = csub(s0,s2);
            S[(b0+L)*17+lane]   = make_float2(s1.x - s3.y, s1.y + s3.x);
            S[(b0+3*L)*17+lane] = make_float2(s1.x + s3.y, s1.y - s3.x);
        }
        __syncthreads();
    }
    float2* dP = g_bufB + (size_t)(2*bd)*VOL + (size_t)h*128 + wb;
    for (int i = tid; i < 128*16; i += 256){
        int t = i >> 4, lane = i & 15;
        dP[(size_t)t*16384 + lane]               = ZA[t*17+lane];
        dP[(size_t)VOL + (size_t)t*16384 + lane] = ZB[t*17+lane];
    }
}

// ---------------- inverse 2D (H,W) per t-slice, crop, fused P*conj(R)/mag/sqrt ----------
__global__ __launch_bounds__(512) void k_inv2D(){
    extern __shared__ unsigned char smraw[];
    float2* s   = (float2*)smraw;              // 128*129
    float2* qd  = s + 128*129;                 // 64*65 (P quadrant stash)
    float2* stw = qd + 64*65;
    int tid = threadIdx.x;
    int t = blockIdx.x, bd = blockIdx.y;
    if (tid < 128){ float2 w = g_tw[tid]; stw[tid] = make_float2(w.x, -w.y); }  // conj
    for (int pass = 0; pass < 2; pass++){
        const float2* src = g_bufB + (size_t)(2*bd + pass)*VOL + (size_t)t*16384;
        __syncthreads();
        for (int i = tid; i < 128*128; i += 512){
            int h = i >> 7, w = i & 127;
            s[brev7(h)*129 + w] = src[i];
        }
        __syncthreads();
        // H-axis inverse DIT (bit-reversed input): radix-2 then fused radix-4
        for (int j = tid; j < 64*128; j += 512){
            int w = j & 127, g = j >> 7;
            int i0 = (2*g)*129 + w, i1 = i0 + 129;
            float2 a = s[i0], b = s[i1];
            s[i0] = cadd(a,b); s[i1] = csub(a,b);
        }
        __syncthreads();
        for (int L = 2; L <= 32; L <<= 2){
            for (int j = tid; j < 32*128; j += 512){
                int w = j & 127, o = j >> 7;
                int grp = o / L, k = o - grp*L;
                int r0 = grp*4*L + k;
                float2 A = s[r0*129+w],       B = s[(r0+L)*129+w];
                float2 C = s[(r0+2*L)*129+w], D = s[(r0+3*L)*129+w];
                float2 w1 = stw[k*(256/(2*L))];
                float2 w2 = stw[k*(256/(4*L))];
                float2 Bt = cmul(w1,B), Dt = cmul(w1,D);
                float2 A1 = cadd(A,Bt), B1 = csub(A,Bt);
                float2 C1 = cadd(C,Dt), D1 = csub(C,Dt);
                float2 C2 = cmul(w2,C1), D2 = cmul(w2,D1);
                float2 D2m = make_float2(-D2.y, D2.x);
                s[r0*129+w]       = cadd(A1,C2);
                s[(r0+2*L)*129+w] = csub(A1,C2);
                s[(r0+L)*129+w]   = cadd(B1,D2m);
                s[(r0+3*L)*129+w] = csub(B1,D2m);
            }
            __syncthreads();
        }
        // W-axis inverse DIF (natural -> bit-reversed) on rows h<64 only
        for (int M = 128; M >= 8; M >>= 2){
            int q = M >> 2;
            for (int j = tid; j < 64*32; j += 512){
                int row = j >> 5, o = j & 31;
                int grp = o / q, k = o - grp*q;
                int b0 = row*129 + grp*M + k;
                float2 A = s[b0], B = s[b0+q], C = s[b0+2*q], D = s[b0+3*q];
                float2 wA = stw[k*(256/M)];
                float2 w2 = stw[(2*k)*(256/M)];
                float2 sAC = cadd(A,C), dAC = csub(A,C);
                float2 sBD = cadd(B,D), dBD = csub(B,D);
                s[b0]   = cadd(sAC, sBD);
                s[b0+q] = cmul(csub(sAC, sBD), w2);
                float2 u2 = make_float2(dAC.x - dBD.y, dAC.y + dBD.x);  // dAC + i*dBD
                s[b0+2*q] = cmul(u2, wA);
                float2 u3 = make_float2(dAC.x + dBD.y, dAC.y - dBD.x); // dAC - i*dBD
                s[b0+3*q] = cmul(u3, cmul(wA, w2));
            }
            __syncthreads();
        }
        for (int j = tid; j < 64*64; j += 512){
            int row = j >> 6, g = j & 63;
            int i0 = row*129 + 2*g;
            float2 a = s[i0], b = s[i0+1];
            s[i0] = cadd(a,b); s[i0+1] = csub(a,b);
        }
        __syncthreads();
        if (pass == 0){
            for (int i = tid; i < 64*64; i += 512){
                int h = i >> 6, w = i & 63;
                qd[h*65 + w] = s[h*129 + brev7(w)];
            }
        } else {
            const float S2 = 1.f/268435456.f;   // (1/16384)^2
            float* dst = g_sq + (size_t)bd*NB + (size_t)t*4096;
            for (int i = tid; i < 64*64; i += 512){
                int h = i >> 6, w = i & 63;
                float2 P = qd[h*65 + w];
                float2 R = s[h*129 + brev7(w)];
                float Sr = (P.x*R.x + P.y*R.y)*S2;     // P * conj(R)
                float Si = (P.y*R.x - P.x*R.y)*S2;
                float mag = fmaxf(0.5f*(sqrtf(Sr*Sr + Si*Si) + Sr), 0.f);
                dst[i] = sqrtf(mag);
            }
        }
    }
}

// ---------------- final mtxi matmul along T ----------------
__global__ __launch_bounds__(256) void k_final(const float* __restrict__ mtxi, float* __restrict__ out){
    __shared__ float sx[128*64];
    int bd = blockIdx.x >> 6, h = blockIdx.x & 63;
    const float* src = g_sq + (size_t)bd*NB + h*64;
    for (int i = threadIdx.x; i < 128*64; i += 256){
        int t = i >> 6, w = i & 63;
        sx[i] = src[(size_t)t*4096 + w];
    }
    __syncthreads();
    float* dst = out + (size_t)bd*NB + h*64;
    for (int o = threadIdx.x; o < 128*64; o += 256){
        int t = o >> 6, w = o & 63;
        float acc = 0.f;
        const float* mi = mtxi + t*128;
        #pragma unroll 8
        for (int m = 0; m < 128; m++) acc = fmaf(mi[m], sx[m*64 + w], acc);
        dst[(size_t)t*4096 + w] = acc;
    }
}

// ---------------- launch ----------------
#define FWD2D_SMEM (128*129*8 + 128*8)
#define INV2D_SMEM (128*129*8 + 64*65*8 + 128*8)
#define FT_SMEM    (2*256*17*8 + 128*8)

extern "C" void kernel_launch(void* const* d_in, const int* in_sizes, int n_in,
                              void* d_out, int out_size){
    const float *feature = 0, *conv_w = 0, *conv_b = 0, *wave = 0;
    const float *invr = 0, *invi = 0, *mtx = 0, *mtxi = 0;
    int scal_seen = 0, mat_seen = 0, psf_seen = 0;
    for (int i = 0; i < n_in; i++){
        const float* p = (const float*)d_in[i];
        int s = in_sizes[i];
        if      (s == 1)       { if (scal_seen++ == 0) conv_w = p; else conv_b = p; }
        else if (s == 126)     wave = p;
        else if (s == 16384)   { if (mat_seen++ == 0) mtx = p; else mtxi = p; }
        else if (s == 4194304) { if (psf_seen++ == 0) invr = p; else invi = p; }
        else if (s == 1048576) feature = p;
    }
    float* out = (float*)d_out;

    cudaFuncSetAttribute(k_fwd2D,  cudaFuncAttributeMaxDynamicSharedMemorySize, FWD2D_SMEM);
    cudaFuncSetAttribute(k_inv2D,  cudaFuncAttributeMaxDynamicSharedMemorySize, INV2D_SMEM);
    cudaFuncSetAttribute(k_fusedT, cudaFuncAttributeMaxDynamicSharedMemorySize, FT_SMEM);

    k_init_tw<<<1,128>>>();
    k_build_M<<<64,256>>>(mtx, wave);

    // forward path
    k_conv<<<128,512>>>(feature);
    k_fwd2D<<<dim3(128,2),512,FWD2D_SMEM>>>();

    // attention scalars (4 reduce + 4 combine)
    k_redA<<<dim3(RBLK,2),256>>>(invr, invi);
    k_combA<<<2,256>>>(conv_w, conv_b);
    k_redB<<<dim3(RBLK,2),256>>>(invr, invi);
    k_combB<<<2,256>>>();
    k_redC<<<dim3(RBLK,2),256>>>(invr, invi);
    k_combC<<<2,256>>>(conv_w, conv_b);
    k_redD<<<dim3(RBLK,2),256>>>(invr, invi);
    k_combD<<<2,256>>>();

    // fused: fwd T-FFT + pointwise G1/G2' + two inverse T-FFTs (crop t<128)
    k_fusedT<<<dim3(8,128,2),256,FT_SMEM>>>(invr, invi);

    // inverse 2D per slice with fused P*conj(R), mag, relu, sqrt
    k_inv2D<<<dim3(128,2),512,INV2D_SMEM>>>();

    k_final<<<128,256>>>(mtxi, out);
}

// round 11
// speedup vs baseline: 1.5928x; 1.2254x over previous
#include <cuda_runtime.h>
#include <math.h>

#define VOL (256*128*128)     /* 4194304 full padded volume */
#define NB  (128*64*64)       /* 524288  crop / attention block */
#define RBLK 512

// ---------------- scratch (static device allocations, no runtime alloc) ----------------
static __device__ float2 g_bufA[2*(size_t)VOL];   // Z spectra per bd (t<128 used)
static __device__ float2 g_bufB[4*(size_t)VOL];   // P,R per bd (t<128 used)
static __device__ float2 g_zc[2*(size_t)NB];      // conv+mtx packed complex (cos + i sin)
static __device__ float  g_sq[2*(size_t)NB];      // sqrt(mag) crop
static __device__ float4 g_Wf[(size_t)VOL];       // (W(k).re, W(k).im, W(-k).re, W(-k).im)/256
static __device__ float  g_Mc[128*128];
static __device__ float  g_Ms[128*128];
static __device__ float2 g_tw[128];               // W_256^k, k<128 (forward sign)

// attention reduction state
static __device__ double g_pD[2][RBLK];
static __device__ float  g_pMnL[2][RBLK], g_pMxL[2][RBLK], g_pMnH[2][RBLK], g_pMxH[2][RBLK];
static __device__ float  g_a1[2], g_c1[2], g_M1f[2], g_Z1i[2];
static __device__ float  g_a2[2], g_c2[2], g_M2f[2], g_Z2i[2];
static __device__ float  g_mnH[2], g_mxH[2];

__device__ __forceinline__ float2 cmul(float2 a, float2 b){
    return make_float2(a.x*b.x - a.y*b.y, a.x*b.y + a.y*b.x);
}
__device__ __forceinline__ float2 cadd(float2 a, float2 b){ return make_float2(a.x+b.x, a.y+b.y); }
__device__ __forceinline__ float2 csub(float2 a, float2 b){ return make_float2(a.x-b.x, a.y-b.y); }
__device__ __forceinline__ int brev7(int i){ return (int)(__brev((unsigned)i) >> 25); }
__device__ __forceinline__ int dr4(int x){   // base-4 digit reversal of 8-bit value
    return ((x&3)<<6) | ((x&12)<<2) | ((x&48)>>2) | ((x&192)>>6);
}

// ---------------- init ----------------
__global__ void k_init_tw(){
    int i = threadIdx.x;
    if (i < 128){
        double a = -2.0*3.14159265358979323846*(double)i/256.0;
        double s, c; sincos(a, &s, &c);
        g_tw[i] = make_float2((float)c, (float)s);
    }
}

// Mc[t][j] = sum_m mtx[t][m] * waveC[j-m+31] (k=63 taps), same for Ms
__global__ void k_build_M(const float* __restrict__ mtx, const float* __restrict__ wave){
    int idx = blockIdx.x*blockDim.x + threadIdx.x;
    if (idx >= 128*128) return;
    int t = idx >> 7, j = idx & 127;
    float ac = 0.f, as = 0.f;
    for (int m = 0; m < 128; m++){
        int tau = j - m + 31;
        if (tau >= 0 && tau < 63){
            float mv = mtx[t*128 + m];
            ac = fmaf(mv, wave[tau],      ac);
            as = fmaf(mv, wave[63 + tau], as);
        }
    }
    g_Mc[idx] = ac; g_Ms[idx] = as;
}

// ---------------- conv+mtx -> packed complex ----------------
__global__ __launch_bounds__(1024) void k_conv(const float* __restrict__ feat){
    __shared__ float sx[128*64];
    int bd = blockIdx.x >> 6, h = blockIdx.x & 63;
    const float* src = feat + (size_t)bd*NB + h*64;
    for (int i = threadIdx.x; i < 128*64; i += 1024){
        int t = i >> 6, w = i & 63;
        sx[i] = src[(size_t)t*4096 + w];
    }
    __syncthreads();
    float2* dst = g_zc + (size_t)bd*NB + h*64;
    for (int o = threadIdx.x; o < 128*64; o += 1024){
        int t = o >> 6, w = o & 63;
        float ac = 0.f, as = 0.f;
        const float* mc = g_Mc + t*128;
        const float* ms = g_Ms + t*128;
        #pragma unroll 8
        for (int m = 0; m < 128; m++){
            float xv = sx[m*64 + w];
            ac = fmaf(mc[m], xv, ac);
            as = fmaf(ms[m], xv, as);
        }
        dst[(size_t)t*4096 + w] = make_float2(ac, as);
    }
}

// ---------------- forward 2D (H,W) FFT per t-slice, zero-padded 64x64 -> 128x128 --------
__global__ __launch_bounds__(1024) void k_fwd2D(){
    extern __shared__ unsigned char smraw[];
    float2* s   = (float2*)smraw;              // [h*129 + w]
    float2* stw = s + 128*129;
    int tid = threadIdx.x;
    int t = blockIdx.x, bd = blockIdx.y;
    if (tid < 128) stw[tid] = g_tw[tid];
    for (int i = tid; i < 128*129; i += 1024) s[i] = make_float2(0.f, 0.f);
    __syncthreads();
    const float2* src = g_zc + (size_t)bd*NB + (size_t)t*4096;
    for (int i = tid; i < 64*64; i += 1024){
        int h = i >> 6, w = i & 63;
        s[brev7(h)*129 + brev7(w)] = src[i];    // even rows / even cols
    }
    __syncthreads();
    // W-axis DIT on the 64 even rows. radix-2 stage: odd w slots are zero -> copy
    for (int j = tid; j < 64*64; j += 1024){
        int row = (j >> 6) << 1, g = j & 63;
        int i0 = row*129 + 2*g;
        s[i0 + 1] = s[i0];
    }
    __syncthreads();
    for (int L = 2; L <= 32; L <<= 2){
        for (int j = tid; j < 64*32; j += 1024){
            int row = (j >> 5) << 1, o = j & 31;
            int grp = o / L, k = o - grp*L;
            int b0 = row*129 + grp*4*L + k;
            float2 A = s[b0], B = s[b0+L], C = s[b0+2*L], D = s[b0+3*L];
            float2 w1 = stw[k*(256/(2*L))];
            float2 w2 = stw[k*(256/(4*L))];
            float2 Bt = cmul(w1,B), Dt = cmul(w1,D);
            float2 A1 = cadd(A,Bt), B1 = csub(A,Bt);
            float2 C1 = cadd(C,Dt), D1 = csub(C,Dt);
            float2 C2 = cmul(w2,C1), D2 = cmul(w2,D1);
            float2 D2m = make_float2(D2.y, -D2.x);
            s[b0]     = cadd(A1,C2);
            s[b0+2*L] = csub(A1,C2);
            s[b0+L]   = cadd(B1,D2m);
            s[b0+3*L] = csub(B1,D2m);
        }
        __syncthreads();
    }
    // H-axis DIT on all 128 columns. radix-2 stage: odd rows are zero -> copy
    for (int j = tid; j < 64*128; j += 1024){
        int w = j & 127, g = j >> 7;
        int i0 = (2*g)*129 + w;
        s[i0 + 129] = s[i0];
    }
    __syncthreads();
    for (int L = 2; L <= 32; L <<= 2){
        for (int j = tid; j < 32*128; j += 1024){
            int w = j & 127, o = j >> 7;
            int grp = o / L, k = o - grp*L;
            int r0 = grp*4*L + k;
            float2 A = s[r0*129+w],       B = s[(r0+L)*129+w];
            float2 C = s[(r0+2*L)*129+w], D = s[(r0+3*L)*129+w];
            float2 w1 = stw[k*(256/(2*L))];
            float2 w2 = stw[k*(256/(4*L))];
            float2 Bt = cmul(w1,B), Dt = cmul(w1,D);
            float2 A1 = cadd(A,Bt), B1 = csub(A,Bt);
            float2 C1 = cadd(C,Dt), D1 = csub(C,Dt);
            float2 C2 = cmul(w2,C1), D2 = cmul(w2,D1);
            float2 D2m = make_float2(D2.y, -D2.x);
            s[r0*129+w]       = cadd(A1,C2);
            s[(r0+2*L)*129+w] = csub(A1,C2);
            s[(r0+L)*129+w]   = cadd(B1,D2m);
            s[(r0+3*L)*129+w] = csub(B1,D2m);
        }
        __syncthreads();
    }
    float2* dst = g_bufA + (size_t)bd*VOL + (size_t)t*16384;
    for (int i = tid; i < 128*128; i += 1024)
        dst[i] = s[(i >> 7)*129 + (i & 127)];
}

// ---------------- attention scalar reductions ----------------
__device__ double blockReduceD(double v){
    __shared__ double sh[256];
    sh[threadIdx.x] = v; __syncthreads();
    for (int s = 128; s; s >>= 1){ if (threadIdx.x < s) sh[threadIdx.x] += sh[threadIdx.x + s]; __syncthreads(); }
    double r = sh[0]; __syncthreads(); return r;
}
__device__ float blockReduceMin(float v){
    __shared__ float sh[256];
    sh[threadIdx.x] = v; __syncthreads();
    for (int s = 128; s; s >>= 1){ if (threadIdx.x < s) sh[threadIdx.x] = fminf(sh[threadIdx.x], sh[threadIdx.x + s]); __syncthreads(); }
    float r = sh[0]; __syncthreads(); return r;
}
__device__ float blockReduceMax(float v){
    __shared__ float sh[256];
    sh[threadIdx.x] = v; __syncthreads();
    for (int s = 128; s; s >>= 1){ if (threadIdx.x < s) sh[threadIdx.x] = fmaxf(sh[threadIdx.x], sh[threadIdx.x + s]); __syncthreads(); }
    float r = sh[0]; __syncthreads(); return r;
}

__device__ __forceinline__ void block_elems(const float* K, int j, float& kL, float& kH, float& vL){
    int tl = j >> 12, hl = (j >> 6) & 63, wl = j & 63;
    float pe = sinf((float)tl);
    vL = K[((192 + tl) & 255)*16384 + ((96 + hl) & 127)*128 + ((96 + wl) & 127)];
    float vH = K[(64 + tl)*16384 + (32 + hl)*128 + (32 + wl)];
    kL = vL + pe; kH = vH + pe;
}

__global__ __launch_bounds__(256) void k_redA(const float* __restrict__ invr, const float* __restrict__ invi){
    int f = blockIdx.y;
    const float* K = f ? invi : invr;
    double sum = 0.0;
    float mnL = 3.4e38f, mxL = -3.4e38f, mnH = 3.4e38f, mxH = -3.4e38f;
    for (int j = blockIdx.x*256 + threadIdx.x; j < NB; j += RBLK*256){
        float kL, kH, vL; block_elems(K, j, kL, kH, vL);
        sum += (double)vL;
        mnL = fminf(mnL, kL); mxL = fmaxf(mxL, kL);
        mnH = fminf(mnH, kH); mxH = fmaxf(mxH, kH);
    }
    sum = blockReduceD(sum);
    mnL = blockReduceMin(mnL); mxL = blockReduceMax(mxL);
    mnH = blockReduceMin(mnH); mxH = blockReduceMax(mxH);
    if (threadIdx.x == 0){
        g_pD[f][blockIdx.x] = sum;
        g_pMnL[f][blockIdx.x] = mnL; g_pMxL[f][blockIdx.x] = mxL;
        g_pMnH[f][blockIdx.x] = mnH; g_pMxH[f][blockIdx.x] = mxH;
    }
}

__global__ void k_combA(const float* __restrict__ wp, const float* __restrict__ bp){
    int f = blockIdx.x, i = threadIdx.x;
    __shared__ double sd[256]; __shared__ float s1[256], s2[256], s3[256], s4[256];
    sd[i] = g_pD[f][i] + g_pD[f][i+256];
    s1[i] = fminf(g_pMnL[f][i], g_pMnL[f][i+256]);
    s2[i] = fmaxf(g_pMxL[f][i], g_pMxL[f][i+256]);
    s3[i] = fminf(g_pMnH[f][i], g_pMnH[f][i+256]);
    s4[i] = fmaxf(g_pMxH[f][i], g_pMxH[f][i+256]);
    __syncthreads();
    for (int s = 128; s; s >>= 1){
        if (i < s){
            sd[i] += sd[i+s];
            s1[i] = fminf(s1[i], s1[i+s]); s2[i] = fmaxf(s2[i], s2[i+s]);
            s3[i] = fminf(s3[i], s3[i+s]); s4[i] = fmaxf(s4[i], s4[i+s]);
        }
        __syncthreads();
    }
    if (i == 0){
        float W = *wp, B = *bp;
        float scal1 = W*(float)(sd[0]/(double)NB) + B;
        float a1 = scal1*W, c1 = scal1*B;
        g_a1[f] = a1; g_c1[f] = c1;
        g_M1f[f] = (a1 >= 0.f ? a1*s2[0] : a1*s1[0]) + c1;
        g_mnH[f] = s3[0]; g_mxH[f] = s4[0];
    }
}

__global__ __launch_bounds__(256) void k_redB(const float* __restrict__ invr, const float* __restrict__ invi){
    int f = blockIdx.y; const float* K = f ? invi : invr;
    float a1 = g_a1[f], c1 = g_c1[f], M1 = g_M1f[f];
    double acc = 0.0;
    for (int j = blockIdx.x*256 + threadIdx.x; j < NB; j += RBLK*256){
        float kL, kH, vL; block_elems(K, j, kL, kH, vL);
        acc += (double)expf(fmaf(a1, kL, c1) - M1);
    }
    acc = blockReduceD(acc);
    if (threadIdx.x == 0) g_pD[f][blockIdx.x] = acc;
}
__global__ void k_combB(){
    int f = blockIdx.x, i = threadIdx.x;
    __shared__ double sd[256];
    sd[i] = g_pD[f][i] + g_pD[f][i+256]; __syncthreads();
    for (int s = 128; s; s >>= 1){ if (i < s) sd[i] += sd[i+s]; __syncthreads(); }
    if (i == 0) g_Z1i[f] = (float)(1.0/sd[0]);
}

__global__ __launch_bounds__(256) void k_redC(const float* __restrict__ invr, const float* __restrict__ invi){
    int f = blockIdx.y; const float* K = f ? invi : invr;
    float a1 = g_a1[f], c1 = g_c1[f], M1 = g_M1f[f], Z1i = g_Z1i[f];
    double acc = 0.0;
    for (int j = blockIdx.x*256 + threadIdx.x; j < NB; j += RBLK*256){
        float kL, kH, vL; block_elems(K, j, kL, kH, vL);
        float sm = expf(fmaf(a1, kL, c1) - M1) * Z1i;
        acc += (double)(kL / (1.f + expf(-sm)));
    }
    acc = blockReduceD(acc);
    if (threadIdx.x == 0) g_pD[f][blockIdx.x] = acc;
}
__global__ void k_combC(const float* __restrict__ wp, const float* __restrict__ bp){
    int f = blockIdx.x, i = threadIdx.x;
    __shared__ double sd[256];
    sd[i] = g_pD[f][i] + g_pD[f][i+256]; __syncthreads();
    for (int s = 128; s; s >>= 1){ if (i < s) sd[i] += sd[i+s]; __syncthreads(); }
    if (i == 0){
        float W = *wp, B = *bp;
        float scal2 = W*(float)(sd[0]/(double)NB) + B;
        float a2 = scal2*W, c2 = scal2*B;
        g_a2[f] = a2; g_c2[f] = c2;
        g_M2f[f] = (a2 >= 0.f ? a2*g_mxH[f] : a2*g_mnH[f]) + c2;
    }
}

__global__ __launch_bounds__(256) void k_redD(const float* __restrict__ invr, const float* __restrict__ invi){
    int f = blockIdx.y; const float* K = f ? invi : invr;
    float a2 = g_a2[f], c2 = g_c2[f], M2 = g_M2f[f];
    double acc = 0.0;
    for (int j = blockIdx.x*256 + threadIdx.x; j < NB; j += RBLK*256){
        float kL, kH, vL; block_elems(K, j, kL, kH, vL);
        acc += (double)expf(fmaf(a2, kH, c2) - M2);
    }
    acc = blockReduceD(acc);
    if (threadIdx.x == 0) g_pD[f][blockIdx.x] = acc;
}
__global__ void k_combD(){
    int f = blockIdx.x, i = threadIdx.x;
    __shared__ double sd[256];
    sd[i] = g_pD[f][i] + g_pD[f][i+256]; __syncthreads();
    for (int s = 128; s; s >>= 1){ if (i < s) sd[i] += sd[i+s]; __syncthreads(); }
    if (i == 0) g_Z2i[f] = (float)(1.0/sd[0]);
}

// ---------------- attention filter (pointwise) ----------------
__device__ __forceinline__ float atten_filter(float v, int t, int h, int w, int f){
    int tl = t - 64, hl = h - 32, wl = w - 32;
    if ((unsigned)tl < 128u && (unsigned)hl < 64u && (unsigned)wl < 64u){
        float k2p = v + sinf((float)tl);
        float sm = expf(fmaf(g_a2[f], k2p, g_c2[f]) - g_M2f[f]) * g_Z2i[f];
        return k2p / (1.f + expf(-sm));
    }
    int tl2 = (t + 64) & 255, hl2 = (h + 32) & 127, wl2 = (w + 32) & 127;
    if (tl2 < 128 && hl2 < 64 && wl2 < 64){
        float k2p = v + sinf((float)tl2);
        float sm = expf(fmaf(g_a1[f], k2p, g_c1[f]) - g_M1f[f]) * g_Z1i[f];
        return k2p / (1.f + expf(-sm));
    }
    return v;
}

// ---------------- precompute filtered W volume: (W(k), W(-k)) / 256 ----------------
__global__ __launch_bounds__(256) void k_filterW(const float* __restrict__ invr, const float* __restrict__ invi){
    int idx = blockIdx.x*256 + threadIdx.x;
    int t = idx >> 14, h = (idx >> 7) & 127, w = idx & 127;
    const float sc = 1.f/256.f;
    int tn = (256 - t) & 255, hn = (128 - h) & 127, wn = (128 - w) & 127;
    size_t ridx = (size_t)tn*16384 + (size_t)hn*128 + wn;
    float w1 = atten_filter(invr[idx],  t,  h,  w,  0)*sc;
    float w2 = atten_filter(invi[idx],  t,  h,  w,  1)*sc;
    float v1 = atten_filter(invr[ridx], tn, hn, wn, 0)*sc;
    float v2 = atten_filter(invi[ridx], tn, hn, wn, 1)*sc;
    g_Wf[idx] = make_float4(w1, w2, v1, v2);
}

// ---------------- fused T: 1 fwd DIF-FFT + pointwise G1/G2' + 2 inv DIT-FFT ----------------
// G1 = W(k)Z(k) -> P ; G2' = conj(W(-k))Z(k) -> R, with Q = conj(R) applied at combine.
__global__ __launch_bounds__(256) void k_fusedT(){
    extern __shared__ unsigned char smraw[];
    float2* ZA  = (float2*)smraw;
    float2* ZB  = ZA + 256*17;
    float2* stw = ZB + 256*17;
    int tid = threadIdx.x;
    int wb = blockIdx.x << 4, h = blockIdx.y, bd = blockIdx.z;
    if (tid < 128) stw[tid] = g_tw[tid];
    const float2* ZS = g_bufA + (size_t)bd*VOL + (size_t)h*128 + wb;
    for (int i = tid; i < 128*16; i += 256){
        int t = i >> 4, lane = i & 15;
        ZA[t*17+lane]       = ZS[(size_t)t*16384 + lane];
        ZA[(t+128)*17+lane] = make_float2(0.f, 0.f);
    }
    __syncthreads();
    // forward radix-4 DIF (natural -> dr4), single tile
    for (int M = 256; M >= 4; M >>= 2){
        int q = M >> 2;
        for (int j = tid; j < 1024; j += 256){
            int lane = j & 15, o = j >> 4;
            int blk = o / q, k = o - blk*q;
            int b0 = blk*M + k;
            float2 A = ZA[b0*17+lane],       B = ZA[(b0+q)*17+lane];
            float2 C = ZA[(b0+2*q)*17+lane], D = ZA[(b0+3*q)*17+lane];
            float2 t0 = cadd(A,C), t1 = csub(A,C), t2 = cadd(B,D), t3 = csub(B,D);
            float2 w1 = stw[k*(256/M)];
            float2 w2 = cmul(w1,w1);
            float2 w3 = cmul(w1,w2);
            ZA[b0*17+lane] = cadd(t0,t2);
            float2 u1 = make_float2(t1.x + t3.y, t1.y - t3.x);   // t1 - i*t3
            ZA[(b0+q)*17+lane]   = cmul(u1, w1);
            ZA[(b0+2*q)*17+lane] = cmul(csub(t0,t2), w2);
            float2 u3 = make_float2(t1.x - t3.y, t1.y + t3.x);   // t1 + i*t3
            ZA[(b0+3*q)*17+lane] = cmul(u3, w3);
        }
        __syncthreads();
    }
    // pointwise: ZB = conj(W(-k)) * Z, ZA = W(k) * Z  (precomputed, coalesced float4)
    const float4* WF = g_Wf + (size_t)h*128 + wb;
    for (int i = tid; i < 256*16; i += 256){
        int t = i >> 4, lane = i & 15;
        int p = dr4(t);
        float4 wf = WF[(size_t)t*16384 + lane];
        float2 z = ZA[p*17+lane];
        ZB[p*17+lane] = cmul(make_float2(wf.z, -wf.w), z);
        ZA[p*17+lane] = cmul(make_float2(wf.x,  wf.y), z);
    }
    __syncthreads();
    // inverse radix-4 DIT (dr4 -> natural), both tiles
    for (int L = 1; L <= 64; L <<= 2){
        for (int j = tid; j < 2048; j += 256){
            float2* S = (j < 1024) ? ZA : ZB;
            int jj = j & 1023;
            int lane = jj & 15, o = jj >> 4;
            int grp = o / L, k = o - grp*L;
            int b0 = grp*4*L + k;
            float2 E0 = S[b0*17+lane],       E1 = S[(b0+L)*17+lane];
            float2 E2 = S[(b0+2*L)*17+lane], E3 = S[(b0+3*L)*17+lane];
            float2 w1 = stw[k*(256/(4*L))]; w1.y = -w1.y;
            float2 w2 = cmul(w1,w1), w3 = cmul(w1,w2);
            float2 b1 = cmul(w1,E1), b2 = cmul(w2,E2), b3 = cmul(w3,E3);
            float2 s0 = cadd(E0,b2), s1 = csub(E0,b2);
            float2 s2 = cadd(b1,b3), s3 = csub(b1,b3);
            S[b0*17+lane]       = cadd(s0,s2);
            S[(b0+2*L)*17+lane] = csub(s0,s2);
            S[(b0+L)*17+lane]   = make_float2(s1.x - s3.y, s1.y + s3.x);
            S[(b0+3*L)*17+lane] = make_float2(s1.x + s3.y, s1.y - s3.x);
        }
        __syncthreads();
    }
    float2* dP = g_bufB + (size_t)(2*bd)*VOL + (size_t)h*128 + wb;
    for (int i = tid; i < 128*16; i += 256){
        int t = i >> 4, lane = i & 15;
        dP[(size_t)t*16384 + lane]               = ZA[t*17+lane];
        dP[(size_t)VOL + (size_t)t*16384 + lane] = ZB[t*17+lane];
    }
}

// ---------------- inverse 2D (H,W) per t-slice, crop, fused P*conj(R)/mag/sqrt ----------
__global__ __launch_bounds__(1024) void k_inv2D(){
    extern __shared__ unsigned char smraw[];
    float2* s   = (float2*)smraw;              // 128*129
    float2* qd  = s + 128*129;                 // 64*65 (P quadrant stash)
    float2* stw = qd + 64*65;
    int tid = threadIdx.x;
    int t = blockIdx.x, bd = blockIdx.y;
    if (tid < 128){ float2 w = g_tw[tid]; stw[tid] = make_float2(w.x, -w.y); }  // conj
    for (int pass = 0; pass < 2; pass++){
        const float2* src = g_bufB + (size_t)(2*bd + pass)*VOL + (size_t)t*16384;
        __syncthreads();
        for (int i = tid; i < 128*128; i += 1024){
            int h = i >> 7, w = i & 127;
            s[brev7(h)*129 + w] = src[i];
        }
        __syncthreads();
        // H-axis inverse DIT (bit-reversed input): radix-2 then fused radix-4
        for (int j = tid; j < 64*128; j += 1024){
            int w = j & 127, g = j >> 7;
            int i0 = (2*g)*129 + w, i1 = i0 + 129;
            float2 a = s[i0], b = s[i1];
            s[i0] = cadd(a,b); s[i1] = csub(a,b);
        }
        __syncthreads();
        for (int L = 2; L <= 32; L <<= 2){
            for (int j = tid; j < 32*128; j += 1024){
                int w = j & 127, o = j >> 7;
                int grp = o / L, k = o - grp*L;
                int r0 = grp*4*L + k;
                float2 A = s[r0*129+w],       B = s[(r0+L)*129+w];
                float2 C = s[(r0+2*L)*129+w], D = s[(r0+3*L)*129+w];
                float2 w1 = stw[k*(256/(2*L))];
                float2 w2 = stw[k*(256/(4*L))];
                float2 Bt = cmul(w1,B), Dt = cmul(w1,D);
                float2 A1 = cadd(A,Bt), B1 = csub(A,Bt);
                float2 C1 = cadd(C,Dt), D1 = csub(C,Dt);
                float2 C2 = cmul(w2,C1), D2 = cmul(w2,D1);
                float2 D2m = make_float2(-D2.y, D2.x);
                s[r0*129+w]       = cadd(A1,C2);
                s[(r0+2*L)*129+w] = csub(A1,C2);
                s[(r0+L)*129+w]   = cadd(B1,D2m);
                s[(r0+3*L)*129+w] = csub(B1,D2m);
            }
            __syncthreads();
        }
        // W-axis inverse DIF (natural -> bit-reversed) on rows h<64 only
        for (int M = 128; M >= 8; M >>= 2){
            int q = M >> 2;
            for (int j = tid; j < 64*32; j += 1024){
                int row = j >> 5, o = j & 31;
                int grp = o / q, k = o - grp*q;
                int b0 = row*129 + grp*M + k;
                float2 A = s[b0], B = s[b0+q], C = s[b0+2*q], D = s[b0+3*q];
                float2 wA = stw[k*(256/M)];
                float2 w2 = stw[(2*k)*(256/M)];
                float2 sAC = cadd(A,C), dAC = csub(A,C);
                float2 sBD = cadd(B,D), dBD = csub(B,D);
                s[b0]   = cadd(sAC, sBD);
                s[b0+q] = cmul(csub(sAC, sBD), w2);
                float2 u2 = make_float2(dAC.x - dBD.y, dAC.y + dBD.x);  // dAC + i*dBD
                s[b0+2*q] = cmul(u2, wA);
                float2 u3 = make_float2(dAC.x + dBD.y, dAC.y - dBD.x); // dAC - i*dBD
                s[b0+3*q] = cmul(u3, cmul(wA, w2));
            }
            __syncthreads();
        }
        for (int j = tid; j < 64*64; j += 1024){
            int row = j >> 6, g = j & 63;
            int i0 = row*129 + 2*g;
            float2 a = s[i0], b = s[i0+1];
            s[i0] = cadd(a,b); s[i0+1] = csub(a,b);
        }
        __syncthreads();
        if (pass == 0){
            for (int i = tid; i < 64*64; i += 1024){
                int h = i >> 6, w = i & 63;
                qd[h*65 + w] = s[h*129 + brev7(w)];
            }
        } else {
            const float S2 = 1.f/268435456.f;   // (1/16384)^2
            float* dst = g_sq + (size_t)bd*NB + (size_t)t*4096;
            for (int i = tid; i < 64*64; i += 1024){
                int h = i >> 6, w = i & 63;
                float2 P = qd[h*65 + w];
                float2 R = s[h*129 + brev7(w)];
                float Sr = (P.x*R.x + P.y*R.y)*S2;     // P * conj(R)
                float Si = (P.y*R.x - P.x*R.y)*S2;
                float mag = fmaxf(0.5f*(sqrtf(Sr*Sr + Si*Si) + Sr), 0.f);
                dst[i] = sqrtf(mag);
            }
        }
    }
}

// ---------------- final mtxi matmul along T ----------------
__global__ __launch_bounds__(1024) void k_final(const float* __restrict__ mtxi, float* __restrict__ out){
    __shared__ float sx[128*64];
    int bd = blockIdx.x >> 6, h = blockIdx.x & 63;
    const float* src = g_sq + (size_t)bd*NB + h*64;
    for (int i = threadIdx.x; i < 128*64; i += 1024){
        int t = i >> 6, w = i & 63;
        sx[i] = src[(size_t)t*4096 + w];
    }
    __syncthreads();
    float* dst = out + (size_t)bd*NB + h*64;
    for (int o = threadIdx.x; o < 128*64; o += 1024){
        int t = o >> 6, w = o & 63;
        float acc = 0.f;
        const float* mi = mtxi + t*128;
        #pragma unroll 8
        for (int m = 0; m < 128; m++) acc = fmaf(mi[m], sx[m*64 + w], acc);
        dst[(size_t)t*4096 + w] = acc;
    }
}

// ---------------- launch ----------------
#define FWD2D_SMEM (128*129*8 + 128*8)
#define INV2D_SMEM (128*129*8 + 64*65*8 + 128*8)
#define FT_SMEM    (2*256*17*8 + 128*8)

extern "C" void kernel_launch(void* const* d_in, const int* in_sizes, int n_in,
                              void* d_out, int out_size){
    const float *feature = 0, *conv_w = 0, *conv_b = 0, *wave = 0;
    const float *invr = 0, *invi = 0, *mtx = 0, *mtxi = 0;
    int scal_seen = 0, mat_seen = 0, psf_seen = 0;
    for (int i = 0; i < n_in; i++){
        const float* p = (const float*)d_in[i];
        int s = in_sizes[i];
        if      (s == 1)       { if (scal_seen++ == 0) conv_w = p; else conv_b = p; }
        else if (s == 126)     wave = p;
        else if (s == 16384)   { if (mat_seen++ == 0) mtx = p; else mtxi = p; }
        else if (s == 4194304) { if (psf_seen++ == 0) invr = p; else invi = p; }
        else if (s == 1048576) feature = p;
    }
    float* out = (float*)d_out;

    cudaFuncSetAttribute(k_fwd2D,  cudaFuncAttributeMaxDynamicSharedMemorySize, FWD2D_SMEM);
    cudaFuncSetAttribute(k_inv2D,  cudaFuncAttributeMaxDynamicSharedMemorySize, INV2D_SMEM);
    cudaFuncSetAttribute(k_fusedT, cudaFuncAttributeMaxDynamicSharedMemorySize, FT_SMEM);

    k_init_tw<<<1,128>>>();
    k_build_M<<<64,256>>>(mtx, wave);

    // forward path
    k_conv<<<128,1024>>>(feature);
    k_fwd2D<<<dim3(128,2),1024,FWD2D_SMEM>>>();

    // attention scalars (4 reduce + 4 combine)
    k_redA<<<dim3(RBLK,2),256>>>(invr, invi);
    k_combA<<<2,256>>>(conv_w, conv_b);
    k_redB<<<dim3(RBLK,2),256>>>(invr, invi);
    k_combB<<<2,256>>>();
    k_redC<<<dim3(RBLK,2),256>>>(invr, invi);
    k_combC<<<2,256>>>(conv_w, conv_b);
    k_redD<<<dim3(RBLK,2),256>>>(invr, invi);
    k_combD<<<2,256>>>();

    // precompute attention-filtered spectrum (W(k), W(-k)) once
    k_filterW<<<VOL/256,256>>>(invr, invi);

    // fused: fwd T-FFT + pointwise G1/G2' + two inverse T-FFTs (crop t<128)
    k_fusedT<<<dim3(8,128,2),256,FT_SMEM>>>();

    // inverse 2D per slice with fused P*conj(R), mag, relu, sqrt
    k_inv2D<<<dim3(128,2),1024,INV2D_SMEM>>>();

    k_final<<<128,1024>>>(mtxi, out);
}

// round 12
// speedup vs baseline: 2.0069x; 1.2600x over previous
#include <cuda_runtime.h>
#include <math.h>

#define VOL (256*128*128)     /* 4194304 full padded volume */
#define NB  (128*64*64)       /* 524288  crop / attention block */
#define RBLK 512

// ---------------- scratch (static device allocations, no runtime alloc) ----------------
static __device__ float2 g_bufA[2*(size_t)VOL];   // Z spectra per bd (t<128 used)
static __device__ float2 g_bufB[4*(size_t)VOL];   // P,R per bd (t<128 used)
static __device__ float2 g_zc[2*(size_t)NB];      // conv+mtx packed complex (cos + i sin)
static __device__ float  g_sq[2*(size_t)NB];      // sqrt(mag) crop
static __device__ float2 g_Wf[(size_t)VOL];       // filtered W(k)/256
static __device__ float  g_Mc[128*128];
static __device__ float  g_Ms[128*128];
static __device__ float2 g_tw[128];               // W_256^k, k<128 (forward sign)

// attention reduction state
static __device__ double g_pD[2][RBLK];
static __device__ float  g_pMnL[2][RBLK], g_pMxL[2][RBLK], g_pMnH[2][RBLK], g_pMxH[2][RBLK];
static __device__ float  g_a1[2], g_c1[2], g_M1f[2], g_Z1i[2];
static __device__ float  g_a2[2], g_c2[2], g_M2f[2], g_Z2i[2];
static __device__ float  g_mnH[2], g_mxH[2];

__device__ __forceinline__ float2 cmul(float2 a, float2 b){
    return make_float2(a.x*b.x - a.y*b.y, a.x*b.y + a.y*b.x);
}
__device__ __forceinline__ float2 cadd(float2 a, float2 b){ return make_float2(a.x+b.x, a.y+b.y); }
__device__ __forceinline__ float2 csub(float2 a, float2 b){ return make_float2(a.x-b.x, a.y-b.y); }
__device__ __forceinline__ int brev7(int i){ return (int)(__brev((unsigned)i) >> 25); }

// ---------------- register FFT-16 machinery ----------------
template<int SGN>
__device__ __forceinline__ float2 twd(const float2* stw, int m){
    m &= 255;
    float2 w = (m < 128) ? stw[m] : make_float2(-stw[m-128].x, -stw[m-128].y);
    if (SGN < 0) w.y = -w.y;
    return w;
}

template<int SGN>
__device__ __forceinline__ void bfly4(float2&a,float2&b,float2&c,float2&d){
    float2 t0=cadd(a,c), t1=csub(a,c), t2=cadd(b,d), t3=csub(b,d);
    float2 it3 = (SGN>0)? make_float2(t3.y,-t3.x) : make_float2(-t3.y,t3.x);
    a=cadd(t0,t2); c=csub(t0,t2);
    b=cadd(t1,it3); d=csub(t1,it3);
}

// 16-pt DFT, natural in / natural out, in registers
template<int SGN>
__device__ __forceinline__ void fft16(float2 r[16], const float2* stw){
    #pragma unroll
    for(int a=0;a<4;a++){
        bfly4<SGN>(r[a], r[a+4], r[a+8], r[a+12]);
        #pragma unroll
        for(int k1=1;k1<4;k1++)
            r[a+4*k1] = cmul(r[a+4*k1], twd<SGN>(stw, 16*a*k1));
    }
    #pragma unroll
    for(int k1=0;k1<4;k1++)
        bfly4<SGN>(r[4*k1], r[4*k1+1], r[4*k1+2], r[4*k1+3]);
    float2 tmp[16];
    #pragma unroll
    for(int i=0;i<16;i++) tmp[((i&3)<<2)|(i>>2)] = r[i];
    #pragma unroll
    for(int i=0;i<16;i++) r[i]=tmp[i];
}

// ---------------- init ----------------
__global__ void k_init_tw(){
    int i = threadIdx.x;
    if (i < 128){
        double a = -2.0*3.14159265358979323846*(double)i/256.0;
        double s, c; sincos(a, &s, &c);
        g_tw[i] = make_float2((float)c, (float)s);
    }
}

// Mc[t][j] = sum_m mtx[t][m] * waveC[j-m+31] (k=63 taps), same for Ms
__global__ void k_build_M(const float* __restrict__ mtx, const float* __restrict__ wave){
    int idx = blockIdx.x*blockDim.x + threadIdx.x;
    if (idx >= 128*128) return;
    int t = idx >> 7, j = idx & 127;
    float ac = 0.f, as = 0.f;
    for (int m = 0; m < 128; m++){
        int tau = j - m + 31;
        if (tau >= 0 && tau < 63){
            float mv = mtx[t*128 + m];
            ac = fmaf(mv, wave[tau],      ac);
            as = fmaf(mv, wave[63 + tau], as);
        }
    }
    g_Mc[idx] = ac; g_Ms[idx] = as;
}

// ---------------- conv+mtx -> packed complex ----------------
__global__ __launch_bounds__(1024) void k_conv(const float* __restrict__ feat){
    __shared__ float sx[128*64];
    int bd = blockIdx.x >> 6, h = blockIdx.x & 63;
    const float* src = feat + (size_t)bd*NB + h*64;
    for (int i = threadIdx.x; i < 128*64; i += 1024){
        int t = i >> 6, w = i & 63;
        sx[i] = src[(size_t)t*4096 + w];
    }
    __syncthreads();
    float2* dst = g_zc + (size_t)bd*NB + h*64;
    for (int o = threadIdx.x; o < 128*64; o += 1024){
        int t = o >> 6, w = o & 63;
        float ac = 0.f, as = 0.f;
        const float* mc = g_Mc + t*128;
        const float* ms = g_Ms + t*128;
        #pragma unroll 8
        for (int m = 0; m < 128; m++){
            float xv = sx[m*64 + w];
            ac = fmaf(mc[m], xv, ac);
            as = fmaf(ms[m], xv, as);
        }
        dst[(size_t)t*4096 + w] = make_float2(ac, as);
    }
}

// ---------------- forward 2D (H,W) FFT per t-slice, zero-padded 64x64 -> 128x128 --------
__global__ __launch_bounds__(1024) void k_fwd2D(){
    extern __shared__ unsigned char smraw[];
    float2* s   = (float2*)smraw;              // [h*129 + w]
    float2* stw = s + 128*129;
    int tid = threadIdx.x;
    int t = blockIdx.x, bd = blockIdx.y;
    if (tid < 128) stw[tid] = g_tw[tid];
    for (int i = tid; i < 128*129; i += 1024) s[i] = make_float2(0.f, 0.f);
    __syncthreads();
    const float2* src = g_zc + (size_t)bd*NB + (size_t)t*4096;
    for (int i = tid; i < 64*64; i += 1024){
        int h = i >> 6, w = i & 63;
        s[brev7(h)*129 + brev7(w)] = src[i];    // even rows / even cols
    }
    __syncthreads();
    for (int j = tid; j < 64*64; j += 1024){
        int row = (j >> 6) << 1, g = j & 63;
        int i0 = row*129 + 2*g;
        s[i0 + 1] = s[i0];
    }
    __syncthreads();
    for (int L = 2; L <= 32; L <<= 2){
        for (int j = tid; j < 64*32; j += 1024){
            int row = (j >> 5) << 1, o = j & 31;
            int grp = o / L, k = o - grp*L;
            int b0 = row*129 + grp*4*L + k;
            float2 A = s[b0], B = s[b0+L], C = s[b0+2*L], D = s[b0+3*L];
            float2 w1 = stw[k*(256/(2*L))];
            float2 w2 = stw[k*(256/(4*L))];
            float2 Bt = cmul(w1,B), Dt = cmul(w1,D);
            float2 A1 = cadd(A,Bt), B1 = csub(A,Bt);
            float2 C1 = cadd(C,Dt), D1 = csub(C,Dt);
            float2 C2 = cmul(w2,C1), D2 = cmul(w2,D1);
            float2 D2m = make_float2(D2.y, -D2.x);
            s[b0]     = cadd(A1,C2);
            s[b0+2*L] = csub(A1,C2);
            s[b0+L]   = cadd(B1,D2m);
            s[b0+3*L] = csub(B1,D2m);
        }
        __syncthreads();
    }
    for (int j = tid; j < 64*128; j += 1024){
        int w = j & 127, g = j >> 7;
        int i0 = (2*g)*129 + w;
        s[i0 + 129] = s[i0];
    }
    __syncthreads();
    for (int L = 2; L <= 32; L <<= 2){
        for (int j = tid; j < 32*128; j += 1024){
            int w = j & 127, o = j >> 7;
            int grp = o / L, k = o - grp*L;
            int r0 = grp*4*L + k;
            float2 A = s[r0*129+w],       B = s[(r0+L)*129+w];
            float2 C = s[(r0+2*L)*129+w], D = s[(r0+3*L)*129+w];
            float2 w1 = stw[k*(256/(2*L))];
            float2 w2 = stw[k*(256/(4*L))];
            float2 Bt = cmul(w1,B), Dt = cmul(w1,D);
            float2 A1 = cadd(A,Bt), B1 = csub(A,Bt);
            float2 C1 = cadd(C,Dt), D1 = csub(C,Dt);
            float2 C2 = cmul(w2,C1), D2 = cmul(w2,D1);
            float2 D2m = make_float2(D2.y, -D2.x);
            s[r0*129+w]       = cadd(A1,C2);
            s[(r0+2*L)*129+w] = csub(A1,C2);
            s[(r0+L)*129+w]   = cadd(B1,D2m);
            s[(r0+3*L)*129+w] = csub(B1,D2m);
        }
        __syncthreads();
    }
    float2* dst = g_bufA + (size_t)bd*VOL + (size_t)t*16384;
    for (int i = tid; i < 128*128; i += 1024)
        dst[i] = s[(i >> 7)*129 + (i & 127)];
}

// ---------------- attention scalar reductions ----------------
__device__ double blockReduceD(double v){
    __shared__ double sh[256];
    sh[threadIdx.x] = v; __syncthreads();
    for (int s = 128; s; s >>= 1){ if (threadIdx.x < s) sh[threadIdx.x] += sh[threadIdx.x + s]; __syncthreads(); }
    double r = sh[0]; __syncthreads(); return r;
}
__device__ float blockReduceMin(float v){
    __shared__ float sh[256];
    sh[threadIdx.x] = v; __syncthreads();
    for (int s = 128; s; s >>= 1){ if (threadIdx.x < s) sh[threadIdx.x] = fminf(sh[threadIdx.x], sh[threadIdx.x + s]); __syncthreads(); }
    float r = sh[0]; __syncthreads(); return r;
}
__device__ float blockReduceMax(float v){
    __shared__ float sh[256];
    sh[threadIdx.x] = v; __syncthreads();
    for (int s = 128; s; s >>= 1){ if (threadIdx.x < s) sh[threadIdx.x] = fmaxf(sh[threadIdx.x], sh[threadIdx.x + s]); __syncthreads(); }
    float r = sh[0]; __syncthreads(); return r;
}

__device__ __forceinline__ void block_elems(const float* K, int j, float& kL, float& kH, float& vL){
    int tl = j >> 12, hl = (j >> 6) & 63, wl = j & 63;
    float pe = sinf((float)tl);
    vL = K[((192 + tl) & 255)*16384 + ((96 + hl) & 127)*128 + ((96 + wl) & 127)];
    float vH = K[(64 + tl)*16384 + (32 + hl)*128 + (32 + wl)];
    kL = vL + pe; kH = vH + pe;
}

__global__ __launch_bounds__(256) void k_redA(const float* __restrict__ invr, const float* __restrict__ invi){
    int f = blockIdx.y;
    const float* K = f ? invi : invr;
    double sum = 0.0;
    float mnL = 3.4e38f, mxL = -3.4e38f, mnH = 3.4e38f, mxH = -3.4e38f;
    for (int j = blockIdx.x*256 + threadIdx.x; j < NB; j += RBLK*256){
        float kL, kH, vL; block_elems(K, j, kL, kH, vL);
        sum += (double)vL;
        mnL = fminf(mnL, kL); mxL = fmaxf(mxL, kL);
        mnH = fminf(mnH, kH); mxH = fmaxf(mxH, kH);
    }
    sum = blockReduceD(sum);
    mnL = blockReduceMin(mnL); mxL = blockReduceMax(mxL);
    mnH = blockReduceMin(mnH); mxH = blockReduceMax(mxH);
    if (threadIdx.x == 0){
        g_pD[f][blockIdx.x] = sum;
        g_pMnL[f][blockIdx.x] = mnL; g_pMxL[f][blockIdx.x] = mxL;
        g_pMnH[f][blockIdx.x] = mnH; g_pMxH[f][blockIdx.x] = mxH;
    }
}

__global__ void k_combA(const float* __restrict__ wp, const float* __restrict__ bp){
    int f = blockIdx.x, i = threadIdx.x;
    __shared__ double sd[256]; __shared__ float s1[256], s2[256], s3[256], s4[256];
    sd[i] = g_pD[f][i] + g_pD[f][i+256];
    s1[i] = fminf(g_pMnL[f][i], g_pMnL[f][i+256]);
    s2[i] = fmaxf(g_pMxL[f][i], g_pMxL[f][i+256]);
    s3[i] = fminf(g_pMnH[f][i], g_pMnH[f][i+256]);
    s4[i] = fmaxf(g_pMxH[f][i], g_pMxH[f][i+256]);
    __syncthreads();
    for (int s = 128; s; s >>= 1){
        if (i < s){
            sd[i] += sd[i+s];
            s1[i] = fminf(s1[i], s1[i+s]); s2[i] = fmaxf(s2[i], s2[i+s]);
            s3[i] = fminf(s3[i], s3[i+s]); s4[i] = fmaxf(s4[i], s4[i+s]);
        }
        __syncthreads();
    }
    if (i == 0){
        float W = *wp, B = *bp;
        float scal1 = W*(float)(sd[0]/(double)NB) + B;
        float a1 = scal1*W, c1 = scal1*B;
        g_a1[f] = a1; g_c1[f] = c1;
        g_M1f[f] = (a1 >= 0.f ? a1*s2[0] : a1*s1[0]) + c1;
        g_mnH[f] = s3[0]; g_mxH[f] = s4[0];
    }
}

__global__ __launch_bounds__(256) void k_redB(const float* __restrict__ invr, const float* __restrict__ invi){
    int f = blockIdx.y; const float* K = f ? invi : invr;
    float a1 = g_a1[f], c1 = g_c1[f], M1 = g_M1f[f];
    double acc = 0.0;
    for (int j = blockIdx.x*256 + threadIdx.x; j < NB; j += RBLK*256){
        float kL, kH, vL; block_elems(K, j, kL, kH, vL);
        acc += (double)expf(fmaf(a1, kL, c1) - M1);
    }
    acc = blockReduceD(acc);
    if (threadIdx.x == 0) g_pD[f][blockIdx.x] = acc;
}
__global__ void k_combB(){
    int f = blockIdx.x, i = threadIdx.x;
    __shared__ double sd[256];
    sd[i] = g_pD[f][i] + g_pD[f][i+256]; __syncthreads();
    for (int s = 128; s; s >>= 1){ if (i < s) sd[i] += sd[i+s]; __syncthreads(); }
    if (i == 0) g_Z1i[f] = (float)(1.0/sd[0]);
}

__global__ __launch_bounds__(256) void k_redC(const float* __restrict__ invr, const float* __restrict__ invi){
    int f = blockIdx.y; const float* K = f ? invi : invr;
    float a1 = g_a1[f], c1 = g_c1[f], M1 = g_M1f[f], Z1i = g_Z1i[f];
    double acc = 0.0;
    for (int j = blockIdx.x*256 + threadIdx.x; j < NB; j += RBLK*256){
        float kL, kH, vL; block_elems(K, j, kL, kH, vL);
        float sm = expf(fmaf(a1, kL, c1) - M1) * Z1i;
        acc += (double)(kL / (1.f + expf(-sm)));
    }
    acc = blockReduceD(acc);
    if (threadIdx.x == 0) g_pD[f][blockIdx.x] = acc;
}
__global__ void k_combC(const float* __restrict__ wp, const float* __restrict__ bp){
    int f = blockIdx.x, i = threadIdx.x;
    __shared__ double sd[256];
    sd[i] = g_pD[f][i] + g_pD[f][i+256]; __syncthreads();
    for (int s = 128; s; s >>= 1){ if (i < s) sd[i] += sd[i+s]; __syncthreads(); }
    if (i == 0){
        float W = *wp, B = *bp;
        float scal2 = W*(float)(sd[0]/(double)NB) + B;
        float a2 = scal2*W, c2 = scal2*B;
        g_a2[f] = a2; g_c2[f] = c2;
        g_M2f[f] = (a2 >= 0.f ? a2*g_mxH[f] : a2*g_mnH[f]) + c2;
    }
}

__global__ __launch_bounds__(256) void k_redD(const float* __restrict__ invr, const float* __restrict__ invi){
    int f = blockIdx.y; const float* K = f ? invi : invr;
    float a2 = g_a2[f], c2 = g_c2[f], M2 = g_M2f[f];
    double acc = 0.0;
    for (int j = blockIdx.x*256 + threadIdx.x; j < NB; j += RBLK*256){
        float kL, kH, vL; block_elems(K, j, kL, kH, vL);
        acc += (double)expf(fmaf(a2, kH, c2) - M2);
    }
    acc = blockReduceD(acc);
    if (threadIdx.x == 0) g_pD[f][blockIdx.x] = acc;
}
__global__ void k_combD(){
    int f = blockIdx.x, i = threadIdx.x;
    __shared__ double sd[256];
    sd[i] = g_pD[f][i] + g_pD[f][i+256]; __syncthreads();
    for (int s = 128; s; s >>= 1){ if (i < s) sd[i] += sd[i+s]; __syncthreads(); }
    if (i == 0) g_Z2i[f] = (float)(1.0/sd[0]);
}

// ---------------- attention filter (pointwise) ----------------
__device__ __forceinline__ float atten_filter(float v, int t, int h, int w, int f){
    int tl = t - 64, hl = h - 32, wl = w - 32;
    if ((unsigned)tl < 128u && (unsigned)hl < 64u && (unsigned)wl < 64u){
        float k2p = v + sinf((float)tl);
        float sm = expf(fmaf(g_a2[f], k2p, g_c2[f]) - g_M2f[f]) * g_Z2i[f];
        return k2p / (1.f + expf(-sm));
    }
    int tl2 = (t + 64) & 255, hl2 = (h + 32) & 127, wl2 = (w + 32) & 127;
    if (tl2 < 128 && hl2 < 64 && wl2 < 64){
        float k2p = v + sinf((float)tl2);
        float sm = expf(fmaf(g_a1[f], k2p, g_c1[f]) - g_M1f[f]) * g_Z1i[f];
        return k2p / (1.f + expf(-sm));
    }
    return v;
}

// ---------------- precompute filtered W volume: W(k)/256 (float2) ----------------
__global__ __launch_bounds__(256) void k_filterW(const float* __restrict__ invr, const float* __restrict__ invi){
    int idx = blockIdx.x*256 + threadIdx.x;
    int t = idx >> 14, h = (idx >> 7) & 127, w = idx & 127;
    const float sc = 1.f/256.f;
    float w1 = atten_filter(invr[idx], t, h, w, 0)*sc;
    float w2 = atten_filter(invi[idx], t, h, w, 1)*sc;
    g_Wf[idx] = make_float2(w1, w2);
}

// ---------------- fused T (16x16 four-step, register FFTs) ----------------
// fwd: X = FFT256(Z pad); A = W(k)X -> P ; B = conj(W(-k))X -> R.
// Thread (role, lane): role = FFT digit, lane = w column. 2 smem buffers 16x257.
__global__ __launch_bounds__(256,2) void k_fusedT(){
    extern __shared__ unsigned char smraw[];
    float2* bufA = (float2*)smraw;           // 16 lanes x 257
    float2* bufB = bufA + 16*257;
    __shared__ float2 stw[128];
    int tid = threadIdx.x, lane = tid & 15, role = tid >> 4;
    if (tid < 128) stw[tid] = g_tw[tid];
    int wb = blockIdx.x << 4, h = blockIdx.y, bd = blockIdx.z;
    int w = wb + lane;

    // load z (t<128; rest zero)
    float2 X[16];
    const float2* ZS = g_bufA + (size_t)bd*VOL + (size_t)h*128 + w;
    #pragma unroll
    for (int j = 0; j < 8; j++) X[j] = ZS[(size_t)(role + 16*j)*16384];
    #pragma unroll
    for (int j = 8; j < 16; j++) X[j] = make_float2(0.f, 0.f);
    __syncthreads();                        // stw ready

    // fwd step1: DFT over n2 (regs), twiddle W256^{n1*k1'}, exchange
    fft16<1>(X, stw);
    int base = lane*257;
    #pragma unroll
    for (int j = 1; j < 16; j++) X[j] = cmul(X[j], twd<1>(stw, role*j));
    #pragma unroll
    for (int j = 0; j < 16; j++) bufA[base + j*16 + role] = X[j];
    __syncthreads();
    // fwd step3: gather over n1, DFT -> X[j] = spectrum at k = role + 16j
    #pragma unroll
    for (int n1 = 0; n1 < 16; n1++) X[n1] = bufA[base + role*16 + n1];
    fft16<1>(X, stw);

    // pointwise: A = W(k)X, B = conj(W(-k))X
    float2 A[16], Bv[16];
    const float2* WD = g_Wf + (size_t)h*128 + w;
    int hn = (128 - h) & 127, wn = (128 - w) & 127;
    const float2* WR = g_Wf + (size_t)hn*128 + wn;
    #pragma unroll
    for (int j = 0; j < 16; j++){
        int k = role + 16*j;
        int kn = (256 - k) & 255;
        float2 wd = WD[(size_t)k*16384];
        float2 wr = WR[(size_t)kn*16384];
        A[j]  = cmul(wd, X[j]);
        Bv[j] = cmul(make_float2(wr.x, -wr.y), X[j]);
    }

    // inverse step1 over k2 (regs already hold G[role+16k2]), twiddle, exchange
    fft16<-1>(A, stw);
    fft16<-1>(Bv, stw);
    __syncthreads();                        // all reads of bufA done
    #pragma unroll
    for (int t1 = 0; t1 < 16; t1++){
        float2 wv = twd<-1>(stw, role*t1);
        bufA[base + t1*16 + role] = cmul(A[t1],  wv);
        bufB[base + t1*16 + role] = cmul(Bv[t1], wv);
    }
    __syncthreads();

    // inverse step3: gather over K, DFT, store crop t<128
    float2* dP = g_bufB + (size_t)(2*bd)*VOL + (size_t)h*128 + w;
    #pragma unroll
    for (int K = 0; K < 16; K++) A[K] = bufA[base + role*16 + K];
    fft16<-1>(A, stw);
    #pragma unroll
    for (int t2 = 0; t2 < 8; t2++) dP[(size_t)(role + 16*t2)*16384] = A[t2];
    #pragma unroll
    for (int K = 0; K < 16; K++) Bv[K] = bufB[base + role*16 + K];
    fft16<-1>(Bv, stw);
    #pragma unroll
    for (int t2 = 0; t2 < 8; t2++) dP[(size_t)VOL + (size_t)(role + 16*t2)*16384] = Bv[t2];
}

// ---------------- inverse 2D (H,W) per t-slice, crop, fused P*conj(R)/mag/sqrt ----------
__global__ __launch_bounds__(1024) void k_inv2D(){
    extern __shared__ unsigned char smraw[];
    float2* s   = (float2*)smraw;              // 128*129
    float2* qd  = s + 128*129;                 // 64*65 (P quadrant stash)
    float2* stw = qd + 64*65;
    int tid = threadIdx.x;
    int t = blockIdx.x, bd = blockIdx.y;
    if (tid < 128){ float2 w = g_tw[tid]; stw[tid] = make_float2(w.x, -w.y); }  // conj
    for (int pass = 0; pass < 2; pass++){
        const float2* src = g_bufB + (size_t)(2*bd + pass)*VOL + (size_t)t*16384;
        __syncthreads();
        for (int i = tid; i < 128*128; i += 1024){
            int h = i >> 7, w = i & 127;
            s[brev7(h)*129 + w] = src[i];
        }
        __syncthreads();
        for (int j = tid; j < 64*128; j += 1024){
            int w = j & 127, g = j >> 7;
            int i0 = (2*g)*129 + w, i1 = i0 + 129;
            float2 a = s[i0], b = s[i1];
            s[i0] = cadd(a,b); s[i1] = csub(a,b);
        }
        __syncthreads();
        for (int L = 2; L <= 32; L <<= 2){
            for (int j = tid; j < 32*128; j += 1024){
                int w = j & 127, o = j >> 7;
                int grp = o / L, k = o - grp*L;
                int r0 = grp*4*L + k;
                float2 A = s[r0*129+w],       B = s[(r0+L)*129+w];
                float2 C = s[(r0+2*L)*129+w], D = s[(r0+3*L)*129+w];
                float2 w1 = stw[k*(256/(2*L))];
                float2 w2 = stw[k*(256/(4*L))];
                float2 Bt = cmul(w1,B), Dt = cmul(w1,D);
                float2 A1 = cadd(A,Bt), B1 = csub(A,Bt);
                float2 C1 = cadd(C,Dt), D1 = csub(C,Dt);
                float2 C2 = cmul(w2,C1), D2 = cmul(w2,D1);
                float2 D2m = make_float2(-D2.y, D2.x);
                s[r0*129+w]       = cadd(A1,C2);
                s[(r0+2*L)*129+w] = csub(A1,C2);
                s[(r0+L)*129+w]   = cadd(B1,D2m);
                s[(r0+3*L)*129+w] = csub(B1,D2m);
            }
            __syncthreads();
        }
        for (int M = 128; M >= 8; M >>= 2){
            int q = M >> 2;
            for (int j = tid; j < 64*32; j += 1024){
                int row = j >> 5, o = j & 31;
                int grp = o / q, k = o - grp*q;
                int b0 = row*129 + grp*M + k;
                float2 A = s[b0], B = s[b0+q], C = s[b0+2*q], D = s[b0+3*q];
                float2 wA = stw[k*(256/M)];
                float2 w2 = stw[(2*k)*(256/M)];
                float2 sAC = cadd(A,C), dAC = csub(A,C);
                float2 sBD = cadd(B,D), dBD = csub(B,D);
                s[b0]   = cadd(sAC, sBD);
                s[b0+q] = cmul(csub(sAC, sBD), w2);
                float2 u2 = make_float2(dAC.x - dBD.y, dAC.y + dBD.x);
                s[b0+2*q] = cmul(u2, wA);
                float2 u3 = make_float2(dAC.x + dBD.y, dAC.y - dBD.x);
                s[b0+3*q] = cmul(u3, cmul(wA, w2));
            }
            __syncthreads();
        }
        for (int j = tid; j < 64*64; j += 1024){
            int row = j >> 6, g = j & 63;
            int i0 = row*129 + 2*g;
            float2 a = s[i0], b = s[i0+1];
            s[i0] = cadd(a,b); s[i0+1] = csub(a,b);
        }
        __syncthreads();
        if (pass == 0){
            for (int i = tid; i < 64*64; i += 1024){
                int h = i >> 6, w = i & 63;
                qd[h*65 + w] = s[h*129 + brev7(w)];
            }
        } else {
            const float S2 = 1.f/268435456.f;   // (1/16384)^2
            float* dst = g_sq + (size_t)bd*NB + (size_t)t*4096;
            for (int i = tid; i < 64*64; i += 1024){
                int h = i >> 6, w = i & 63;
                float2 P = qd[h*65 + w];
                float2 R = s[h*129 + brev7(w)];
                float Sr = (P.x*R.x + P.y*R.y)*S2;     // P * conj(R)
                float Si = (P.y*R.x - P.x*R.y)*S2;
                float mag = fmaxf(0.5f*(sqrtf(Sr*Sr + Si*Si) + Sr), 0.f);
                dst[i] = sqrtf(mag);
            }
        }
    }
}

// ---------------- final mtxi matmul along T ----------------
__global__ __launch_bounds__(1024) void k_final(const float* __restrict__ mtxi, float* __restrict__ out){
    __shared__ float sx[128*64];
    int bd = blockIdx.x >> 6, h = blockIdx.x & 63;
    const float* src = g_sq + (size_t)bd*NB + h*64;
    for (int i = threadIdx.x; i < 128*64; i += 1024){
        int t = i >> 6, w = i & 63;
        sx[i] = src[(size_t)t*4096 + w];
    }
    __syncthreads();
    float* dst = out + (size_t)bd*NB + h*64;
    for (int o = threadIdx.x; o < 128*64; o += 1024){
        int t = o >> 6, w = o & 63;
        float acc = 0.f;
        const float* mi = mtxi + t*128;
        #pragma unroll 8
        for (int m = 0; m < 128; m++) acc = fmaf(mi[m], sx[m*64 + w], acc);
        dst[(size_t)t*4096 + w] = acc;
    }
}

// ---------------- launch ----------------
#define FWD2D_SMEM (128*129*8 + 128*8)
#define INV2D_SMEM (128*129*8 + 64*65*8 + 128*8)
#define FT_SMEM    (2*16*257*8)

extern "C" void kernel_launch(void* const* d_in, const int* in_sizes, int n_in,
                              void* d_out, int out_size){
    const float *feature = 0, *conv_w = 0, *conv_b = 0, *wave = 0;
    const float *invr = 0, *invi = 0, *mtx = 0, *mtxi = 0;
    int scal_seen = 0, mat_seen = 0, psf_seen = 0;
    for (int i = 0; i < n_in; i++){
        const float* p = (const float*)d_in[i];
        int s = in_sizes[i];
        if      (s == 1)       { if (scal_seen++ == 0) conv_w = p; else conv_b = p; }
        else if (s == 126)     wave = p;
        else if (s == 16384)   { if (mat_seen++ == 0) mtx = p; else mtxi = p; }
        else if (s == 4194304) { if (psf_seen++ == 0) invr = p; else invi = p; }
        else if (s == 1048576) feature = p;
    }
    float* out = (float*)d_out;

    cudaFuncSetAttribute(k_fwd2D,  cudaFuncAttributeMaxDynamicSharedMemorySize, FWD2D_SMEM);
    cudaFuncSetAttribute(k_inv2D,  cudaFuncAttributeMaxDynamicSharedMemorySize, INV2D_SMEM);
    cudaFuncSetAttribute(k_fusedT, cudaFuncAttributeMaxDynamicSharedMemorySize, FT_SMEM);

    k_init_tw<<<1,128>>>();
    k_build_M<<<64,256>>>(mtx, wave);

    // forward path
    k_conv<<<128,1024>>>(feature);
    k_fwd2D<<<dim3(128,2),1024,FWD2D_SMEM>>>();

    // attention scalars (4 reduce + 4 combine)
    k_redA<<<dim3(RBLK,2),256>>>(invr, invi);
    k_combA<<<2,256>>>(conv_w, conv_b);
    k_redB<<<dim3(RBLK,2),256>>>(invr, invi);
    k_combB<<<2,256>>>();
    k_redC<<<dim3(RBLK,2),256>>>(invr, invi);
    k_combC<<<2,256>>>(conv_w, conv_b);
    k_redD<<<dim3(RBLK,2),256>>>(invr, invi);
    k_combD<<<2,256>>>();

    // precompute attention-filtered spectrum W(k) once
    k_filterW<<<VOL/256,256>>>(invr, invi);

    // fused: fwd T-FFT + pointwise G1/G2' + two inverse T-FFTs (crop t<128)
    k_fusedT<<<dim3(8,128,2),256,FT_SMEM>>>();

    // inverse 2D per slice with fused P*conj(R), mag, relu, sqrt
    k_inv2D<<<dim3(128,2),1024,INV2D_SMEM>>>();

    k_final<<<128,1024>>>(mtxi, out);
}

// round 13
// speedup vs baseline: 2.0095x; 1.0013x over previous
#include <cuda_runtime.h>
#include <math.h>

#define VOL (256*128*128)     /* 4194304 full padded volume */
#define NB  (128*64*64)       /* 524288  crop / attention block */
#define RBLK 512

// ---------------- scratch (static device allocations, no runtime alloc) ----------------
static __device__ float2 g_bufA[2*(size_t)VOL];   // Z spectra per bd (t<128 used)
static __device__ float2 g_bufB[4*(size_t)VOL];   // P,R per bd (t<128 used)
static __device__ float2 g_zc[2*(size_t)NB];      // conv+mtx packed complex (cos + i sin)
static __device__ float  g_sq[2*(size_t)NB];      // sqrt(mag) crop
static __device__ float2 g_Wf[(size_t)VOL];       // filtered W(k)/256
static __device__ float  g_Mc[128*128];
static __device__ float  g_Ms[128*128];
static __device__ float2 g_tw[128];               // W_256^k, k<128 (forward sign)
static __device__ float  g_sinT[128];             // sin(t), t=0..127

// attention reduction state
static __device__ double g_pD[2][RBLK];
static __device__ float  g_pMnL[2][RBLK], g_pMxL[2][RBLK], g_pMnH[2][RBLK], g_pMxH[2][RBLK];
static __device__ float  g_a1[2], g_c1[2], g_M1f[2], g_Z1i[2];
static __device__ float  g_a2[2], g_c2[2], g_M2f[2], g_Z2i[2];
static __device__ float  g_mnH[2], g_mxH[2];

__device__ __forceinline__ float2 cmul(float2 a, float2 b){
    return make_float2(a.x*b.x - a.y*b.y, a.x*b.y + a.y*b.x);
}
__device__ __forceinline__ float2 cadd(float2 a, float2 b){ return make_float2(a.x+b.x, a.y+b.y); }
__device__ __forceinline__ float2 csub(float2 a, float2 b){ return make_float2(a.x-b.x, a.y-b.y); }
__device__ __forceinline__ int brev7(int i){ return (int)(__brev((unsigned)i) >> 25); }

// ---------------- register FFT-16 machinery ----------------
template<int SGN>
__device__ __forceinline__ float2 twd(const float2* stw, int m){
    m &= 255;
    float2 w = (m < 128) ? stw[m] : make_float2(-stw[m-128].x, -stw[m-128].y);
    if (SGN < 0) w.y = -w.y;
    return w;
}

template<int SGN>
__device__ __forceinline__ void bfly4(float2&a,float2&b,float2&c,float2&d){
    float2 t0=cadd(a,c), t1=csub(a,c), t2=cadd(b,d), t3=csub(b,d);
    float2 it3 = (SGN>0)? make_float2(t3.y,-t3.x) : make_float2(-t3.y,t3.x);
    a=cadd(t0,t2); c=csub(t0,t2);
    b=cadd(t1,it3); d=csub(t1,it3);
}

// 16-pt DFT, natural in / natural out, in registers
template<int SGN>
__device__ __forceinline__ void fft16(float2 r[16], const float2* stw){
    #pragma unroll
    for(int a=0;a<4;a++){
        bfly4<SGN>(r[a], r[a+4], r[a+8], r[a+12]);
        #pragma unroll
        for(int k1=1;k1<4;k1++)
            r[a+4*k1] = cmul(r[a+4*k1], twd<SGN>(stw, 16*a*k1));
    }
    #pragma unroll
    for(int k1=0;k1<4;k1++)
        bfly4<SGN>(r[4*k1], r[4*k1+1], r[4*k1+2], r[4*k1+3]);
    float2 tmp[16];
    #pragma unroll
    for(int i=0;i<16;i++) tmp[((i&3)<<2)|(i>>2)] = r[i];
    #pragma unroll
    for(int i=0;i<16;i++) r[i]=tmp[i];
}

// ---------------- init ----------------
__global__ void k_init_tw(){
    int i = threadIdx.x;
    if (i < 128){
        double a = -2.0*3.14159265358979323846*(double)i/256.0;
        double s, c; sincos(a, &s, &c);
        g_tw[i] = make_float2((float)c, (float)s);
        g_sinT[i] = (float)sin((double)i);
    }
}

// Mc[t][j] = sum_m mtx[t][m] * waveC[j-m+31] (k=63 taps), same for Ms
__global__ void k_build_M(const float* __restrict__ mtx, const float* __restrict__ wave){
    int idx = blockIdx.x*blockDim.x + threadIdx.x;
    if (idx >= 128*128) return;
    int t = idx >> 7, j = idx & 127;
    float ac = 0.f, as = 0.f;
    for (int m = 0; m < 128; m++){
        int tau = j - m + 31;
        if (tau >= 0 && tau < 63){
            float mv = mtx[t*128 + m];
            ac = fmaf(mv, wave[tau],      ac);
            as = fmaf(mv, wave[63 + tau], as);
        }
    }
    g_Mc[idx] = ac; g_Ms[idx] = as;
}

// ---------------- conv+mtx -> packed complex (w-split: 256 blocks) ----------------
__global__ __launch_bounds__(512) void k_conv(const float* __restrict__ feat){
    __shared__ float sx[128*32];
    int bid = blockIdx.x;
    int bd = bid >> 7, r = bid & 127, h = r >> 1, wo = (r & 1)*32;
    const float* src = feat + (size_t)bd*NB + h*64 + wo;
    for (int i = threadIdx.x; i < 128*32; i += 512){
        int t = i >> 5, wl = i & 31;
        sx[i] = src[(size_t)t*4096 + wl];
    }
    __syncthreads();
    float2* dst = g_zc + (size_t)bd*NB + h*64 + wo;
    for (int o = threadIdx.x; o < 128*32; o += 512){
        int t = o >> 5, wl = o & 31;
        float ac = 0.f, as = 0.f;
        const float* mc = g_Mc + t*128;
        const float* ms = g_Ms + t*128;
        #pragma unroll 8
        for (int m = 0; m < 128; m++){
            float xv = sx[m*32 + wl];
            ac = fmaf(mc[m], xv, ac);
            as = fmaf(ms[m], xv, as);
        }
        dst[(size_t)t*4096 + wl] = make_float2(ac, as);
    }
}

// ---------------- forward 2D (H,W) FFT per t-slice, zero-padded 64x64 -> 128x128 --------
__global__ __launch_bounds__(1024) void k_fwd2D(){
    extern __shared__ unsigned char smraw[];
    float2* s   = (float2*)smraw;              // [h*129 + w]
    float2* stw = s + 128*129;
    int tid = threadIdx.x;
    int t = blockIdx.x, bd = blockIdx.y;
    if (tid < 128) stw[tid] = g_tw[tid];
    const float2* src = g_zc + (size_t)bd*NB + (size_t)t*4096;
    // scatter writes ALL (even,even) bitrev cells; copy stages fill odd cols then odd rows,
    // so no zero-fill of smem is needed.
    for (int i = tid; i < 64*64; i += 1024){
        int h = i >> 6, w = i & 63;
        s[brev7(h)*129 + brev7(w)] = src[i];
    }
    __syncthreads();
    for (int j = tid; j < 64*64; j += 1024){
        int row = (j >> 6) << 1, g = j & 63;
        int i0 = row*129 + 2*g;
        s[i0 + 1] = s[i0];
    }
    __syncthreads();
    for (int L = 2; L <= 32; L <<= 2){
        for (int j = tid; j < 64*32; j += 1024){
            int row = (j >> 5) << 1, o = j & 31;
            int grp = o / L, k = o - grp*L;
            int b0 = row*129 + grp*4*L + k;
            float2 A = s[b0], B = s[b0+L], C = s[b0+2*L], D = s[b0+3*L];
            float2 w1 = stw[k*(256/(2*L))];
            float2 w2 = stw[k*(256/(4*L))];
            float2 Bt = cmul(w1,B), Dt = cmul(w1,D);
            float2 A1 = cadd(A,Bt), B1 = csub(A,Bt);
            float2 C1 = cadd(C,Dt), D1 = csub(C,Dt);
            float2 C2 = cmul(w2,C1), D2 = cmul(w2,D1);
            float2 D2m = make_float2(D2.y, -D2.x);
            s[b0]     = cadd(A1,C2);
            s[b0+2*L] = csub(A1,C2);
            s[b0+L]   = cadd(B1,D2m);
            s[b0+3*L] = csub(B1,D2m);
        }
        __syncthreads();
    }
    for (int j = tid; j < 64*128; j += 1024){
        int w = j & 127, g = j >> 7;
        int i0 = (2*g)*129 + w;
        s[i0 + 129] = s[i0];
    }
    __syncthreads();
    for (int L = 2; L <= 32; L <<= 2){
        for (int j = tid; j < 32*128; j += 1024){
            int w = j & 127, o = j >> 7;
            int grp = o / L, k = o - grp*L;
            int r0 = grp*4*L + k;
            float2 A = s[r0*129+w],       B = s[(r0+L)*129+w];
            float2 C = s[(r0+2*L)*129+w], D = s[(r0+3*L)*129+w];
            float2 w1 = stw[k*(256/(2*L))];
            float2 w2 = stw[k*(256/(4*L))];
            float2 Bt = cmul(w1,B), Dt = cmul(w1,D);
            float2 A1 = cadd(A,Bt), B1 = csub(A,Bt);
            float2 C1 = cadd(C,Dt), D1 = csub(C,Dt);
            float2 C2 = cmul(w2,C1), D2 = cmul(w2,D1);
            float2 D2m = make_float2(D2.y, -D2.x);
            s[r0*129+w]       = cadd(A1,C2);
            s[(r0+2*L)*129+w] = csub(A1,C2);
            s[(r0+L)*129+w]   = cadd(B1,D2m);
            s[(r0+3*L)*129+w] = csub(B1,D2m);
        }
        __syncthreads();
    }
    float2* dst = g_bufA + (size_t)bd*VOL + (size_t)t*16384;
    for (int i = tid; i < 128*128; i += 1024)
        dst[i] = s[(i >> 7)*129 + (i & 127)];
}

// ---------------- attention scalar reductions ----------------
__device__ double blockReduceD(double v){
    __shared__ double sh[256];
    sh[threadIdx.x] = v; __syncthreads();
    for (int s = 128; s; s >>= 1){ if (threadIdx.x < s) sh[threadIdx.x] += sh[threadIdx.x + s]; __syncthreads(); }
    double r = sh[0]; __syncthreads(); return r;
}
__device__ float blockReduceMin(float v){
    __shared__ float sh[256];
    sh[threadIdx.x] = v; __syncthreads();
    for (int s = 128; s; s >>= 1){ if (threadIdx.x < s) sh[threadIdx.x] = fminf(sh[threadIdx.x], sh[threadIdx.x + s]); __syncthreads(); }
    float r = sh[0]; __syncthreads(); return r;
}
__device__ float blockReduceMax(float v){
    __shared__ float sh[256];
    sh[threadIdx.x] = v; __syncthreads();
    for (int s = 128; s; s >>= 1){ if (threadIdx.x < s) sh[threadIdx.x] = fmaxf(sh[threadIdx.x], sh[threadIdx.x + s]); __syncthreads(); }
    float r = sh[0]; __syncthreads(); return r;
}

__device__ __forceinline__ void block_elems(const float* K, int j, float& kL, float& kH, float& vL){
    int tl = j >> 12, hl = (j >> 6) & 63, wl = j & 63;
    float pe = g_sinT[tl];
    vL = K[((192 + tl) & 255)*16384 + ((96 + hl) & 127)*128 + ((96 + wl) & 127)];
    float vH = K[(64 + tl)*16384 + (32 + hl)*128 + (32 + wl)];
    kL = vL + pe; kH = vH + pe;
}

__global__ __launch_bounds__(256) void k_redA(const float* __restrict__ invr, const float* __restrict__ invi){
    int f = blockIdx.y;
    const float* K = f ? invi : invr;
    double sum = 0.0;
    float mnL = 3.4e38f, mxL = -3.4e38f, mnH = 3.4e38f, mxH = -3.4e38f;
    for (int j = blockIdx.x*256 + threadIdx.x; j < NB; j += RBLK*256){
        float kL, kH, vL; block_elems(K, j, kL, kH, vL);
        sum += (double)vL;
        mnL = fminf(mnL, kL); mxL = fmaxf(mxL, kL);
        mnH = fminf(mnH, kH); mxH = fmaxf(mxH, kH);
    }
    sum = blockReduceD(sum);
    mnL = blockReduceMin(mnL); mxL = blockReduceMax(mxL);
    mnH = blockReduceMin(mnH); mxH = blockReduceMax(mxH);
    if (threadIdx.x == 0){
        g_pD[f][blockIdx.x] = sum;
        g_pMnL[f][blockIdx.x] = mnL; g_pMxL[f][blockIdx.x] = mxL;
        g_pMnH[f][blockIdx.x] = mnH; g_pMxH[f][blockIdx.x] = mxH;
    }
}

__global__ void k_combA(const float* __restrict__ wp, const float* __restrict__ bp){
    int f = blockIdx.x, i = threadIdx.x;
    __shared__ double sd[256]; __shared__ float s1[256], s2[256], s3[256], s4[256];
    sd[i] = g_pD[f][i] + g_pD[f][i+256];
    s1[i] = fminf(g_pMnL[f][i], g_pMnL[f][i+256]);
    s2[i] = fmaxf(g_pMxL[f][i], g_pMxL[f][i+256]);
    s3[i] = fminf(g_pMnH[f][i], g_pMnH[f][i+256]);
    s4[i] = fmaxf(g_pMxH[f][i], g_pMxH[f][i+256]);
    __syncthreads();
    for (int s = 128; s; s >>= 1){
        if (i < s){
            sd[i] += sd[i+s];
            s1[i] = fminf(s1[i], s1[i+s]); s2[i] = fmaxf(s2[i], s2[i+s]);
            s3[i] = fminf(s3[i], s3[i+s]); s4[i] = fmaxf(s4[i], s4[i+s]);
        }
        __syncthreads();
    }
    if (i == 0){
        float W = *wp, B = *bp;
        float scal1 = W*(float)(sd[0]/(double)NB) + B;
        float a1 = scal1*W, c1 = scal1*B;
        g_a1[f] = a1; g_c1[f] = c1;
        g_M1f[f] = (a1 >= 0.f ? a1*s2[0] : a1*s1[0]) + c1;
        g_mnH[f] = s3[0]; g_mxH[f] = s4[0];
    }
}

__global__ __launch_bounds__(256) void k_redB(const float* __restrict__ invr, const float* __restrict__ invi){
    int f = blockIdx.y; const float* K = f ? invi : invr;
    float a1 = g_a1[f], c1 = g_c1[f], M1 = g_M1f[f];
    double acc = 0.0;
    for (int j = blockIdx.x*256 + threadIdx.x; j < NB; j += RBLK*256){
        float kL, kH, vL; block_elems(K, j, kL, kH, vL);
        acc += (double)__expf(fmaf(a1, kL, c1) - M1);
    }
    acc = blockReduceD(acc);
    if (threadIdx.x == 0) g_pD[f][blockIdx.x] = acc;
}
__global__ void k_combB(){
    int f = blockIdx.x, i = threadIdx.x;
    __shared__ double sd[256];
    sd[i] = g_pD[f][i] + g_pD[f][i+256]; __syncthreads();
    for (int s = 128; s; s >>= 1){ if (i < s) sd[i] += sd[i+s]; __syncthreads(); }
    if (i == 0) g_Z1i[f] = (float)(1.0/sd[0]);
}

__global__ __launch_bounds__(256) void k_redC(const float* __restrict__ invr, const float* __restrict__ invi){
    int f = blockIdx.y; const float* K = f ? invi : invr;
    float a1 = g_a1[f], c1 = g_c1[f], M1 = g_M1f[f], Z1i = g_Z1i[f];
    double acc = 0.0;
    for (int j = blockIdx.x*256 + threadIdx.x; j < NB; j += RBLK*256){
        float kL, kH, vL; block_elems(K, j, kL, kH, vL);
        float sm = __expf(fmaf(a1, kL, c1) - M1) * Z1i;
        acc += (double)(kL / (1.f + __expf(-sm)));
    }
    acc = blockReduceD(acc);
    if (threadIdx.x == 0) g_pD[f][blockIdx.x] = acc;
}
__global__ void k_combC(const float* __restrict__ wp, const float* __restrict__ bp){
    int f = blockIdx.x, i = threadIdx.x;
    __shared__ double sd[256];
    sd[i] = g_pD[f][i] + g_pD[f][i+256]; __syncthreads();
    for (int s = 128; s; s >>= 1){ if (i < s) sd[i] += sd[i+s]; __syncthreads(); }
    if (i == 0){
        float W = *wp, B = *bp;
        float scal2 = W*(float)(sd[0]/(double)NB) + B;
        float a2 = scal2*W, c2 = scal2*B;
        g_a2[f] = a2; g_c2[f] = c2;
        g_M2f[f] = (a2 >= 0.f ? a2*g_mxH[f] : a2*g_mnH[f]) + c2;
    }
}

__global__ __launch_bounds__(256) void k_redD(const float* __restrict__ invr, const float* __restrict__ invi){
    int f = blockIdx.y; const float* K = f ? invi : invr;
    float a2 = g_a2[f], c2 = g_c2[f], M2 = g_M2f[f];
    double acc = 0.0;
    for (int j = blockIdx.x*256 + threadIdx.x; j < NB; j += RBLK*256){
        float kL, kH, vL; block_elems(K, j, kL, kH, vL);
        acc += (double)__expf(fmaf(a2, kH, c2) - M2);
    }
    acc = blockReduceD(acc);
    if (threadIdx.x == 0) g_pD[f][blockIdx.x] = acc;
}
__global__ void k_combD(){
    int f = blockIdx.x, i = threadIdx.x;
    __shared__ double sd[256];
    sd[i] = g_pD[f][i] + g_pD[f][i+256]; __syncthreads();
    for (int s = 128; s; s >>= 1){ if (i < s) sd[i] += sd[i+s]; __syncthreads(); }
    if (i == 0) g_Z2i[f] = (float)(1.0/sd[0]);
}

// ---------------- attention filter (pointwise) ----------------
__device__ __forceinline__ float atten_filter(float v, int t, int h, int w, int f){
    int tl = t - 64, hl = h - 32, wl = w - 32;
    if ((unsigned)tl < 128u && (unsigned)hl < 64u && (unsigned)wl < 64u){
        float k2p = v + g_sinT[tl];
        float sm = __expf(fmaf(g_a2[f], k2p, g_c2[f]) - g_M2f[f]) * g_Z2i[f];
        return k2p / (1.f + __expf(-sm));
    }
    int tl2 = (t + 64) & 255, hl2 = (h + 32) & 127, wl2 = (w + 32) & 127;
    if (tl2 < 128 && hl2 < 64 && wl2 < 64){
        float k2p = v + g_sinT[tl2];
        float sm = __expf(fmaf(g_a1[f], k2p, g_c1[f]) - g_M1f[f]) * g_Z1i[f];
        return k2p / (1.f + __expf(-sm));
    }
    return v;
}

// ---------------- precompute filtered W volume: W(k)/256 (float2) ----------------
__global__ __launch_bounds__(256) void k_filterW(const float* __restrict__ invr, const float* __restrict__ invi){
    int idx = blockIdx.x*256 + threadIdx.x;
    int t = idx >> 14, h = (idx >> 7) & 127, w = idx & 127;
    const float sc = 1.f/256.f;
    float w1 = atten_filter(invr[idx], t, h, w, 0)*sc;
    float w2 = atten_filter(invi[idx], t, h, w, 1)*sc;
    g_Wf[idx] = make_float2(w1, w2);
}

// ---------------- fused T (16x16 four-step, register FFTs) ----------------
// fwd: X = FFT256(Z pad); A = W(k)X -> P ; B = conj(W(-k))X -> R.
__global__ __launch_bounds__(256,2) void k_fusedT(){
    extern __shared__ unsigned char smraw[];
    float2* bufA = (float2*)smraw;           // 16 lanes x 257
    float2* bufB = bufA + 16*257;
    __shared__ float2 stw[128];
    int tid = threadIdx.x, lane = tid & 15, role = tid >> 4;
    if (tid < 128) stw[tid] = g_tw[tid];
    int wb = blockIdx.x << 4, h = blockIdx.y, bd = blockIdx.z;
    int w = wb + lane;

    // load z (t<128; rest zero)
    float2 X[16];
    const float2* ZS = g_bufA + (size_t)bd*VOL + (size_t)h*128 + w;
    #pragma unroll
    for (int j = 0; j < 8; j++) X[j] = ZS[(size_t)(role + 16*j)*16384];
    #pragma unroll
    for (int j = 8; j < 16; j++) X[j] = make_float2(0.f, 0.f);
    __syncthreads();                        // stw ready

    // fwd step1: DFT over n2 (regs), twiddle W256^{n1*k1'}, exchange
    fft16<1>(X, stw);
    int base = lane*257;
    #pragma unroll
    for (int j = 1; j < 16; j++) X[j] = cmul(X[j], twd<1>(stw, role*j));
    #pragma unroll
    for (int j = 0; j < 16; j++) bufA[base + j*16 + role] = X[j];
    __syncthreads();
    // fwd step3: gather over n1, DFT -> S[j] = spectrum at k = role + 16j
    float2 S[16];
    #pragma unroll
    for (int n1 = 0; n1 < 16; n1++) S[n1] = bufA[base + role*16 + n1];
    fft16<1>(S, stw);

    // A path: A = W(k) S, inverse step1, twiddle, exchange
    const float2* WD = g_Wf + (size_t)h*128 + w;
    float2 A[16];
    #pragma unroll
    for (int j = 0; j < 16; j++){
        float2 wd = WD[(size_t)(role + 16*j)*16384];
        A[j] = cmul(wd, S[j]);
    }
    fft16<-1>(A, stw);
    __syncthreads();                        // all bufA reads done before overwrite
    #pragma unroll
    for (int t1 = 0; t1 < 16; t1++)
        bufA[base + t1*16 + role] = cmul(A[t1], twd<-1>(stw, role*t1));

    // B path (reuse A regs): B = conj(W(-k)) S
    int hn = (128 - h) & 127, wn = (128 - w) & 127;
    const float2* WR = g_Wf + (size_t)hn*128 + wn;
    #pragma unroll
    for (int j = 0; j < 16; j++){
        int kn = (256 - (role + 16*j)) & 255;
        float2 wr = WR[(size_t)kn*16384];
        A[j] = cmul(make_float2(wr.x, -wr.y), S[j]);
    }
    fft16<-1>(A, stw);
    #pragma unroll
    for (int t1 = 0; t1 < 16; t1++)
        bufB[base + t1*16 + role] = cmul(A[t1], twd<-1>(stw, role*t1));
    __syncthreads();

    // inverse step3: gather over K, DFT, store crop t<128
    float2* dP = g_bufB + (size_t)(2*bd)*VOL + (size_t)h*128 + w;
    #pragma unroll
    for (int K = 0; K < 16; K++) A[K] = bufA[base + role*16 + K];
    fft16<-1>(A, stw);
    #pragma unroll
    for (int t2 = 0; t2 < 8; t2++) dP[(size_t)(role + 16*t2)*16384] = A[t2];
    #pragma unroll
    for (int K = 0; K < 16; K++) A[K] = bufB[base + role*16 + K];
    fft16<-1>(A, stw);
    #pragma unroll
    for (int t2 = 0; t2 < 8; t2++) dP[(size_t)VOL + (size_t)(role + 16*t2)*16384] = A[t2];
}

// ---------------- inverse 2D (H,W) per t-slice, crop, fused P*conj(R)/mag/sqrt ----------
__global__ __launch_bounds__(1024) void k_inv2D(){
    extern __shared__ unsigned char smraw[];
    float2* s   = (float2*)smraw;              // 128*129
    float2* qd  = s + 128*129;                 // 64*65 (P quadrant stash)
    float2* stw = qd + 64*65;
    int tid = threadIdx.x;
    int t = blockIdx.x, bd = blockIdx.y;
    if (tid < 128){ float2 w = g_tw[tid]; stw[tid] = make_float2(w.x, -w.y); }  // conj
    for (int pass = 0; pass < 2; pass++){
        const float2* src = g_bufB + (size_t)(2*bd + pass)*VOL + (size_t)t*16384;
        __syncthreads();
        for (int i = tid; i < 128*128; i += 1024){
            int h = i >> 7, w = i & 127;
            s[brev7(h)*129 + w] = src[i];
        }
        __syncthreads();
        for (int j = tid; j < 64*128; j += 1024){
            int w = j & 127, g = j >> 7;
            int i0 = (2*g)*129 + w, i1 = i0 + 129;
            float2 a = s[i0], b = s[i1];
            s[i0] = cadd(a,b); s[i1] = csub(a,b);
        }
        __syncthreads();
        for (int L = 2; L <= 32; L <<= 2){
            for (int j = tid; j < 32*128; j += 1024){
                int w = j & 127, o = j >> 7;
                int grp = o / L, k = o - grp*L;
                int r0 = grp*4*L + k;
                float2 A = s[r0*129+w],       B = s[(r0+L)*129+w];
                float2 C = s[(r0+2*L)*129+w], D = s[(r0+3*L)*129+w];
                float2 w1 = stw[k*(256/(2*L))];
                float2 w2 = stw[k*(256/(4*L))];
                float2 Bt = cmul(w1,B), Dt = cmul(w1,D);
                float2 A1 = cadd(A,Bt), B1 = csub(A,Bt);
                float2 C1 = cadd(C,Dt), D1 = csub(C,Dt);
                float2 C2 = cmul(w2,C1), D2 = cmul(w2,D1);
                float2 D2m = make_float2(-D2.y, D2.x);
                s[r0*129+w]       = cadd(A1,C2);
                s[(r0+2*L)*129+w] = csub(A1,C2);
                s[(r0+L)*129+w]   = cadd(B1,D2m);
                s[(r0+3*L)*129+w] = csub(B1,D2m);
            }
            __syncthreads();
        }
        for (int M = 128; M >= 8; M >>= 2){
            int q = M >> 2;
            for (int j = tid; j < 64*32; j += 1024){
                int row = j >> 5, o = j & 31;
                int grp = o / q, k = o - grp*q;
                int b0 = row*129 + grp*M + k;
                float2 A = s[b0], B = s[b0+q], C = s[b0+2*q], D = s[b0+3*q];
                float2 wA = stw[k*(256/M)];
                float2 w2 = stw[(2*k)*(256/M)];
                float2 sAC = cadd(A,C), dAC = csub(A,C);
                float2 sBD = cadd(B,D), dBD = csub(B,D);
                s[b0]   = cadd(sAC, sBD);
                s[b0+q] = cmul(csub(sAC, sBD), w2);
                float2 u2 = make_float2(dAC.x - dBD.y, dAC.y + dBD.x);
                s[b0+2*q] = cmul(u2, wA);
                float2 u3 = make_float2(dAC.x + dBD.y, dAC.y - dBD.x);
                s[b0+3*q] = cmul(u3, cmul(wA, w2));
            }
            __syncthreads();
        }
        for (int j = tid; j < 64*64; j += 1024){
            int row = j >> 6, g = j & 63;
            int i0 = row*129 + 2*g;
            float2 a = s[i0], b = s[i0+1];
            s[i0] = cadd(a,b); s[i0+1] = csub(a,b);
        }
        __syncthreads();
        if (pass == 0){
            for (int i = tid; i < 64*64; i += 1024){
                int h = i >> 6, w = i & 63;
                qd[h*65 + w] = s[h*129 + brev7(w)];
            }
        } else {
            const float S2 = 1.f/268435456.f;   // (1/16384)^2
            float* dst = g_sq + (size_t)bd*NB + (size_t)t*4096;
            for (int i = tid; i < 64*64; i += 1024){
                int h = i >> 6, w = i & 63;
                float2 P = qd[h*65 + w];
                float2 R = s[h*129 + brev7(w)];
                float Sr = (P.x*R.x + P.y*R.y)*S2;     // P * conj(R)
                float Si = (P.y*R.x - P.x*R.y)*S2;
                float mag = fmaxf(0.5f*(sqrtf(Sr*Sr + Si*Si) + Sr), 0.f);
                dst[i] = sqrtf(mag);
            }
        }
    }
}

// ---------------- final mtxi matmul along T (w-split: 256 blocks) ----------------
__global__ __launch_bounds__(512) void k_final(const float* __restrict__ mtxi, float* __restrict__ out){
    __shared__ float sx[128*32];
    int bid = blockIdx.x;
    int bd = bid >> 7, r = bid & 127, h = r >> 1, wo = (r & 1)*32;
    const float* src = g_sq + (size_t)bd*NB + h*64 + wo;
    for (int i = threadIdx.x; i < 128*32; i += 512){
        int t = i >> 5, wl = i & 31;
        sx[i] = src[(size_t)t*4096 + wl];
    }
    __syncthreads();
    float* dst = out + (size_t)bd*NB + h*64 + wo;
    for (int o = threadIdx.x; o < 128*32; o += 512){
        int t = o >> 5, wl = o & 31;
        float acc = 0.f;
        const float* mi = mtxi + t*128;
        #pragma unroll 8
        for (int m = 0; m < 128; m++) acc = fmaf(mi[m], sx[m*32 + wl], acc);
        dst[(size_t)t*4096 + wl] = acc;
    }
}

// ---------------- launch ----------------
#define FWD2D_SMEM (128*129*8 + 128*8)
#define INV2D_SMEM (128*129*8 + 64*65*8 + 128*8)
#define FT_SMEM    (2*16*257*8)

extern "C" void kernel_launch(void* const* d_in, const int* in_sizes, int n_in,
                              void* d_out, int out_size){
    const float *feature = 0, *conv_w = 0, *conv_b = 0, *wave = 0;
    const float *invr = 0, *invi = 0, *mtx = 0, *mtxi = 0;
    int scal_seen = 0, mat_seen = 0, psf_seen = 0;
    for (int i = 0; i < n_in; i++){
        const float* p = (const float*)d_in[i];
        int s = in_sizes[i];
        if      (s == 1)       { if (scal_seen++ == 0) conv_w = p; else conv_b = p; }
        else if (s == 126)     wave = p;
        else if (s == 16384)   { if (mat_seen++ == 0) mtx = p; else mtxi = p; }
        else if (s == 4194304) { if (psf_seen++ == 0) invr = p; else invi = p; }
        else if (s == 1048576) feature = p;
    }
    float* out = (float*)d_out;

    cudaFuncSetAttribute(k_fwd2D,  cudaFuncAttributeMaxDynamicSharedMemorySize, FWD2D_SMEM);
    cudaFuncSetAttribute(k_inv2D,  cudaFuncAttributeMaxDynamicSharedMemorySize, INV2D_SMEM);
    cudaFuncSetAttribute(k_fusedT, cudaFuncAttributeMaxDynamicSharedMemorySize, FT_SMEM);

    k_init_tw<<<1,128>>>();
    k_build_M<<<64,256>>>(mtx, wave);

    // forward path
    k_conv<<<256,512>>>(feature);
    k_fwd2D<<<dim3(128,2),1024,FWD2D_SMEM>>>();

    // attention scalars (4 reduce + 4 combine)
    k_redA<<<dim3(RBLK,2),256>>>(invr, invi);
    k_combA<<<2,256>>>(conv_w, conv_b);
    k_redB<<<dim3(RBLK,2),256>>>(invr, invi);
    k_combB<<<2,256>>>();
    k_redC<<<dim3(RBLK,2),256>>>(invr, invi);
    k_combC<<<2,256>>>(conv_w, conv_b);
    k_redD<<<dim3(RBLK,2),256>>>(invr, invi);
    k_combD<<<2,256>>>();

    // precompute attention-filtered spectrum W(k) once
    k_filterW<<<VOL/256,256>>>(invr, invi);

    // fused: fwd T-FFT + pointwise G1/G2' + two inverse T-FFTs (crop t<128)
    k_fusedT<<<dim3(8,128,2),256,FT_SMEM>>>();

    // inverse 2D per slice with fused P*conj(R), mag, relu, sqrt
    k_inv2D<<<dim3(128,2),1024,INV2D_SMEM>>>();

    k_final<<<256,512>>>(mtxi, out);
}

// round 14
// speedup vs baseline: 2.3336x; 1.1613x over previous
#include <cuda_runtime.h>
#include <math.h>

#define VOL (256*128*128)     /* 4194304 full padded volume */
#define NB  (128*64*64)       /* 524288  crop / attention block */
#define RBLK 512
#define SMP 129               /* smem tile pitch (float2) */

// ---------------- scratch (static device allocations, no runtime alloc) ----------------
static __device__ float2 g_bufA[2*(size_t)VOL];   // Z spectra per bd (t<128 used)
static __device__ float2 g_bufB[4*(size_t)VOL];   // P,R per bd (t<128 used)
static __device__ float2 g_zc[2*(size_t)NB];      // conv+mtx packed complex (cos + i sin)
static __device__ float  g_sq[2*(size_t)NB];      // sqrt(mag) crop
static __device__ float2 g_Wf[(size_t)VOL];       // filtered W(k)/256
static __device__ float  g_Mc[128*128];
static __device__ float  g_Ms[128*128];
static __device__ float2 g_tw[128];               // W_256^k, k<128 (forward sign)
static __device__ float  g_sinT[128];             // sin(t), t=0..127

// attention reduction state
static __device__ double g_pD[2][RBLK];
static __device__ float  g_pMnL[2][RBLK], g_pMxL[2][RBLK], g_pMnH[2][RBLK], g_pMxH[2][RBLK];
static __device__ float  g_a1[2], g_c1[2], g_M1f[2], g_Z1i[2];
static __device__ float  g_a2[2], g_c2[2], g_M2f[2], g_Z2i[2];
static __device__ float  g_mnH[2], g_mxH[2];

__device__ __forceinline__ float2 cmul(float2 a, float2 b){
    return make_float2(a.x*b.x - a.y*b.y, a.x*b.y + a.y*b.x);
}
__device__ __forceinline__ float2 cadd(float2 a, float2 b){ return make_float2(a.x+b.x, a.y+b.y); }
__device__ __forceinline__ float2 csub(float2 a, float2 b){ return make_float2(a.x-b.x, a.y-b.y); }

// ---------------- register FFT machinery ----------------
template<int SGN>
__device__ __forceinline__ float2 twd(const float2* stw, int m){
    m &= 255;
    float2 w = (m < 128) ? stw[m] : make_float2(-stw[m-128].x, -stw[m-128].y);
    if (SGN < 0) w.y = -w.y;
    return w;
}

template<int SGN>
__device__ __forceinline__ void bfly4(float2&a,float2&b,float2&c,float2&d){
    float2 t0=cadd(a,c), t1=csub(a,c), t2=cadd(b,d), t3=csub(b,d);
    float2 it3 = (SGN>0)? make_float2(t3.y,-t3.x) : make_float2(-t3.y,t3.x);
    a=cadd(t0,t2); c=csub(t0,t2);
    b=cadd(t1,it3); d=csub(t1,it3);
}

// 16-pt DFT, natural in / natural out, in registers
template<int SGN>
__device__ __forceinline__ void fft16(float2 r[16], const float2* stw){
    #pragma unroll
    for(int a=0;a<4;a++){
        bfly4<SGN>(r[a], r[a+4], r[a+8], r[a+12]);
        #pragma unroll
        for(int k1=1;k1<4;k1++)
            r[a+4*k1] = cmul(r[a+4*k1], twd<SGN>(stw, 16*a*k1));
    }
    #pragma unroll
    for(int k1=0;k1<4;k1++)
        bfly4<SGN>(r[4*k1], r[4*k1+1], r[4*k1+2], r[4*k1+3]);
    float2 tmp[16];
    #pragma unroll
    for(int i=0;i<16;i++) tmp[((i&3)<<2)|(i>>2)] = r[i];
    #pragma unroll
    for(int i=0;i<16;i++) r[i]=tmp[i];
}

// 8-pt DFT, natural in / natural out, in registers
template<int SGN>
__device__ __forceinline__ void fft8(float2 r[8], const float2* stw){
    #pragma unroll
    for(int a=0;a<4;a++){
        float2 u=r[a], v=r[a+4];
        r[a]=cadd(u,v); r[a+4]=csub(u,v);
    }
    #pragma unroll
    for(int a=1;a<4;a++)
        r[a+4]=cmul(r[a+4], twd<SGN>(stw, 32*a));   // W8^a
    bfly4<SGN>(r[0],r[1],r[2],r[3]);
    bfly4<SGN>(r[4],r[5],r[6],r[7]);
    float2 tmp[8];
    #pragma unroll
    for(int m=0;m<8;m++){ int p=m>>2, q=m&3; tmp[2*q+p]=r[m]; }
    #pragma unroll
    for(int m=0;m<8;m++) r[m]=tmp[m];
}

// ---------------- init ----------------
__global__ void k_init_tw(){
    int i = threadIdx.x;
    if (i < 128){
        double a = -2.0*3.14159265358979323846*(double)i/256.0;
        double s, c; sincos(a, &s, &c);
        g_tw[i] = make_float2((float)c, (float)s);
        g_sinT[i] = (float)sin((double)i);
    }
}

// Mc[t][j] = sum_m mtx[t][m] * waveC[j-m+31] (k=63 taps), same for Ms
__global__ void k_build_M(const float* __restrict__ mtx, const float* __restrict__ wave){
    int idx = blockIdx.x*blockDim.x + threadIdx.x;
    if (idx >= 128*128) return;
    int t = idx >> 7, j = idx & 127;
    float ac = 0.f, as = 0.f;
    for (int m = 0; m < 128; m++){
        int tau = j - m + 31;
        if (tau >= 0 && tau < 63){
            float mv = mtx[t*128 + m];
            ac = fmaf(mv, wave[tau],      ac);
            as = fmaf(mv, wave[63 + tau], as);
        }
    }
    g_Mc[idx] = ac; g_Ms[idx] = as;
}

// ---------------- conv+mtx -> packed complex (w-split: 256 blocks) ----------------
__global__ __launch_bounds__(512) void k_conv(const float* __restrict__ feat){
    __shared__ float sx[128*32];
    int bid = blockIdx.x;
    int bd = bid >> 7, r = bid & 127, h = r >> 1, wo = (r & 1)*32;
    const float* src = feat + (size_t)bd*NB + h*64 + wo;
    for (int i = threadIdx.x; i < 128*32; i += 512){
        int t = i >> 5, wl = i & 31;
        sx[i] = src[(size_t)t*4096 + wl];
    }
    __syncthreads();
    float2* dst = g_zc + (size_t)bd*NB + h*64 + wo;
    for (int o = threadIdx.x; o < 128*32; o += 512){
        int t = o >> 5, wl = o & 31;
        float ac = 0.f, as = 0.f;
        const float* mc = g_Mc + t*128;
        const float* ms = g_Ms + t*128;
        #pragma unroll 8
        for (int m = 0; m < 128; m++){
            float xv = sx[m*32 + wl];
            ac = fmaf(mc[m], xv, ac);
            as = fmaf(ms[m], xv, as);
        }
        dst[(size_t)t*4096 + wl] = make_float2(ac, as);
    }
}

// ---------------- forward 2D (H,W) FFT per t-slice (register four-step) ----------------
// 64x64 zero-padded -> 128x128.  smem: sm[0..64*SMP) = exchange E, sm[64*SMP..) = row buffer S.
__global__ __launch_bounds__(512,1) void k_fwd2D(){
    extern __shared__ float2 sm[];           // 128*SMP
    __shared__ float2 stw[128];
    int tid = threadIdx.x;
    if (tid < 128) stw[tid] = g_tw[tid];
    int t = blockIdx.x, bd = blockIdx.y;
    float2* S = sm + 64*SMP;                 // 64 x SMP region
    const float2* src = g_zc + (size_t)bd*NB + (size_t)t*4096;

    // stage input (coalesced) into S[h][w], w<64
    for (int i = tid; i < 64*64; i += 512){
        int h = i >> 6, w = i & 63;
        S[h*SMP + w] = src[i];
    }
    __syncthreads();

    // phase W: rows h<64, w = n1(+8 threads) + 8*n2(16 regs), n2<8 nonzero
    {
        int h = tid & 63, r = tid >> 6;
        float2 X[16];
        #pragma unroll
        for (int n2 = 0; n2 < 8; n2++) X[n2] = S[h*SMP + r + 8*n2];
        #pragma unroll
        for (int n2 = 8; n2 < 16; n2++) X[n2] = make_float2(0.f,0.f);
        fft16<1>(X, stw);
        #pragma unroll
        for (int k2 = 1; k2 < 16; k2++) X[k2] = cmul(X[k2], twd<1>(stw, 2*r*k2));
        #pragma unroll
        for (int k2 = 0; k2 < 16; k2++) sm[h*SMP + k2*8 + r] = X[k2];
    }
    __syncthreads();
    {   // cross fft8, write full-w rows back into S
        int h = tid & 63, rp = tid >> 6;
        #pragma unroll
        for (int kk = 0; kk < 2; kk++){
            int k2 = 2*rp + kk;
            float2 r8[8];
            #pragma unroll
            for (int n1 = 0; n1 < 8; n1++) r8[n1] = sm[h*SMP + k2*8 + n1];
            fft8<1>(r8, stw);
            #pragma unroll
            for (int k1 = 0; k1 < 8; k1++) S[h*SMP + k2 + 16*k1] = r8[k1];
        }
    }

    // phase H: 128 columns in two groups of 64; h = n1 + 8*n2, n2<8 nonzero
    for (int g = 0; g < 2; g++){
        __syncthreads();
        int cl = tid & 63, r = tid >> 6;
        float2 X[16];
        #pragma unroll
        for (int n2 = 0; n2 < 8; n2++) X[n2] = S[(r + 8*n2)*SMP + g*64 + cl];
        #pragma unroll
        for (int n2 = 8; n2 < 16; n2++) X[n2] = make_float2(0.f,0.f);
        fft16<1>(X, stw);
        #pragma unroll
        for (int k2 = 1; k2 < 16; k2++) X[k2] = cmul(X[k2], twd<1>(stw, 2*r*k2));
        #pragma unroll
        for (int k2 = 0; k2 < 16; k2++) sm[cl*SMP + k2*8 + r] = X[k2];
        __syncthreads();
        float2* dst = g_bufA + (size_t)bd*VOL + (size_t)t*16384 + g*64 + cl;
        #pragma unroll
        for (int kk = 0; kk < 2; kk++){
            int k2 = 2*r + kk;
            float2 r8[8];
            #pragma unroll
            for (int n1 = 0; n1 < 8; n1++) r8[n1] = sm[cl*SMP + k2*8 + n1];
            fft8<1>(r8, stw);
            #pragma unroll
            for (int k1 = 0; k1 < 8; k1++) dst[(size_t)(k2 + 16*k1)*128] = r8[k1];
        }
    }
}

// ---------------- attention scalar reductions ----------------
__device__ double blockReduceD(double v){
    __shared__ double sh[256];
    sh[threadIdx.x] = v; __syncthreads();
    for (int s = 128; s; s >>= 1){ if (threadIdx.x < s) sh[threadIdx.x] += sh[threadIdx.x + s]; __syncthreads(); }
    double r = sh[0]; __syncthreads(); return r;
}
__device__ float blockReduceMin(float v){
    __shared__ float sh[256];
    sh[threadIdx.x] = v; __syncthreads();
    for (int s = 128; s; s >>= 1){ if (threadIdx.x < s) sh[threadIdx.x] = fminf(sh[threadIdx.x], sh[threadIdx.x + s]); __syncthreads(); }
    float r = sh[0]; __syncthreads(); return r;
}
__device__ float blockReduceMax(float v){
    __shared__ float sh[256];
    sh[threadIdx.x] = v; __syncthreads();
    for (int s = 128; s; s >>= 1){ if (threadIdx.x < s) sh[threadIdx.x] = fmaxf(sh[threadIdx.x], sh[threadIdx.x + s]); __syncthreads(); }
    float r = sh[0]; __syncthreads(); return r;
}

__device__ __forceinline__ void block_elems(const float* K, int j, float& kL, float& kH, float& vL){
    int tl = j >> 12, hl = (j >> 6) & 63, wl = j & 63;
    float pe = g_sinT[tl];
    vL = K[((192 + tl) & 255)*16384 + ((96 + hl) & 127)*128 + ((96 + wl) & 127)];
    float vH = K[(64 + tl)*16384 + (32 + hl)*128 + (32 + wl)];
    kL = vL + pe; kH = vH + pe;
}

__global__ __launch_bounds__(256) void k_redA(const float* __restrict__ invr, const float* __restrict__ invi){
    int f = blockIdx.y;
    const float* K = f ? invi : invr;
    double sum = 0.0;
    float mnL = 3.4e38f, mxL = -3.4e38f, mnH = 3.4e38f, mxH = -3.4e38f;
    for (int j = blockIdx.x*256 + threadIdx.x; j < NB; j += RBLK*256){
        float kL, kH, vL; block_elems(K, j, kL, kH, vL);
        sum += (double)vL;
        mnL = fminf(mnL, kL); mxL = fmaxf(mxL, kL);
        mnH = fminf(mnH, kH); mxH = fmaxf(mxH, kH);
    }
    sum = blockReduceD(sum);
    mnL = blockReduceMin(mnL); mxL = blockReduceMax(mxL);
    mnH = blockReduceMin(mnH); mxH = blockReduceMax(mxH);
    if (threadIdx.x == 0){
        g_pD[f][blockIdx.x] = sum;
        g_pMnL[f][blockIdx.x] = mnL; g_pMxL[f][blockIdx.x] = mxL;
        g_pMnH[f][blockIdx.x] = mnH; g_pMxH[f][blockIdx.x] = mxH;
    }
}

__global__ void k_combA(const float* __restrict__ wp, const float* __restrict__ bp){
    int f = blockIdx.x, i = threadIdx.x;
    __shared__ double sd[256]; __shared__ float s1[256], s2[256], s3[256], s4[256];
    sd[i] = g_pD[f][i] + g_pD[f][i+256];
    s1[i] = fminf(g_pMnL[f][i], g_pMnL[f][i+256]);
    s2[i] = fmaxf(g_pMxL[f][i], g_pMxL[f][i+256]);
    s3[i] = fminf(g_pMnH[f][i], g_pMnH[f][i+256]);
    s4[i] = fmaxf(g_pMxH[f][i], g_pMxH[f][i+256]);
    __syncthreads();
    for (int s = 128; s; s >>= 1){
        if (i < s){
            sd[i] += sd[i+s];
            s1[i] = fminf(s1[i], s1[i+s]); s2[i] = fmaxf(s2[i], s2[i+s]);
            s3[i] = fminf(s3[i], s3[i+s]); s4[i] = fmaxf(s4[i], s4[i+s]);
        }
        __syncthreads();
    }
    if (i == 0){
        float W = *wp, B = *bp;
        float scal1 = W*(float)(sd[0]/(double)NB) + B;
        float a1 = scal1*W, c1 = scal1*B;
        g_a1[f] = a1; g_c1[f] = c1;
        g_M1f[f] = (a1 >= 0.f ? a1*s2[0] : a1*s1[0]) + c1;
        g_mnH[f] = s3[0]; g_mxH[f] = s4[0];
    }
}

__global__ __launch_bounds__(256) void k_redB(const float* __restrict__ invr, const float* __restrict__ invi){
    int f = blockIdx.y; const float* K = f ? invi : invr;
    float a1 = g_a1[f], c1 = g_c1[f], M1 = g_M1f[f];
    double acc = 0.0;
    for (int j = blockIdx.x*256 + threadIdx.x; j < NB; j += RBLK*256){
        float kL, kH, vL; block_elems(K, j, kL, kH, vL);
        acc += (double)__expf(fmaf(a1, kL, c1) - M1);
    }
    acc = blockReduceD(acc);
    if (threadIdx.x == 0) g_pD[f][blockIdx.x] = acc;
}
__global__ void k_combB(){
    int f = blockIdx.x, i = threadIdx.x;
    __shared__ double sd[256];
    sd[i] = g_pD[f][i] + g_pD[f][i+256]; __syncthreads();
    for (int s = 128; s; s >>= 1){ if (i < s) sd[i] += sd[i+s]; __syncthreads(); }
    if (i == 0) g_Z1i[f] = (float)(1.0/sd[0]);
}

__global__ __launch_bounds__(256) void k_redC(const float* __restrict__ invr, const float* __restrict__ invi){
    int f = blockIdx.y; const float* K = f ? invi : invr;
    float a1 = g_a1[f], c1 = g_c1[f], M1 = g_M1f[f], Z1i = g_Z1i[f];
    double acc = 0.0;
    for (int j = blockIdx.x*256 + threadIdx.x; j < NB; j += RBLK*256){
        float kL, kH, vL; block_elems(K, j, kL, kH, vL);
        float sm = __expf(fmaf(a1, kL, c1) - M1) * Z1i;
        acc += (double)(kL / (1.f + __expf(-sm)));
    }
    acc = blockReduceD(acc);
    if (threadIdx.x == 0) g_pD[f][blockIdx.x] = acc;
}
__global__ void k_combC(const float* __restrict__ wp, const float* __restrict__ bp){
    int f = blockIdx.x, i = threadIdx.x;
    __shared__ double sd[256];
    sd[i] = g_pD[f][i] + g_pD[f][i+256]; __syncthreads();
    for (int s = 128; s; s >>= 1){ if (i < s) sd[i] += sd[i+s]; __syncthreads(); }
    if (i == 0){
        float W = *wp, B = *bp;
        float scal2 = W*(float)(sd[0]/(double)NB) + B;
        float a2 = scal2*W, c2 = scal2*B;
        g_a2[f] = a2; g_c2[f] = c2;
        g_M2f[f] = (a2 >= 0.f ? a2*g_mxH[f] : a2*g_mnH[f]) + c2;
    }
}

__global__ __launch_bounds__(256) void k_redD(const float* __restrict__ invr, const float* __restrict__ invi){
    int f = blockIdx.y; const float* K = f ? invi : invr;
    float a2 = g_a2[f], c2 = g_c2[f], M2 = g_M2f[f];
    double acc = 0.0;
    for (int j = blockIdx.x*256 + threadIdx.x; j < NB; j += RBLK*256){
        float kL, kH, vL; block_elems(K, j, kL, kH, vL);
        acc += (double)__expf(fmaf(a2, kH, c2) - M2);
    }
    acc = blockReduceD(acc);
    if (threadIdx.x == 0) g_pD[f][blockIdx.x] = acc;
}
__global__ void k_combD(){
    int f = blockIdx.x, i = threadIdx.x;
    __shared__ double sd[256];
    sd[i] = g_pD[f][i] + g_pD[f][i+256]; __syncthreads();
    for (int s = 128; s; s >>= 1){ if (i < s) sd[i] += sd[i+s]; __syncthreads(); }
    if (i == 0) g_Z2i[f] = (float)(1.0/sd[0]);
}

// ---------------- attention filter (pointwise) ----------------
__device__ __forceinline__ float atten_filter(float v, int t, int h, int w, int f){
    int tl = t - 64, hl = h - 32, wl = w - 32;
    if ((unsigned)tl < 128u && (unsigned)hl < 64u && (unsigned)wl < 64u){
        float k2p = v + g_sinT[tl];
        float sm = __expf(fmaf(g_a2[f], k2p, g_c2[f]) - g_M2f[f]) * g_Z2i[f];
        return k2p / (1.f + __expf(-sm));
    }
    int tl2 = (t + 64) & 255, hl2 = (h + 32) & 127, wl2 = (w + 32) & 127;
    if (tl2 < 128 && hl2 < 64 && wl2 < 64){
        float k2p = v + g_sinT[tl2];
        float sm = __expf(fmaf(g_a1[f], k2p, g_c1[f]) - g_M1f[f]) * g_Z1i[f];
        return k2p / (1.f + __expf(-sm));
    }
    return v;
}

// ---------------- precompute filtered W volume: W(k)/256 (float2) ----------------
__global__ __launch_bounds__(256) void k_filterW(const float* __restrict__ invr, const float* __restrict__ invi){
    int idx = blockIdx.x*256 + threadIdx.x;
    int t = idx >> 14, h = (idx >> 7) & 127, w = idx & 127;
    const float sc = 1.f/256.f;
    float w1 = atten_filter(invr[idx], t, h, w, 0)*sc;
    float w2 = atten_filter(invi[idx], t, h, w, 1)*sc;
    g_Wf[idx] = make_float2(w1, w2);
}

// ---------------- fused T (16x16 four-step, register FFTs) ----------------
__global__ __launch_bounds__(256,2) void k_fusedT(){
    extern __shared__ unsigned char smraw[];
    float2* bufA = (float2*)smraw;           // 16 lanes x 257
    float2* bufB = bufA + 16*257;
    __shared__ float2 stw[128];
    int tid = threadIdx.x, lane = tid & 15, role = tid >> 4;
    if (tid < 128) stw[tid] = g_tw[tid];
    int wb = blockIdx.x << 4, h = blockIdx.y, bd = blockIdx.z;
    int w = wb + lane;

    float2 X[16];
    const float2* ZS = g_bufA + (size_t)bd*VOL + (size_t)h*128 + w;
    #pragma unroll
    for (int j = 0; j < 8; j++) X[j] = ZS[(size_t)(role + 16*j)*16384];
    #pragma unroll
    for (int j = 8; j < 16; j++) X[j] = make_float2(0.f, 0.f);
    __syncthreads();

    fft16<1>(X, stw);
    int base = lane*257;
    #pragma unroll
    for (int j = 1; j < 16; j++) X[j] = cmul(X[j], twd<1>(stw, role*j));
    #pragma unroll
    for (int j = 0; j < 16; j++) bufA[base + j*16 + role] = X[j];
    __syncthreads();
    float2 S[16];
    #pragma unroll
    for (int n1 = 0; n1 < 16; n1++) S[n1] = bufA[base + role*16 + n1];
    fft16<1>(S, stw);

    const float2* WD = g_Wf + (size_t)h*128 + w;
    float2 A[16];
    #pragma unroll
    for (int j = 0; j < 16; j++){
        float2 wd = WD[(size_t)(role + 16*j)*16384];
        A[j] = cmul(wd, S[j]);
    }
    fft16<-1>(A, stw);
    __syncthreads();
    #pragma unroll
    for (int t1 = 0; t1 < 16; t1++)
        bufA[base + t1*16 + role] = cmul(A[t1], twd<-1>(stw, role*t1));

    int hn = (128 - h) & 127, wn = (128 - w) & 127;
    const float2* WR = g_Wf + (size_t)hn*128 + wn;
    #pragma unroll
    for (int j = 0; j < 16; j++){
        int kn = (256 - (role + 16*j)) & 255;
        float2 wr = WR[(size_t)kn*16384];
        A[j] = cmul(make_float2(wr.x, -wr.y), S[j]);
    }
    fft16<-1>(A, stw);
    #pragma unroll
    for (int t1 = 0; t1 < 16; t1++)
        bufB[base + t1*16 + role] = cmul(A[t1], twd<-1>(stw, role*t1));
    __syncthreads();

    float2* dP = g_bufB + (size_t)(2*bd)*VOL + (size_t)h*128 + w;
    #pragma unroll
    for (int K = 0; K < 16; K++) A[K] = bufA[base + role*16 + K];
    fft16<-1>(A, stw);
    #pragma unroll
    for (int t2 = 0; t2 < 8; t2++) dP[(size_t)(role + 16*t2)*16384] = A[t2];
    #pragma unroll
    for (int K = 0; K < 16; K++) A[K] = bufB[base + role*16 + K];
    fft16<-1>(A, stw);
    #pragma unroll
    for (int t2 = 0; t2 < 8; t2++) dP[(size_t)VOL + (size_t)(role + 16*t2)*16384] = A[t2];
}

// ---------------- inverse 2D (H,W) per t-slice (register four-step) -----------------
// crop h<64,w<64; fused P*conj(R)/mag/sqrt with P-quadrant stash in smem.
__global__ __launch_bounds__(512,1) void k_inv2D(){
    extern __shared__ float2 sm[];           // 128*SMP: rows 0..63 = exchange E, 64..127 = O
    __shared__ float2 stw[128];
    __shared__ float2 qd[64*65];
    int tid = threadIdx.x;
    if (tid < 128){ stw[tid] = g_tw[tid]; }
    int t = blockIdx.x, bd = blockIdx.y;
    float2* O = sm + 64*SMP;

    for (int pass = 0; pass < 2; pass++){
        const float2* src = g_bufB + (size_t)(2*bd + pass)*VOL + (size_t)t*16384;
        // phase H: inverse FFT over h for 128 cols (2 groups), keep h<64 into O
        for (int g = 0; g < 2; g++){
            __syncthreads();
            int cl = tid & 63, r = tid >> 6;
            float2 X[16];
            #pragma unroll
            for (int n2 = 0; n2 < 16; n2++) X[n2] = src[(size_t)(r + 8*n2)*128 + g*64 + cl];
            fft16<-1>(X, stw);
            #pragma unroll
            for (int k2 = 1; k2 < 16; k2++) X[k2] = cmul(X[k2], twd<-1>(stw, 2*r*k2));
            #pragma unroll
            for (int k2 = 0; k2 < 16; k2++) sm[cl*SMP + k2*8 + r] = X[k2];
            __syncthreads();
            #pragma unroll
            for (int kk = 0; kk < 2; kk++){
                int k2 = 2*r + kk;
                float2 r8[8];
                #pragma unroll
                for (int n1 = 0; n1 < 8; n1++) r8[n1] = sm[cl*SMP + k2*8 + n1];
                fft8<-1>(r8, stw);
                #pragma unroll
                for (int k1 = 0; k1 < 4; k1++) O[(k2 + 16*k1)*SMP + g*64 + cl] = r8[k1];
            }
        }
        __syncthreads();
        // phase W: inverse FFT over w for 64 rows, keep w<64
        {
            int h = tid & 63, r = tid >> 6;
            float2 X[16];
            #pragma unroll
            for (int n2 = 0; n2 < 16; n2++) X[n2] = O[h*SMP + r + 8*n2];
            fft16<-1>(X, stw);
            #pragma unroll
            for (int k2 = 1; k2 < 16; k2++) X[k2] = cmul(X[k2], twd<-1>(stw, 2*r*k2));
            #pragma unroll
            for (int k2 = 0; k2 < 16; k2++) sm[h*SMP + k2*8 + r] = X[k2];
        }
        __syncthreads();
        {
            int h = tid & 63, r = tid >> 6;
            float* fq = (float*)O;          // O region free after the sync above
            #pragma unroll
            for (int kk = 0; kk < 2; kk++){
                int k2 = 2*r + kk;
                float2 r8[8];
                #pragma unroll
                for (int n1 = 0; n1 < 8; n1++) r8[n1] = sm[h*SMP + k2*8 + n1];
                fft8<-1>(r8, stw);
                if (pass == 0){
                    #pragma unroll
                    for (int k1 = 0; k1 < 4; k1++)
                        qd[h*65 + k2 + 16*k1] = r8[k1];
                } else {
                    const float S2 = 1.f/268435456.f;   // (1/16384)^2
                    #pragma unroll
                    for (int k1 = 0; k1 < 4; k1++){
                        int w = k2 + 16*k1;
                        float2 P = qd[h*65 + w];
                        float2 R = r8[k1];
                        float Sr = (P.x*R.x + P.y*R.y)*S2;
                        float Si = (P.y*R.x - P.x*R.y)*S2;
                        float mag = fmaxf(0.5f*(sqrtf(Sr*Sr + Si*Si) + Sr), 0.f);
                        fq[h*65 + w] = sqrtf(mag);
                    }
                }
            }
        }
        if (pass == 1){
            __syncthreads();
            const float* fq = (const float*)O;
            float* dst = g_sq + (size_t)bd*NB + (size_t)t*4096;
            for (int i = tid; i < 4096; i += 512)
                dst[i] = fq[(i >> 6)*65 + (i & 63)];
        }
    }
}

// ---------------- final mtxi matmul along T (w-split: 256 blocks) ----------------
__global__ __launch_bounds__(512) void k_final(const float* __restrict__ mtxi, float* __restrict__ out){
    __shared__ float sx[128*32];
    int bid = blockIdx.x;
    int bd = bid >> 7, r = bid & 127, h = r >> 1, wo = (r & 1)*32;
    const float* src = g_sq + (size_t)bd*NB + h*64 + wo;
    for (int i = threadIdx.x; i < 128*32; i += 512){
        int t = i >> 5, wl = i & 31;
        sx[i] = src[(size_t)t*4096 + wl];
    }
    __syncthreads();
    float* dst = out + (size_t)bd*NB + h*64 + wo;
    for (int o = threadIdx.x; o < 128*32; o += 512){
        int t = o >> 5, wl = o & 31;
        float acc = 0.f;
        const float* mi = mtxi + t*128;
        #pragma unroll 8
        for (int m = 0; m < 128; m++) acc = fmaf(mi[m], sx[m*32 + wl], acc);
        dst[(size_t)t*4096 + wl] = acc;
    }
}

// ---------------- launch ----------------
#define TILE_SMEM (128*SMP*8)
#define FT_SMEM   (2*16*257*8)

extern "C" void kernel_launch(void* const* d_in, const int* in_sizes, int n_in,
                              void* d_out, int out_size){
    const float *feature = 0, *conv_w = 0, *conv_b = 0, *wave = 0;
    const float *invr = 0, *invi = 0, *mtx = 0, *mtxi = 0;
    int scal_seen = 0, mat_seen = 0, psf_seen = 0;
    for (int i = 0; i < n_in; i++){
        const float* p = (const float*)d_in[i];
        int s = in_sizes[i];
        if      (s == 1)       { if (scal_seen++ == 0) conv_w = p; else conv_b = p; }
        else if (s == 126)     wave = p;
        else if (s == 16384)   { if (mat_seen++ == 0) mtx = p; else mtxi = p; }
        else if (s == 4194304) { if (psf_seen++ == 0) invr = p; else invi = p; }
        else if (s == 1048576) feature = p;
    }
    float* out = (float*)d_out;

    cudaFuncSetAttribute(k_fwd2D,  cudaFuncAttributeMaxDynamicSharedMemorySize, TILE_SMEM);
    cudaFuncSetAttribute(k_inv2D,  cudaFuncAttributeMaxDynamicSharedMemorySize, TILE_SMEM);
    cudaFuncSetAttribute(k_fusedT, cudaFuncAttributeMaxDynamicSharedMemorySize, FT_SMEM);

    k_init_tw<<<1,128>>>();
    k_build_M<<<64,256>>>(mtx, wave);

    // forward path
    k_conv<<<256,512>>>(feature);
    k_fwd2D<<<dim3(128,2),512,TILE_SMEM>>>();

    // attention scalars (4 reduce + 4 combine)
    k_redA<<<dim3(RBLK,2),256>>>(invr, invi);
    k_combA<<<2,256>>>(conv_w, conv_b);
    k_redB<<<dim3(RBLK,2),256>>>(invr, invi);
    k_combB<<<2,256>>>();
    k_redC<<<dim3(RBLK,2),256>>>(invr, invi);
    k_combC<<<2,256>>>(conv_w, conv_b);
    k_redD<<<dim3(RBLK,2),256>>>(invr, invi);
    k_combD<<<2,256>>>();

    // precompute attention-filtered spectrum W(k) once
    k_filterW<<<VOL/256,256>>>(invr, invi);

    // fused: fwd T-FFT + pointwise G1/G2' + two inverse T-FFTs (crop t<128)
    k_fusedT<<<dim3(8,128,2),256,FT_SMEM>>>();

    // inverse 2D per slice with fused P*conj(R), mag, relu, sqrt
    k_inv2D<<<dim3(128,2),512,TILE_SMEM>>>();

    k_final<<<256,512>>>(mtxi, out);
}

// round 15
// speedup vs baseline: 2.6529x; 1.1368x over previous
#include <cuda_runtime.h>
#include <math.h>

#define VOL (256*128*128)     /* 4194304 full padded volume */
#define NB  (128*64*64)       /* 524288  crop / attention block */
#define RBLK 512
#define SMP 129               /* smem tile pitch (float2) */

// ---------------- scratch (static device allocations, no runtime alloc) ----------------
static __device__ float2 g_bufA[2*(size_t)VOL];   // Z spectra per bd (t<128 used)
static __device__ float2 g_bufB[4*(size_t)VOL];   // P,R per bd (t<128 used)
static __device__ float2 g_zc[2*(size_t)NB];      // conv+mtx packed complex (cos + i sin)
static __device__ float  g_sq[2*(size_t)NB];      // sqrt(mag) crop
static __device__ float2 g_Wf[(size_t)VOL];       // filtered W(k)/256
static __device__ float  g_Mc[128*128];
static __device__ float  g_Ms[128*128];
static __device__ float2 g_tw[128];               // W_256^k, k<128 (forward sign)
static __device__ float  g_sinT[128];             // sin(t), t=0..127

// attention reduction state
static __device__ double g_pD[2][RBLK];
static __device__ float  g_pMnL[2][RBLK], g_pMxL[2][RBLK], g_pMnH[2][RBLK], g_pMxH[2][RBLK];
static __device__ float  g_a1[2], g_c1[2], g_M1f[2], g_Z1i[2];
static __device__ float  g_a2[2], g_c2[2], g_M2f[2], g_Z2i[2];
static __device__ float  g_mnH[2], g_mxH[2];

__device__ __forceinline__ float2 cmul(float2 a, float2 b){
    return make_float2(a.x*b.x - a.y*b.y, a.x*b.y + a.y*b.x);
}
__device__ __forceinline__ float2 cadd(float2 a, float2 b){ return make_float2(a.x+b.x, a.y+b.y); }
__device__ __forceinline__ float2 csub(float2 a, float2 b){ return make_float2(a.x-b.x, a.y-b.y); }

// ---------------- register FFT machinery ----------------
template<int SGN>
__device__ __forceinline__ float2 twd(const float2* stw, int m){
    m &= 255;
    float2 w = (m < 128) ? stw[m] : make_float2(-stw[m-128].x, -stw[m-128].y);
    if (SGN < 0) w.y = -w.y;
    return w;
}

template<int SGN>
__device__ __forceinline__ void bfly4(float2&a,float2&b,float2&c,float2&d){
    float2 t0=cadd(a,c), t1=csub(a,c), t2=cadd(b,d), t3=csub(b,d);
    float2 it3 = (SGN>0)? make_float2(t3.y,-t3.x) : make_float2(-t3.y,t3.x);
    a=cadd(t0,t2); c=csub(t0,t2);
    b=cadd(t1,it3); d=csub(t1,it3);
}

// 16-pt DFT, natural in / natural out, in registers
template<int SGN>
__device__ __forceinline__ void fft16(float2 r[16], const float2* stw){
    #pragma unroll
    for(int a=0;a<4;a++){
        bfly4<SGN>(r[a], r[a+4], r[a+8], r[a+12]);
        #pragma unroll
        for(int k1=1;k1<4;k1++)
            r[a+4*k1] = cmul(r[a+4*k1], twd<SGN>(stw, 16*a*k1));
    }
    #pragma unroll
    for(int k1=0;k1<4;k1++)
        bfly4<SGN>(r[4*k1], r[4*k1+1], r[4*k1+2], r[4*k1+3]);
    float2 tmp[16];
    #pragma unroll
    for(int i=0;i<16;i++) tmp[((i&3)<<2)|(i>>2)] = r[i];
    #pragma unroll
    for(int i=0;i<16;i++) r[i]=tmp[i];
}

// 8-pt DFT, natural in / natural out, in registers
template<int SGN>
__device__ __forceinline__ void fft8(float2 r[8], const float2* stw){
    #pragma unroll
    for(int a=0;a<4;a++){
        float2 u=r[a], v=r[a+4];
        r[a]=cadd(u,v); r[a+4]=csub(u,v);
    }
    #pragma unroll
    for(int a=1;a<4;a++)
        r[a+4]=cmul(r[a+4], twd<SGN>(stw, 32*a));   // W8^a
    bfly4<SGN>(r[0],r[1],r[2],r[3]);
    bfly4<SGN>(r[4],r[5],r[6],r[7]);
    float2 tmp[8];
    #pragma unroll
    for(int m=0;m<8;m++){ int p=m>>2, q=m&3; tmp[2*q+p]=r[m]; }
    #pragma unroll
    for(int m=0;m<8;m++) r[m]=tmp[m];
}

// ---------------- init ----------------
__global__ void k_init_tw(){
    int i = threadIdx.x;
    if (i < 128){
        double a = -2.0*3.14159265358979323846*(double)i/256.0;
        double s, c; sincos(a, &s, &c);
        g_tw[i] = make_float2((float)c, (float)s);
        g_sinT[i] = (float)sin((double)i);
    }
}

// Mc[t][j] = sum_m mtx[t][m] * waveC[j-m+31] (k=63 taps), same for Ms
__global__ void k_build_M(const float* __restrict__ mtx, const float* __restrict__ wave){
    int idx = blockIdx.x*blockDim.x + threadIdx.x;
    if (idx >= 128*128) return;
    int t = idx >> 7, j = idx & 127;
    float ac = 0.f, as = 0.f;
    for (int m = 0; m < 128; m++){
        int tau = j - m + 31;
        if (tau >= 0 && tau < 63){
            float mv = mtx[t*128 + m];
            ac = fmaf(mv, wave[tau],      ac);
            as = fmaf(mv, wave[63 + tau], as);
        }
    }
    g_Mc[idx] = ac; g_Ms[idx] = as;
}

// ---------------- conv+mtx -> packed complex (w-split: 256 blocks) ----------------
__global__ __launch_bounds__(512) void k_conv(const float* __restrict__ feat){
    __shared__ float sx[128*32];
    int bid = blockIdx.x;
    int bd = bid >> 7, r = bid & 127, h = r >> 1, wo = (r & 1)*32;
    const float* src = feat + (size_t)bd*NB + h*64 + wo;
    for (int i = threadIdx.x; i < 128*32; i += 512){
        int t = i >> 5, wl = i & 31;
        sx[i] = src[(size_t)t*4096 + wl];
    }
    __syncthreads();
    float2* dst = g_zc + (size_t)bd*NB + h*64 + wo;
    for (int o = threadIdx.x; o < 128*32; o += 512){
        int t = o >> 5, wl = o & 31;
        float ac = 0.f, as = 0.f;
        const float* mc = g_Mc + t*128;
        const float* ms = g_Ms + t*128;
        #pragma unroll 8
        for (int m = 0; m < 128; m++){
            float xv = sx[m*32 + wl];
            ac = fmaf(mc[m], xv, ac);
            as = fmaf(ms[m], xv, as);
        }
        dst[(size_t)t*4096 + wl] = make_float2(ac, as);
    }
}

// ---------------- forward 2D (H,W) FFT per t-slice (register four-step) ----------------
__global__ __launch_bounds__(512,1) void k_fwd2D(){
    extern __shared__ float2 sm[];           // 128*SMP
    __shared__ float2 stw[128];
    int tid = threadIdx.x;
    if (tid < 128) stw[tid] = g_tw[tid];
    int t = blockIdx.x, bd = blockIdx.y;
    float2* S = sm + 64*SMP;                 // 64 x SMP region
    const float2* src = g_zc + (size_t)bd*NB + (size_t)t*4096;

    for (int i = tid; i < 64*64; i += 512){
        int h = i >> 6, w = i & 63;
        S[h*SMP + w] = src[i];
    }
    __syncthreads();

    // phase W
    {
        int h = tid & 63, r = tid >> 6;
        float2 X[16];
        #pragma unroll
        for (int n2 = 0; n2 < 8; n2++) X[n2] = S[h*SMP + r + 8*n2];
        #pragma unroll
        for (int n2 = 8; n2 < 16; n2++) X[n2] = make_float2(0.f,0.f);
        fft16<1>(X, stw);
        #pragma unroll
        for (int k2 = 1; k2 < 16; k2++) X[k2] = cmul(X[k2], twd<1>(stw, 2*r*k2));
        #pragma unroll
        for (int k2 = 0; k2 < 16; k2++) sm[h*SMP + k2*8 + r] = X[k2];
    }
    __syncthreads();
    {
        int h = tid & 63, rp = tid >> 6;
        #pragma unroll
        for (int kk = 0; kk < 2; kk++){
            int k2 = 2*rp + kk;
            float2 r8[8];
            #pragma unroll
            for (int n1 = 0; n1 < 8; n1++) r8[n1] = sm[h*SMP + k2*8 + n1];
            fft8<1>(r8, stw);
            #pragma unroll
            for (int k1 = 0; k1 < 8; k1++) S[h*SMP + k2 + 16*k1] = r8[k1];
        }
    }

    // phase H: 128 columns in two groups of 64
    for (int g = 0; g < 2; g++){
        __syncthreads();
        int cl = tid & 63, r = tid >> 6;
        float2 X[16];
        #pragma unroll
        for (int n2 = 0; n2 < 8; n2++) X[n2] = S[(r + 8*n2)*SMP + g*64 + cl];
        #pragma unroll
        for (int n2 = 8; n2 < 16; n2++) X[n2] = make_float2(0.f,0.f);
        fft16<1>(X, stw);
        #pragma unroll
        for (int k2 = 1; k2 < 16; k2++) X[k2] = cmul(X[k2], twd<1>(stw, 2*r*k2));
        #pragma unroll
        for (int k2 = 0; k2 < 16; k2++) sm[cl*SMP + k2*8 + r] = X[k2];
        __syncthreads();
        float2* dst = g_bufA + (size_t)bd*VOL + (size_t)t*16384 + g*64 + cl;
        #pragma unroll
        for (int kk = 0; kk < 2; kk++){
            int k2 = 2*r + kk;
            float2 r8[8];
            #pragma unroll
            for (int n1 = 0; n1 < 8; n1++) r8[n1] = sm[cl*SMP + k2*8 + n1];
            fft8<1>(r8, stw);
            #pragma unroll
            for (int k1 = 0; k1 < 8; k1++) dst[(size_t)(k2 + 16*k1)*128] = r8[k1];
        }
    }
}

// ---------------- attention scalar reductions ----------------
__device__ double blockReduceD(double v){
    __shared__ double sh[256];
    sh[threadIdx.x] = v; __syncthreads();
    for (int s = 128; s; s >>= 1){ if (threadIdx.x < s) sh[threadIdx.x] += sh[threadIdx.x + s]; __syncthreads(); }
    double r = sh[0]; __syncthreads(); return r;
}
__device__ float blockReduceMin(float v){
    __shared__ float sh[256];
    sh[threadIdx.x] = v; __syncthreads();
    for (int s = 128; s; s >>= 1){ if (threadIdx.x < s) sh[threadIdx.x] = fminf(sh[threadIdx.x], sh[threadIdx.x + s]); __syncthreads(); }
    float r = sh[0]; __syncthreads(); return r;
}
__device__ float blockReduceMax(float v){
    __shared__ float sh[256];
    sh[threadIdx.x] = v; __syncthreads();
    for (int s = 128; s; s >>= 1){ if (threadIdx.x < s) sh[threadIdx.x] = fmaxf(sh[threadIdx.x], sh[threadIdx.x + s]); __syncthreads(); }
    float r = sh[0]; __syncthreads(); return r;
}

__device__ __forceinline__ void block_elems(const float* K, int j, float& kL, float& kH, float& vL){
    int tl = j >> 12, hl = (j >> 6) & 63, wl = j & 63;
    float pe = g_sinT[tl];
    vL = K[((192 + tl) & 255)*16384 + ((96 + hl) & 127)*128 + ((96 + wl) & 127)];
    float vH = K[(64 + tl)*16384 + (32 + hl)*128 + (32 + wl)];
    kL = vL + pe; kH = vH + pe;
}

__global__ __launch_bounds__(256) void k_redA(const float* __restrict__ invr, const float* __restrict__ invi){
    int f = blockIdx.y;
    const float* K = f ? invi : invr;
    double sum = 0.0;
    float mnL = 3.4e38f, mxL = -3.4e38f, mnH = 3.4e38f, mxH = -3.4e38f;
    for (int j = blockIdx.x*256 + threadIdx.x; j < NB; j += RBLK*256){
        float kL, kH, vL; block_elems(K, j, kL, kH, vL);
        sum += (double)vL;
        mnL = fminf(mnL, kL); mxL = fmaxf(mxL, kL);
        mnH = fminf(mnH, kH); mxH = fmaxf(mxH, kH);
    }
    sum = blockReduceD(sum);
    mnL = blockReduceMin(mnL); mxL = blockReduceMax(mxL);
    mnH = blockReduceMin(mnH); mxH = blockReduceMax(mxH);
    if (threadIdx.x == 0){
        g_pD[f][blockIdx.x] = sum;
        g_pMnL[f][blockIdx.x] = mnL; g_pMxL[f][blockIdx.x] = mxL;
        g_pMnH[f][blockIdx.x] = mnH; g_pMxH[f][blockIdx.x] = mxH;
    }
}

__global__ void k_combA(const float* __restrict__ wp, const float* __restrict__ bp){
    int f = blockIdx.x, i = threadIdx.x;
    __shared__ double sd[256]; __shared__ float s1[256], s2[256], s3[256], s4[256];
    sd[i] = g_pD[f][i] + g_pD[f][i+256];
    s1[i] = fminf(g_pMnL[f][i], g_pMnL[f][i+256]);
    s2[i] = fmaxf(g_pMxL[f][i], g_pMxL[f][i+256]);
    s3[i] = fminf(g_pMnH[f][i], g_pMnH[f][i+256]);
    s4[i] = fmaxf(g_pMxH[f][i], g_pMxH[f][i+256]);
    __syncthreads();
    for (int s = 128; s; s >>= 1){
        if (i < s){
            sd[i] += sd[i+s];
            s1[i] = fminf(s1[i], s1[i+s]); s2[i] = fmaxf(s2[i], s2[i+s]);
            s3[i] = fminf(s3[i], s3[i+s]); s4[i] = fmaxf(s4[i], s4[i+s]);
        }
        __syncthreads();
    }
    if (i == 0){
        float W = *wp, B = *bp;
        float scal1 = W*(float)(sd[0]/(double)NB) + B;
        float a1 = scal1*W, c1 = scal1*B;
        g_a1[f] = a1; g_c1[f] = c1;
        g_M1f[f] = (a1 >= 0.f ? a1*s2[0] : a1*s1[0]) + c1;
        g_mnH[f] = s3[0]; g_mxH[f] = s4[0];
    }
}

__global__ __launch_bounds__(256) void k_redB(const float* __restrict__ invr, const float* __restrict__ invi){
    int f = blockIdx.y; const float* K = f ? invi : invr;
    float a1 = g_a1[f], c1 = g_c1[f], M1 = g_M1f[f];
    double acc = 0.0;
    for (int j = blockIdx.x*256 + threadIdx.x; j < NB; j += RBLK*256){
        float kL, kH, vL; block_elems(K, j, kL, kH, vL);
        acc += (double)__expf(fmaf(a1, kL, c1) - M1);
    }
    acc = blockReduceD(acc);
    if (threadIdx.x == 0) g_pD[f][blockIdx.x] = acc;
}
__global__ void k_combB(){
    int f = blockIdx.x, i = threadIdx.x;
    __shared__ double sd[256];
    sd[i] = g_pD[f][i] + g_pD[f][i+256]; __syncthreads();
    for (int s = 128; s; s >>= 1){ if (i < s) sd[i] += sd[i+s]; __syncthreads(); }
    if (i == 0) g_Z1i[f] = (float)(1.0/sd[0]);
}

__global__ __launch_bounds__(256) void k_redC(const float* __restrict__ invr, const float* __restrict__ invi){
    int f = blockIdx.y; const float* K = f ? invi : invr;
    float a1 = g_a1[f], c1 = g_c1[f], M1 = g_M1f[f], Z1i = g_Z1i[f];
    double acc = 0.0;
    for (int j = blockIdx.x*256 + threadIdx.x; j < NB; j += RBLK*256){
        float kL, kH, vL; block_elems(K, j, kL, kH, vL);
        float sm = __expf(fmaf(a1, kL, c1) - M1) * Z1i;
        acc += (double)(kL / (1.f + __expf(-sm)));
    }
    acc = blockReduceD(acc);
    if (threadIdx.x == 0) g_pD[f][blockIdx.x] = acc;
}
__global__ void k_combC(const float* __restrict__ wp, const float* __restrict__ bp){
    int f = blockIdx.x, i = threadIdx.x;
    __shared__ double sd[256];
    sd[i] = g_pD[f][i] + g_pD[f][i+256]; __syncthreads();
    for (int s = 128; s; s >>= 1){ if (i < s) sd[i] += sd[i+s]; __syncthreads(); }
    if (i == 0){
        float W = *wp, B = *bp;
        float scal2 = W*(float)(sd[0]/(double)NB) + B;
        float a2 = scal2*W, c2 = scal2*B;
        g_a2[f] = a2; g_c2[f] = c2;
        g_M2f[f] = (a2 >= 0.f ? a2*g_mxH[f] : a2*g_mnH[f]) + c2;
    }
}

__global__ __launch_bounds__(256) void k_redD(const float* __restrict__ invr, const float* __restrict__ invi){
    int f = blockIdx.y; const float* K = f ? invi : invr;
    float a2 = g_a2[f], c2 = g_c2[f], M2 = g_M2f[f];
    double acc = 0.0;
    for (int j = blockIdx.x*256 + threadIdx.x; j < NB; j += RBLK*256){
        float kL, kH, vL; block_elems(K, j, kL, kH, vL);
        acc += (double)__expf(fmaf(a2, kH, c2) - M2);
    }
    acc = blockReduceD(acc);
    if (threadIdx.x == 0) g_pD[f][blockIdx.x] = acc;
}
__global__ void k_combD(){
    int f = blockIdx.x, i = threadIdx.x;
    __shared__ double sd[256];
    sd[i] = g_pD[f][i] + g_pD[f][i+256]; __syncthreads();
    for (int s = 128; s; s >>= 1){ if (i < s) sd[i] += sd[i+s]; __syncthreads(); }
    if (i == 0) g_Z2i[f] = (float)(1.0/sd[0]);
}

// ---------------- attention filter (pointwise) ----------------
__device__ __forceinline__ float atten_filter(float v, int t, int h, int w, int f){
    int tl = t - 64, hl = h - 32, wl = w - 32;
    if ((unsigned)tl < 128u && (unsigned)hl < 64u && (unsigned)wl < 64u){
        float k2p = v + g_sinT[tl];
        float sm = __expf(fmaf(g_a2[f], k2p, g_c2[f]) - g_M2f[f]) * g_Z2i[f];
        return k2p / (1.f + __expf(-sm));
    }
    int tl2 = (t + 64) & 255, hl2 = (h + 32) & 127, wl2 = (w + 32) & 127;
    if (tl2 < 128 && hl2 < 64 && wl2 < 64){
        float k2p = v + g_sinT[tl2];
        float sm = __expf(fmaf(g_a1[f], k2p, g_c1[f]) - g_M1f[f]) * g_Z1i[f];
        return k2p / (1.f + __expf(-sm));
    }
    return v;
}

// ---------------- precompute filtered W volume: W(k)/256 (float2) ----------------
__global__ __launch_bounds__(256) void k_filterW(const float* __restrict__ invr, const float* __restrict__ invi){
    int idx = blockIdx.x*256 + threadIdx.x;
    int t = idx >> 14, h = (idx >> 7) & 127, w = idx & 127;
    const float sc = 1.f/256.f;
    float w1 = atten_filter(invr[idx], t, h, w, 0)*sc;
    float w2 = atten_filter(invi[idx], t, h, w, 1)*sc;
    g_Wf[idx] = make_float2(w1, w2);
}

// ---------------- fused T (16x16 four-step, register FFTs) ----------------
__global__ __launch_bounds__(256,2) void k_fusedT(){
    extern __shared__ unsigned char smraw[];
    float2* bufA = (float2*)smraw;           // 16 lanes x 257
    float2* bufB = bufA + 16*257;
    __shared__ float2 stw[128];
    int tid = threadIdx.x, lane = tid & 15, role = tid >> 4;
    if (tid < 128) stw[tid] = g_tw[tid];
    int wb = blockIdx.x << 4, h = blockIdx.y, bd = blockIdx.z;
    int w = wb + lane;

    float2 X[16];
    const float2* ZS = g_bufA + (size_t)bd*VOL + (size_t)h*128 + w;
    #pragma unroll
    for (int j = 0; j < 8; j++) X[j] = ZS[(size_t)(role + 16*j)*16384];
    #pragma unroll
    for (int j = 8; j < 16; j++) X[j] = make_float2(0.f, 0.f);
    __syncthreads();

    fft16<1>(X, stw);
    int base = lane*257;
    #pragma unroll
    for (int j = 1; j < 16; j++) X[j] = cmul(X[j], twd<1>(stw, role*j));
    #pragma unroll
    for (int j = 0; j < 16; j++) bufA[base + j*16 + role] = X[j];
    __syncthreads();
    float2 S[16];
    #pragma unroll
    for (int n1 = 0; n1 < 16; n1++) S[n1] = bufA[base + role*16 + n1];
    fft16<1>(S, stw);

    const float2* WD = g_Wf + (size_t)h*128 + w;
    float2 A[16];
    #pragma unroll
    for (int j = 0; j < 16; j++){
        float2 wd = WD[(size_t)(role + 16*j)*16384];
        A[j] = cmul(wd, S[j]);
    }
    fft16<-1>(A, stw);
    __syncthreads();
    #pragma unroll
    for (int t1 = 0; t1 < 16; t1++)
        bufA[base + t1*16 + role] = cmul(A[t1], twd<-1>(stw, role*t1));

    int hn = (128 - h) & 127, wn = (128 - w) & 127;
    const float2* WR = g_Wf + (size_t)hn*128 + wn;
    #pragma unroll
    for (int j = 0; j < 16; j++){
        int kn = (256 - (role + 16*j)) & 255;
        float2 wr = WR[(size_t)kn*16384];
        A[j] = cmul(make_float2(wr.x, -wr.y), S[j]);
    }
    fft16<-1>(A, stw);
    #pragma unroll
    for (int t1 = 0; t1 < 16; t1++)
        bufB[base + t1*16 + role] = cmul(A[t1], twd<-1>(stw, role*t1));
    __syncthreads();

    float2* dP = g_bufB + (size_t)(2*bd)*VOL + (size_t)h*128 + w;
    #pragma unroll
    for (int K = 0; K < 16; K++) A[K] = bufA[base + role*16 + K];
    fft16<-1>(A, stw);
    #pragma unroll
    for (int t2 = 0; t2 < 8; t2++) dP[(size_t)(role + 16*t2)*16384] = A[t2];
    #pragma unroll
    for (int K = 0; K < 16; K++) A[K] = bufB[base + role*16 + K];
    fft16<-1>(A, stw);
    #pragma unroll
    for (int t2 = 0; t2 < 8; t2++) dP[(size_t)VOL + (size_t)(role + 16*t2)*16384] = A[t2];
}

// ---------------- inverse 2D (H,W) per t-slice (register four-step) -----------------
__global__ __launch_bounds__(512,1) void k_inv2D(){
    extern __shared__ float2 sm[];           // 128*SMP: rows 0..63 = exchange E, 64..127 = O
    __shared__ float2 stw[128];
    __shared__ float2 qd[64*65];
    int tid = threadIdx.x;
    if (tid < 128){ stw[tid] = g_tw[tid]; }
    int t = blockIdx.x, bd = blockIdx.y;
    float2* O = sm + 64*SMP;

    for (int pass = 0; pass < 2; pass++){
        const float2* src = g_bufB + (size_t)(2*bd + pass)*VOL + (size_t)t*16384;
        for (int g = 0; g < 2; g++){
            __syncthreads();
            int cl = tid & 63, r = tid >> 6;
            float2 X[16];
            #pragma unroll
            for (int n2 = 0; n2 < 16; n2++) X[n2] = src[(size_t)(r + 8*n2)*128 + g*64 + cl];
            fft16<-1>(X, stw);
            #pragma unroll
            for (int k2 = 1; k2 < 16; k2++) X[k2] = cmul(X[k2], twd<-1>(stw, 2*r*k2));
            #pragma unroll
            for (int k2 = 0; k2 < 16; k2++) sm[cl*SMP + k2*8 + r] = X[k2];
            __syncthreads();
            #pragma unroll
            for (int kk = 0; kk < 2; kk++){
                int k2 = 2*r + kk;
                float2 r8[8];
                #pragma unroll
                for (int n1 = 0; n1 < 8; n1++) r8[n1] = sm[cl*SMP + k2*8 + n1];
                fft8<-1>(r8, stw);
                #pragma unroll
                for (int k1 = 0; k1 < 4; k1++) O[(k2 + 16*k1)*SMP + g*64 + cl] = r8[k1];
            }
        }
        __syncthreads();
        {
            int h = tid & 63, r = tid >> 6;
            float2 X[16];
            #pragma unroll
            for (int n2 = 0; n2 < 16; n2++) X[n2] = O[h*SMP + r + 8*n2];
            fft16<-1>(X, stw);
            #pragma unroll
            for (int k2 = 1; k2 < 16; k2++) X[k2] = cmul(X[k2], twd<-1>(stw, 2*r*k2));
            #pragma unroll
            for (int k2 = 0; k2 < 16; k2++) sm[h*SMP + k2*8 + r] = X[k2];
        }
        __syncthreads();
        {
            int h = tid & 63, r = tid >> 6;
            float* fq = (float*)O;
            #pragma unroll
            for (int kk = 0; kk < 2; kk++){
                int k2 = 2*r + kk;
                float2 r8[8];
                #pragma unroll
                for (int n1 = 0; n1 < 8; n1++) r8[n1] = sm[h*SMP + k2*8 + n1];
                fft8<-1>(r8, stw);
                if (pass == 0){
                    #pragma unroll
                    for (int k1 = 0; k1 < 4; k1++)
                        qd[h*65 + k2 + 16*k1] = r8[k1];
                } else {
                    const float S2 = 1.f/268435456.f;   // (1/16384)^2
                    #pragma unroll
                    for (int k1 = 0; k1 < 4; k1++){
                        int w = k2 + 16*k1;
                        float2 P = qd[h*65 + w];
                        float2 R = r8[k1];
                        float Sr = (P.x*R.x + P.y*R.y)*S2;
                        float Si = (P.y*R.x - P.x*R.y)*S2;
                        float mag = fmaxf(0.5f*(sqrtf(Sr*Sr + Si*Si) + Sr), 0.f);
                        fq[h*65 + w] = sqrtf(mag);
                    }
                }
            }
        }
        if (pass == 1){
            __syncthreads();
            const float* fq = (const float*)O;
            float* dst = g_sq + (size_t)bd*NB + (size_t)t*4096;
            for (int i = tid; i < 4096; i += 512)
                dst[i] = fq[(i >> 6)*65 + (i & 63)];
        }
    }
}

// ---------------- final mtxi matmul along T (w-split: 256 blocks) ----------------
__global__ __launch_bounds__(512) void k_final(const float* __restrict__ mtxi, float* __restrict__ out){
    __shared__ float sx[128*32];
    int bid = blockIdx.x;
    int bd = bid >> 7, r = bid & 127, h = r >> 1, wo = (r & 1)*32;
    const float* src = g_sq + (size_t)bd*NB + h*64 + wo;
    for (int i = threadIdx.x; i < 128*32; i += 512){
        int t = i >> 5, wl = i & 31;
        sx[i] = src[(size_t)t*4096 + wl];
    }
    __syncthreads();
    float* dst = out + (size_t)bd*NB + h*64 + wo;
    for (int o = threadIdx.x; o < 128*32; o += 512){
        int t = o >> 5, wl = o & 31;
        float acc = 0.f;
        const float* mi = mtxi + t*128;
        #pragma unroll 8
        for (int m = 0; m < 128; m++) acc = fmaf(mi[m], sx[m*32 + wl], acc);
        dst[(size_t)t*4096 + wl] = acc;
    }
}

// ---------------- launch ----------------
#define TILE_SMEM (128*SMP*8)
#define FT_SMEM   (2*16*257*8)

extern "C" void kernel_launch(void* const* d_in, const int* in_sizes, int n_in,
                              void* d_out, int out_size){
    const float *feature = 0, *conv_w = 0, *conv_b = 0, *wave = 0;
    const float *invr = 0, *invi = 0, *mtx = 0, *mtxi = 0;
    int scal_seen = 0, mat_seen = 0, psf_seen = 0;
    for (int i = 0; i < n_in; i++){
        const float* p = (const float*)d_in[i];
        int s = in_sizes[i];
        if      (s == 1)       { if (scal_seen++ == 0) conv_w = p; else conv_b = p; }
        else if (s == 126)     wave = p;
        else if (s == 16384)   { if (mat_seen++ == 0) mtx = p; else mtxi = p; }
        else if (s == 4194304) { if (psf_seen++ == 0) invr = p; else invi = p; }
        else if (s == 1048576) feature = p;
    }
    float* out = (float*)d_out;

    // lazy one-time resources (no device memory; same launches every call)
    static cudaStream_t s2 = 0;
    static cudaEvent_t  evFork = 0, evJoin = 0;
    static int attrs_set = 0;
    if (!s2){
        cudaStreamCreateWithFlags(&s2, cudaStreamNonBlocking);
        cudaEventCreateWithFlags(&evFork, cudaEventDisableTiming);
        cudaEventCreateWithFlags(&evJoin, cudaEventDisableTiming);
    }
    if (!attrs_set){
        cudaFuncSetAttribute(k_fwd2D,  cudaFuncAttributeMaxDynamicSharedMemorySize, TILE_SMEM);
        cudaFuncSetAttribute(k_inv2D,  cudaFuncAttributeMaxDynamicSharedMemorySize, TILE_SMEM);
        cudaFuncSetAttribute(k_fusedT, cudaFuncAttributeMaxDynamicSharedMemorySize, FT_SMEM);
        attrs_set = 1;
    }

    k_init_tw<<<1,128>>>();

    // fork: side stream runs the attention-scalar chain + filterW (needs only g_sinT)
    cudaEventRecord(evFork, 0);
    cudaStreamWaitEvent(s2, evFork, 0);

    k_redA<<<dim3(RBLK,2),256,0,s2>>>(invr, invi);
    k_combA<<<2,256,0,s2>>>(conv_w, conv_b);
    k_redB<<<dim3(RBLK,2),256,0,s2>>>(invr, invi);
    k_combB<<<2,256,0,s2>>>();
    k_redC<<<dim3(RBLK,2),256,0,s2>>>(invr, invi);
    k_combC<<<2,256,0,s2>>>(conv_w, conv_b);
    k_redD<<<dim3(RBLK,2),256,0,s2>>>(invr, invi);
    k_combD<<<2,256,0,s2>>>();
    k_filterW<<<VOL/256,256,0,s2>>>(invr, invi);
    cudaEventRecord(evJoin, s2);

    // main stream: forward path
    k_build_M<<<64,256>>>(mtx, wave);
    k_conv<<<256,512>>>(feature);
    k_fwd2D<<<dim3(128,2),512,TILE_SMEM>>>();

    // join before fusedT (needs g_bufA AND g_Wf)
    cudaStreamWaitEvent(0, evJoin, 0);

    k_fusedT<<<dim3(8,128,2),256,FT_SMEM>>>();
    k_inv2D<<<dim3(128,2),512,TILE_SMEM>>>();
    k_final<<<256,512>>>(mtxi, out);
}